// round 1
// baseline (speedup 1.0000x reference)
#include <cuda_runtime.h>
#include <cstddef>

#define BB 2
#define NN 2048
#define CC 768
#define HH 12
#define HD 64
#define BN (BB * NN)          // 4096
#define QKVC (3 * CC)         // 2304

// Scratch (device globals — no allocation allowed in kernel_launch)
__device__ float g_qkv[(size_t)BN * QKVC];     // [B*N, 2304]
__device__ float g_att[(size_t)BN * CC];       // [B*N, 768]

// ---------------------------------------------------------------------------
// Generic tiled fp32 GEMM: C[M,N] = A[M,K] * B[K,N] (+ bias). All dims % 64==0,
// K % 16 == 0. Block 256 threads, 64x64 tile, 4x4 micro-tile, KTILE=16.
// ---------------------------------------------------------------------------
__global__ __launch_bounds__(256) void gemm_tiled(
    const float* __restrict__ A, const float* __restrict__ Bm,
    float* __restrict__ Cm, int M, int Nn, int K,
    const float* __restrict__ bias)
{
    __shared__ float As[16][65];   // [k][m], padded
    __shared__ float Bs[16][65];   // [k][n], padded

    const int tid = threadIdx.x;
    const int tx = tid & 15, ty = tid >> 4;
    const int m0 = blockIdx.y * 64, n0 = blockIdx.x * 64;

    const int ak = tid & 15, am = tid >> 4;   // A load: k in [0,16), m base in [0,16)
    const int bn = tid & 63, bk = tid >> 6;   // B load: n in [0,64), k base in [0,4)

    float acc[4][4] = {};

    for (int k0 = 0; k0 < K; k0 += 16) {
        #pragma unroll
        for (int r = 0; r < 4; r++)
            As[ak][am + r * 16] = A[(size_t)(m0 + am + r * 16) * K + k0 + ak];
        #pragma unroll
        for (int r = 0; r < 4; r++)
            Bs[bk + r * 4][bn] = Bm[(size_t)(k0 + bk + r * 4) * Nn + n0 + bn];
        __syncthreads();

        #pragma unroll
        for (int kk = 0; kk < 16; kk++) {
            float a[4], bv[4];
            #pragma unroll
            for (int i = 0; i < 4; i++) a[i] = As[kk][ty * 4 + i];
            #pragma unroll
            for (int j = 0; j < 4; j++) bv[j] = Bs[kk][tx * 4 + j];
            #pragma unroll
            for (int i = 0; i < 4; i++)
                #pragma unroll
                for (int j = 0; j < 4; j++)
                    acc[i][j] += a[i] * bv[j];
        }
        __syncthreads();
    }

    #pragma unroll
    for (int i = 0; i < 4; i++) {
        const int row = m0 + ty * 4 + i;
        #pragma unroll
        for (int j = 0; j < 4; j++) {
            const int col = n0 + tx * 4 + j;
            float v = acc[i][j];
            if (bias) v += bias[col];
            Cm[(size_t)row * Nn + col] = v;
        }
    }
}

// ---------------------------------------------------------------------------
// Attention: per (b, h, q-tile of 64). Flash-style streaming over key tiles of
// 64, faithful to reference: p = exp(s)*mask (NO max subtraction), out = P·V
// accumulated, denom = rowsum(P), divide at the end.
// ---------------------------------------------------------------------------
__global__ __launch_bounds__(256) void attn_kernel(
    const float* __restrict__ qkv, const int* __restrict__ mask,
    float* __restrict__ aout)
{
    extern __shared__ float sm[];
    float* Qs = sm;                 // 64 x 65
    float* Ks = Qs + 64 * 65;       // 64 x 65  (row = key, col = d)
    float* Vs = Ks + 64 * 65;       // 64 x 65  (row = key, col = d)
    float* Ps = Vs + 64 * 65;       // 64 x 65  (row = query, col = key)
    float* mk = Ps + 64 * 65;       // 64
    float* denom = mk + 64;         // 64

    const int b = blockIdx.z, h = blockIdx.y, q0 = blockIdx.x * 64;
    const int tid = threadIdx.x;
    const int tx = tid & 15, ty = tid >> 4;
    const float scale = 0.125f;     // 64^-0.5

    // Load Q tile (scale folded in)
    for (int i = tid; i < 64 * 64; i += 256) {
        const int r = i >> 6, d = i & 63;
        Qs[r * 65 + d] = qkv[(size_t)(b * NN + q0 + r) * QKVC + h * HD + d] * scale;
    }
    if (tid < 64) denom[tid] = 0.0f;

    float acc[4][4] = {};

    for (int k0 = 0; k0 < NN; k0 += 64) {
        // Load K, V, mask tiles
        for (int i = tid; i < 64 * 64; i += 256) {
            const int r = i >> 6, d = i & 63;
            const float* base = &qkv[(size_t)(b * NN + k0 + r) * QKVC + h * HD + d];
            Ks[r * 65 + d] = base[CC];
            Vs[r * 65 + d] = base[2 * CC];
        }
        if (tid < 64) mk[tid] = (float)mask[b * NN + k0 + tid];
        __syncthreads();

        // S = Q * K^T  (per-thread 4x4)
        float s[4][4] = {};
        #pragma unroll 16
        for (int kk = 0; kk < 64; kk++) {
            float a[4], bv[4];
            #pragma unroll
            for (int i = 0; i < 4; i++) a[i] = Qs[(ty * 4 + i) * 65 + kk];
            #pragma unroll
            for (int j = 0; j < 4; j++) bv[j] = Ks[(tx * 4 + j) * 65 + kk];
            #pragma unroll
            for (int i = 0; i < 4; i++)
                #pragma unroll
                for (int j = 0; j < 4; j++)
                    s[i][j] += a[i] * bv[j];
        }

        // P = exp(S) * mask  -> Ps
        float pm[4];
        #pragma unroll
        for (int j = 0; j < 4; j++) pm[j] = mk[tx * 4 + j];
        #pragma unroll
        for (int i = 0; i < 4; i++)
            #pragma unroll
            for (int j = 0; j < 4; j++)
                Ps[(ty * 4 + i) * 65 + tx * 4 + j] = __expf(s[i][j]) * pm[j];
        __syncthreads();

        // acc += P * V ; denom += rowsum(P)
        #pragma unroll 16
        for (int kk = 0; kk < 64; kk++) {
            float p[4], v[4];
            #pragma unroll
            for (int i = 0; i < 4; i++) p[i] = Ps[(ty * 4 + i) * 65 + kk];
            #pragma unroll
            for (int j = 0; j < 4; j++) v[j] = Vs[kk * 65 + tx * 4 + j];
            #pragma unroll
            for (int i = 0; i < 4; i++)
                #pragma unroll
                for (int j = 0; j < 4; j++)
                    acc[i][j] += p[i] * v[j];
        }
        if (tid < 64) {
            float dsum = 0.0f;
            #pragma unroll 8
            for (int m = 0; m < 64; m++) dsum += Ps[tid * 65 + m];
            denom[tid] += dsum;
        }
        __syncthreads();
    }

    // Epilogue: divide by denom, store [B*N, C] with col = h*64 + d
    float dinv[4];
    #pragma unroll
    for (int i = 0; i < 4; i++) dinv[i] = 1.0f / denom[ty * 4 + i];
    #pragma unroll
    for (int i = 0; i < 4; i++)
        #pragma unroll
        for (int j = 0; j < 4; j++)
            aout[(size_t)(b * NN + q0 + ty * 4 + i) * CC + h * HD + tx * 4 + j] =
                acc[i][j] * dinv[i];
}

// ---------------------------------------------------------------------------
extern "C" void kernel_launch(void* const* d_in, const int* in_sizes, int n_in,
                              void* d_out, int out_size)
{
    const float* x      = (const float*)d_in[0];  // [2,2048,768]
    const int*   mask   = (const int*)  d_in[1];  // [2,2048]
    const float* w_qkv  = (const float*)d_in[2];  // [768,2304]
    const float* w_proj = (const float*)d_in[3];  // [768,768]
    const float* b_proj = (const float*)d_in[4];  // [768]
    float* out = (float*)d_out;                   // [2,2048,768]

    float* qkv_ptr = nullptr;
    float* att_ptr = nullptr;
    cudaGetSymbolAddress((void**)&qkv_ptr, g_qkv);
    cudaGetSymbolAddress((void**)&att_ptr, g_att);

    // 1) QKV GEMM: [4096,768] x [768,2304]
    gemm_tiled<<<dim3(QKVC / 64, BN / 64), 256>>>(x, w_qkv, qkv_ptr,
                                                  BN, QKVC, CC, nullptr);

    // 2) Attention
    const int smem = (4 * 64 * 65 + 128) * (int)sizeof(float);  // 67584 B
    static bool attr_set = false;
    cudaFuncSetAttribute(attn_kernel, cudaFuncAttributeMaxDynamicSharedMemorySize, smem);
    (void)attr_set;
    attn_kernel<<<dim3(NN / 64, HH, BB), 256, smem>>>(qkv_ptr, mask, att_ptr);

    // 3) Projection GEMM + bias: [4096,768] x [768,768]
    gemm_tiled<<<dim3(CC / 64, BN / 64), 256>>>(att_ptr, w_proj, out,
                                                BN, CC, CC, b_proj);
}

// round 3
// speedup vs baseline: 1.4425x; 1.4425x over previous
#include <cuda_runtime.h>
#include <cuda_bf16.h>
#include <cstdint>
#include <cstddef>

#define BB 2
#define NN 2048
#define CC 768
#define HH 12
#define HD 64
#define BN (BB * NN)          // 4096
#define QKVC (3 * CC)         // 2304

// ---------------------------------------------------------------------------
// Scratch (device globals — no allocation allowed anywhere)
// ---------------------------------------------------------------------------
__device__ float g_qkv[(size_t)BN * QKVC];                        // fp32 [4096,2304]
__device__ __align__(16) __nv_bfloat16 g_xhi[(size_t)BN * CC];
__device__ __align__(16) __nv_bfloat16 g_xlo[(size_t)BN * CC];
__device__ __align__(16) __nv_bfloat16 g_wqhi[(size_t)QKVC * CC]; // Wqkv^T [2304,768]
__device__ __align__(16) __nv_bfloat16 g_wqlo[(size_t)QKVC * CC];
__device__ __align__(16) __nv_bfloat16 g_wphi[(size_t)CC * CC];   // Wproj^T [768,768]
__device__ __align__(16) __nv_bfloat16 g_wplo[(size_t)CC * CC];
__device__ __align__(16) __nv_bfloat16 g_ahi[(size_t)BN * CC];    // attention out hi
__device__ __align__(16) __nv_bfloat16 g_alo[(size_t)BN * CC];    // attention out lo

// ---------------------------------------------------------------------------
// Family-common PTX helpers (NO tcgen05 — ptxas target is sm_103 w/o 'a')
// ---------------------------------------------------------------------------
__device__ __forceinline__ uint32_t smem_u32(const void* p) {
    uint32_t a;
    asm("{ .reg .u64 t; cvta.to.shared.u64 t, %1; cvt.u32.u64 %0, t; }"
        : "=r"(a) : "l"(p));
    return a;
}
#define CP_ASYNC16(dst, src) \
    asm volatile("cp.async.cg.shared.global [%0], [%1], 16;" :: "r"(dst), "l"(src))
#define CP_COMMIT() asm volatile("cp.async.commit_group;" ::: "memory")
#define CP_WAIT(n)  asm volatile("cp.async.wait_group %0;" :: "n"(n) : "memory")

#define LDSM_X4(r0, r1, r2, r3, addr)                                          \
    asm volatile("ldmatrix.sync.aligned.m8n8.x4.shared.b16 {%0,%1,%2,%3}, [%4];" \
                 : "=r"(r0), "=r"(r1), "=r"(r2), "=r"(r3) : "r"(addr))
#define LDSM_X2(r0, r1, addr)                                                  \
    asm volatile("ldmatrix.sync.aligned.m8n8.x2.shared.b16 {%0,%1}, [%2];"     \
                 : "=r"(r0), "=r"(r1) : "r"(addr))

#define MMA16816(d, a, b)                                                      \
    asm volatile("mma.sync.aligned.m16n8k16.row.col.f32.bf16.bf16.f32 "        \
                 "{%0,%1,%2,%3}, {%4,%5,%6,%7}, {%8,%9}, {%0,%1,%2,%3};"       \
                 : "+f"((d)[0]), "+f"((d)[1]), "+f"((d)[2]), "+f"((d)[3])      \
                 : "r"((a)[0]), "r"((a)[1]), "r"((a)[2]), "r"((a)[3]),         \
                   "r"((b)[0]), "r"((b)[1]))

// ---------------------------------------------------------------------------
// mma.sync split-bf16 GEMM: C[M,Nn] = A[M,K]·B[Nn,K]^T (+bias)
// A as hi/lo bf16 [M,K] row-major; B as hi/lo bf16 [Nn,K] row-major.
// Block tile 128x128, 8 warps (4M x 2N), warp tile 32x64, K-chunk 32,
// cp.async double-buffered. Row stride in smem = 40 bf16 (80 B).
// ---------------------------------------------------------------------------
#define RS 40                    // smem row stride (bf16 elems)
#define MAT_BYTES (128 * RS * 2) // 10240
#define STAGE_BYTES (4 * MAT_BYTES)
#define GEMM_SMEM (2 * STAGE_BYTES)   // 81920

__global__ __launch_bounds__(256) void gemm_mma(
    const uint4* __restrict__ Ah, const uint4* __restrict__ Al,
    const uint4* __restrict__ Bh, const uint4* __restrict__ Bl,
    float* __restrict__ C, int M, int Nn, int K,
    const float* __restrict__ bias)
{
    extern __shared__ char smem[];
    const uint32_t sb = smem_u32(smem);
    const int tid = threadIdx.x, wid = tid >> 5, lane = tid & 31;
    const int m0 = blockIdx.y * 128, n0 = blockIdx.x * 128;
    const int Krow = K >> 3;             // uint4 per gmem row
    const int nch = K >> 5;              // 32-wide K chunks

    const int wm = wid >> 1, wn = wid & 1;
    const int m_base = wm * 32, n_base = wn * 64;

    // ---- cp.async chunk prefetch into stage s ----
    auto prefetch = [&](int c, int s) {
        const uint32_t stage = sb + s * STAGE_BYTES;
        const int r = tid >> 2, q = tid & 3;          // 256 threads: 64 rows x 4
        const uint32_t doff = (uint32_t)(r * (RS * 2) + q * 16);
        #pragma unroll
        for (int half = 0; half < 2; half++) {        // rows r and r+64
            const int rr = r + half * 64;
            const uint32_t d2 = doff + (uint32_t)(half * 64 * RS * 2);
            const size_t ga = (size_t)(m0 + rr) * Krow + c * 4 + q;
            const size_t gb = (size_t)(n0 + rr) * Krow + c * 4 + q;
            CP_ASYNC16(stage +                 d2, Ah + ga);
            CP_ASYNC16(stage + MAT_BYTES +     d2, Al + ga);
            CP_ASYNC16(stage + 2 * MAT_BYTES + d2, Bh + gb);
            CP_ASYNC16(stage + 3 * MAT_BYTES + d2, Bl + gb);
        }
    };

    float acc[2][8][4] = {};

    prefetch(0, 0);
    CP_COMMIT();

    // ldmatrix lane addressing (byte offsets within a matrix)
    const int a_r = (lane & 15);                 // A: rows 0..15 of the m16 tile
    const int a_c = (lane >> 4) * 8;             // k half
    const int b_r = (lane & 7);                  // B: 8 n-rows
    const int b_c = ((lane >> 3) & 1) * 8;       // k half (lanes 8-15)

    for (int c = 0; c < nch; c++) {
        const int s = c & 1;
        if (c + 1 < nch) {
            prefetch(c + 1, 1 - s);
            CP_COMMIT();
            CP_WAIT(1);
        } else {
            CP_WAIT(0);
        }
        __syncthreads();

        const uint32_t As_h = sb + s * STAGE_BYTES;
        const uint32_t As_l = As_h + MAT_BYTES;
        const uint32_t Bs_h = As_h + 2 * MAT_BYTES;
        const uint32_t Bs_l = As_h + 3 * MAT_BYTES;

        #pragma unroll
        for (int kk = 0; kk < 2; kk++) {
            uint32_t ah[2][4], al[2][4];
            #pragma unroll
            for (int mt = 0; mt < 2; mt++) {
                const uint32_t ao =
                    (uint32_t)((m_base + mt * 16 + a_r) * (RS * 2) +
                               (kk * 16 + a_c) * 2);
                LDSM_X4(ah[mt][0], ah[mt][1], ah[mt][2], ah[mt][3], As_h + ao);
                LDSM_X4(al[mt][0], al[mt][1], al[mt][2], al[mt][3], As_l + ao);
            }
            #pragma unroll
            for (int nt = 0; nt < 8; nt++) {
                const uint32_t bo =
                    (uint32_t)((n_base + nt * 8 + b_r) * (RS * 2) +
                               (kk * 16 + b_c) * 2);
                uint32_t bh[2], bl[2];
                LDSM_X2(bh[0], bh[1], Bs_h + bo);
                LDSM_X2(bl[0], bl[1], Bs_l + bo);
                #pragma unroll
                for (int mt = 0; mt < 2; mt++) {
                    MMA16816(acc[mt][nt], ah[mt], bh);
                    MMA16816(acc[mt][nt], ah[mt], bl);
                    MMA16816(acc[mt][nt], al[mt], bh);
                }
            }
        }
        __syncthreads();
    }

    // ---- epilogue ----
    #pragma unroll
    for (int mt = 0; mt < 2; mt++) {
        const int row0 = m0 + m_base + mt * 16 + (lane >> 2);
        #pragma unroll
        for (int nt = 0; nt < 8; nt++) {
            const int col = n0 + n_base + nt * 8 + (lane & 3) * 2;
            float b0 = 0.f, b1 = 0.f;
            if (bias) { b0 = bias[col]; b1 = bias[col + 1]; }
            float2 v0 = { acc[mt][nt][0] + b0, acc[mt][nt][1] + b1 };
            float2 v1 = { acc[mt][nt][2] + b0, acc[mt][nt][3] + b1 };
            *(float2*)(C + (size_t)row0 * Nn + col) = v0;
            *(float2*)(C + (size_t)(row0 + 8) * Nn + col) = v1;
        }
    }
}

// ---------------------------------------------------------------------------
// fp32 -> bf16 hi/lo split (elementwise)
// ---------------------------------------------------------------------------
__global__ void split_fp32(const float* __restrict__ in,
                           __nv_bfloat16* __restrict__ hi,
                           __nv_bfloat16* __restrict__ lo, int n)
{
    int i = blockIdx.x * blockDim.x + threadIdx.x;
    if (i < n) {
        float v = in[i];
        __nv_bfloat16 h = __float2bfloat16(v);
        hi[i] = h;
        lo[i] = __float2bfloat16(v - __bfloat162float(h));
    }
}

// ---------------------------------------------------------------------------
// W[K,N] fp32 -> Wt hi/lo bf16 [N,K] (transpose + split)
// ---------------------------------------------------------------------------
__global__ void transpose_split(const float* __restrict__ W,
                                __nv_bfloat16* __restrict__ hi,
                                __nv_bfloat16* __restrict__ lo, int K, int N)
{
    __shared__ float t[32][33];
    const int n0 = blockIdx.x * 32, k0 = blockIdx.y * 32;
    const int tx = threadIdx.x, ty = threadIdx.y;   // 32 x 8
    #pragma unroll
    for (int j = 0; j < 4; j++)
        t[ty + 8 * j][tx] = W[(size_t)(k0 + ty + 8 * j) * N + n0 + tx];
    __syncthreads();
    #pragma unroll
    for (int j = 0; j < 4; j++) {
        int nl = ty + 8 * j;
        float v = t[tx][nl];
        __nv_bfloat16 h = __float2bfloat16(v);
        size_t o = (size_t)(n0 + nl) * K + k0 + tx;
        hi[o] = h;
        lo[o] = __float2bfloat16(v - __bfloat162float(h));
    }
}

// ---------------------------------------------------------------------------
// Attention (SIMT fp32): per (b, h, q-tile 64), streaming k-tiles.
// Faithful: p = exp(s)*mask (no max sub), divide by rowsum at the end.
// Epilogue writes bf16 hi/lo directly for the proj GEMM.
// ---------------------------------------------------------------------------
__global__ __launch_bounds__(256) void attn_kernel(
    const float* __restrict__ qkv, const int* __restrict__ mask,
    __nv_bfloat16* __restrict__ ahi, __nv_bfloat16* __restrict__ alo)
{
    extern __shared__ float sm[];
    float* Qs = sm;                 // 64 x 65
    float* Ks = Qs + 64 * 65;
    float* Vs = Ks + 64 * 65;
    float* Ps = Vs + 64 * 65;
    float* mk = Ps + 64 * 65;
    float* denom = mk + 64;

    const int b = blockIdx.z, h = blockIdx.y, q0 = blockIdx.x * 64;
    const int tid = threadIdx.x;
    const int tx = tid & 15, ty = tid >> 4;
    const float scale = 0.125f;

    for (int i = tid; i < 64 * 64; i += 256) {
        const int r = i >> 6, d = i & 63;
        Qs[r * 65 + d] = qkv[(size_t)(b * NN + q0 + r) * QKVC + h * HD + d] * scale;
    }
    if (tid < 64) denom[tid] = 0.0f;

    float acc[4][4] = {};

    for (int k0 = 0; k0 < NN; k0 += 64) {
        for (int i = tid; i < 64 * 64; i += 256) {
            const int r = i >> 6, d = i & 63;
            const float* base = &qkv[(size_t)(b * NN + k0 + r) * QKVC + h * HD + d];
            Ks[r * 65 + d] = base[CC];
            Vs[r * 65 + d] = base[2 * CC];
        }
        if (tid < 64) mk[tid] = (float)mask[b * NN + k0 + tid];
        __syncthreads();

        float s[4][4] = {};
        #pragma unroll 16
        for (int kk = 0; kk < 64; kk++) {
            float a[4], bv[4];
            #pragma unroll
            for (int i = 0; i < 4; i++) a[i] = Qs[(ty * 4 + i) * 65 + kk];
            #pragma unroll
            for (int j = 0; j < 4; j++) bv[j] = Ks[(tx * 4 + j) * 65 + kk];
            #pragma unroll
            for (int i = 0; i < 4; i++)
                #pragma unroll
                for (int j = 0; j < 4; j++)
                    s[i][j] += a[i] * bv[j];
        }

        float pm[4];
        #pragma unroll
        for (int j = 0; j < 4; j++) pm[j] = mk[tx * 4 + j];
        #pragma unroll
        for (int i = 0; i < 4; i++)
            #pragma unroll
            for (int j = 0; j < 4; j++)
                Ps[(ty * 4 + i) * 65 + tx * 4 + j] = __expf(s[i][j]) * pm[j];
        __syncthreads();

        #pragma unroll 16
        for (int kk = 0; kk < 64; kk++) {
            float p[4], v[4];
            #pragma unroll
            for (int i = 0; i < 4; i++) p[i] = Ps[(ty * 4 + i) * 65 + kk];
            #pragma unroll
            for (int j = 0; j < 4; j++) v[j] = Vs[kk * 65 + tx * 4 + j];
            #pragma unroll
            for (int i = 0; i < 4; i++)
                #pragma unroll
                for (int j = 0; j < 4; j++)
                    acc[i][j] += p[i] * v[j];
        }
        if (tid < 64) {
            float dsum = 0.0f;
            #pragma unroll 8
            for (int m = 0; m < 64; m++) dsum += Ps[tid * 65 + m];
            denom[tid] += dsum;
        }
        __syncthreads();
    }

    float dinv[4];
    #pragma unroll
    for (int i = 0; i < 4; i++) dinv[i] = 1.0f / denom[ty * 4 + i];
    #pragma unroll
    for (int i = 0; i < 4; i++)
        #pragma unroll
        for (int j = 0; j < 4; j++) {
            float v = acc[i][j] * dinv[i];
            __nv_bfloat16 hh = __float2bfloat16(v);
            size_t o = (size_t)(b * NN + q0 + ty * 4 + i) * CC + h * HD + tx * 4 + j;
            ahi[o] = hh;
            alo[o] = __float2bfloat16(v - __bfloat162float(hh));
        }
}

// ---------------------------------------------------------------------------
extern "C" void kernel_launch(void* const* d_in, const int* in_sizes, int n_in,
                              void* d_out, int out_size)
{
    const float* x      = (const float*)d_in[0];  // [2,2048,768]
    const int*   mask   = (const int*)  d_in[1];  // [2,2048]
    const float* w_qkv  = (const float*)d_in[2];  // [768,2304]
    const float* w_proj = (const float*)d_in[3];  // [768,768]
    const float* b_proj = (const float*)d_in[4];  // [768]
    float* out = (float*)d_out;                   // [2,2048,768]

    float* qkv_p;
    __nv_bfloat16 *xhi, *xlo, *wqhi, *wqlo, *wphi, *wplo, *ahi, *alo;
    cudaGetSymbolAddress((void**)&qkv_p, g_qkv);
    cudaGetSymbolAddress((void**)&xhi, g_xhi);
    cudaGetSymbolAddress((void**)&xlo, g_xlo);
    cudaGetSymbolAddress((void**)&wqhi, g_wqhi);
    cudaGetSymbolAddress((void**)&wqlo, g_wqlo);
    cudaGetSymbolAddress((void**)&wphi, g_wphi);
    cudaGetSymbolAddress((void**)&wplo, g_wplo);
    cudaGetSymbolAddress((void**)&ahi, g_ahi);
    cudaGetSymbolAddress((void**)&alo, g_alo);

    cudaFuncSetAttribute(gemm_mma, cudaFuncAttributeMaxDynamicSharedMemorySize, GEMM_SMEM);
    const int attn_smem = (4 * 64 * 65 + 128) * (int)sizeof(float);
    cudaFuncSetAttribute(attn_kernel, cudaFuncAttributeMaxDynamicSharedMemorySize, attn_smem);

    // 0) precision splits / weight transposes
    split_fp32<<<(BN * CC + 255) / 256, 256>>>(x, xhi, xlo, BN * CC);
    transpose_split<<<dim3(QKVC / 32, CC / 32), dim3(32, 8)>>>(w_qkv, wqhi, wqlo, CC, QKVC);
    transpose_split<<<dim3(CC / 32, CC / 32), dim3(32, 8)>>>(w_proj, wphi, wplo, CC, CC);

    // 1) QKV GEMM (mma.sync): [4096,768] x [2304,768]^T -> fp32 [4096,2304]
    gemm_mma<<<dim3(QKVC / 128, BN / 128), 256, GEMM_SMEM>>>(
        (const uint4*)xhi, (const uint4*)xlo, (const uint4*)wqhi, (const uint4*)wqlo,
        qkv_p, BN, QKVC, CC, nullptr);

    // 2) Attention (fp32 SIMT), writes bf16 hi/lo
    attn_kernel<<<dim3(NN / 64, HH, BB), 256, attn_smem>>>(qkv_p, mask, ahi, alo);

    // 3) Projection GEMM (mma.sync) + bias -> out
    gemm_mma<<<dim3(CC / 128, BN / 128), 256, GEMM_SMEM>>>(
        (const uint4*)ahi, (const uint4*)alo, (const uint4*)wphi, (const uint4*)wplo,
        out, BN, CC, CC, b_proj);
}

// round 5
// speedup vs baseline: 3.9462x; 2.7357x over previous
#include <cuda_runtime.h>
#include <cuda_bf16.h>
#include <cstdint>
#include <cstddef>

#define BB 2
#define NN 2048
#define CC 768
#define HH 12
#define HD 64
#define BN (BB * NN)          // 4096
#define QKVC (3 * CC)         // 2304

// ---------------------------------------------------------------------------
// Scratch (device globals — no allocation allowed anywhere)
// ---------------------------------------------------------------------------
__device__ float g_qkv[(size_t)BN * QKVC];                        // fp32 [4096,2304]
__device__ __align__(16) __nv_bfloat16 g_xhi[(size_t)BN * CC];
__device__ __align__(16) __nv_bfloat16 g_xlo[(size_t)BN * CC];
__device__ __align__(16) __nv_bfloat16 g_wqhi[(size_t)QKVC * CC]; // Wqkv^T [2304,768]
__device__ __align__(16) __nv_bfloat16 g_wqlo[(size_t)QKVC * CC];
__device__ __align__(16) __nv_bfloat16 g_wphi[(size_t)CC * CC];   // Wproj^T [768,768]
__device__ __align__(16) __nv_bfloat16 g_wplo[(size_t)CC * CC];
__device__ __align__(16) __nv_bfloat16 g_ahi[(size_t)BN * CC];    // attention out hi
__device__ __align__(16) __nv_bfloat16 g_alo[(size_t)BN * CC];    // attention out lo
// attention operands
__device__ __align__(16) __nv_bfloat16 g_qhi[(size_t)BB * HH * NN * HD];
__device__ __align__(16) __nv_bfloat16 g_qlo[(size_t)BB * HH * NN * HD];
__device__ __align__(16) __nv_bfloat16 g_khi[(size_t)BB * HH * NN * HD];
__device__ __align__(16) __nv_bfloat16 g_klo[(size_t)BB * HH * NN * HD];
__device__ __align__(16) __nv_bfloat16 g_vth[(size_t)BB * HH * HD * NN];
__device__ __align__(16) __nv_bfloat16 g_vtl[(size_t)BB * HH * HD * NN];
__device__ int g_kidx[BB * NN];
__device__ int g_kcnt[BB];

// ---------------------------------------------------------------------------
// Family-common PTX helpers (ptxas target is sm_103 w/o 'a' — no tcgen05)
// ---------------------------------------------------------------------------
__device__ __forceinline__ uint32_t smem_u32(const void* p) {
    uint32_t a;
    asm("{ .reg .u64 t; cvta.to.shared.u64 t, %1; cvt.u32.u64 %0, t; }"
        : "=r"(a) : "l"(p));
    return a;
}
#define CP_ASYNC16(dst, src) \
    asm volatile("cp.async.cg.shared.global [%0], [%1], 16;" :: "r"(dst), "l"(src))
#define CP_COMMIT() asm volatile("cp.async.commit_group;" ::: "memory")
#define CP_WAIT(n)  asm volatile("cp.async.wait_group %0;" :: "n"(n) : "memory")

#define LDSM_X4(r0, r1, r2, r3, addr)                                          \
    asm volatile("ldmatrix.sync.aligned.m8n8.x4.shared.b16 {%0,%1,%2,%3}, [%4];" \
                 : "=r"(r0), "=r"(r1), "=r"(r2), "=r"(r3) : "r"(addr))
#define LDSM_X2(r0, r1, addr)                                                  \
    asm volatile("ldmatrix.sync.aligned.m8n8.x2.shared.b16 {%0,%1}, [%2];"     \
                 : "=r"(r0), "=r"(r1) : "r"(addr))

#define MMA16816(d, a, b)                                                      \
    asm volatile("mma.sync.aligned.m16n8k16.row.col.f32.bf16.bf16.f32 "        \
                 "{%0,%1,%2,%3}, {%4,%5,%6,%7}, {%8,%9}, {%0,%1,%2,%3};"       \
                 : "+f"((d)[0]), "+f"((d)[1]), "+f"((d)[2]), "+f"((d)[3])      \
                 : "r"((a)[0]), "r"((a)[1]), "r"((a)[2]), "r"((a)[3]),         \
                   "r"((b)[0]), "r"((b)[1]))

// ---------------------------------------------------------------------------
// mma.sync split-bf16 GEMM (verified): C[M,Nn] = A[M,K]·B[Nn,K]^T (+bias)
// ---------------------------------------------------------------------------
#define RS 40
#define MAT_BYTES (128 * RS * 2)
#define STAGE_BYTES (4 * MAT_BYTES)
#define GEMM_SMEM (2 * STAGE_BYTES)

__global__ __launch_bounds__(256) void gemm_mma(
    const uint4* __restrict__ Ah, const uint4* __restrict__ Al,
    const uint4* __restrict__ Bh, const uint4* __restrict__ Bl,
    float* __restrict__ C, int M, int Nn, int K,
    const float* __restrict__ bias)
{
    extern __shared__ char smem[];
    const uint32_t sb = smem_u32(smem);
    const int tid = threadIdx.x, wid = tid >> 5, lane = tid & 31;
    const int m0 = blockIdx.y * 128, n0 = blockIdx.x * 128;
    const int Krow = K >> 3;
    const int nch = K >> 5;

    const int wm = wid >> 1, wn = wid & 1;
    const int m_base = wm * 32, n_base = wn * 64;

    auto prefetch = [&](int c, int s) {
        const uint32_t stage = sb + s * STAGE_BYTES;
        const int r = tid >> 2, q = tid & 3;
        const uint32_t doff = (uint32_t)(r * (RS * 2) + q * 16);
        #pragma unroll
        for (int half = 0; half < 2; half++) {
            const int rr = r + half * 64;
            const uint32_t d2 = doff + (uint32_t)(half * 64 * RS * 2);
            const size_t ga = (size_t)(m0 + rr) * Krow + c * 4 + q;
            const size_t gb = (size_t)(n0 + rr) * Krow + c * 4 + q;
            CP_ASYNC16(stage +                 d2, Ah + ga);
            CP_ASYNC16(stage + MAT_BYTES +     d2, Al + ga);
            CP_ASYNC16(stage + 2 * MAT_BYTES + d2, Bh + gb);
            CP_ASYNC16(stage + 3 * MAT_BYTES + d2, Bl + gb);
        }
    };

    float acc[2][8][4] = {};

    prefetch(0, 0);
    CP_COMMIT();

    const int a_r = (lane & 15);
    const int a_c = (lane >> 4) * 8;
    const int b_r = (lane & 7);
    const int b_c = ((lane >> 3) & 1) * 8;

    for (int c = 0; c < nch; c++) {
        const int s = c & 1;
        if (c + 1 < nch) { prefetch(c + 1, 1 - s); CP_COMMIT(); CP_WAIT(1); }
        else { CP_WAIT(0); }
        __syncthreads();

        const uint32_t As_h = sb + s * STAGE_BYTES;
        const uint32_t As_l = As_h + MAT_BYTES;
        const uint32_t Bs_h = As_h + 2 * MAT_BYTES;
        const uint32_t Bs_l = As_h + 3 * MAT_BYTES;

        #pragma unroll
        for (int kk = 0; kk < 2; kk++) {
            uint32_t ah[2][4], al[2][4];
            #pragma unroll
            for (int mt = 0; mt < 2; mt++) {
                const uint32_t ao =
                    (uint32_t)((m_base + mt * 16 + a_r) * (RS * 2) +
                               (kk * 16 + a_c) * 2);
                LDSM_X4(ah[mt][0], ah[mt][1], ah[mt][2], ah[mt][3], As_h + ao);
                LDSM_X4(al[mt][0], al[mt][1], al[mt][2], al[mt][3], As_l + ao);
            }
            #pragma unroll
            for (int nt = 0; nt < 8; nt++) {
                const uint32_t bo =
                    (uint32_t)((n_base + nt * 8 + b_r) * (RS * 2) +
                               (kk * 16 + b_c) * 2);
                uint32_t bh[2], bl[2];
                LDSM_X2(bh[0], bh[1], Bs_h + bo);
                LDSM_X2(bl[0], bl[1], Bs_l + bo);
                #pragma unroll
                for (int mt = 0; mt < 2; mt++) {
                    MMA16816(acc[mt][nt], ah[mt], bh);
                    MMA16816(acc[mt][nt], ah[mt], bl);
                    MMA16816(acc[mt][nt], al[mt], bh);
                }
            }
        }
        __syncthreads();
    }

    #pragma unroll
    for (int mt = 0; mt < 2; mt++) {
        const int row0 = m0 + m_base + mt * 16 + (lane >> 2);
        #pragma unroll
        for (int nt = 0; nt < 8; nt++) {
            const int col = n0 + n_base + nt * 8 + (lane & 3) * 2;
            float b0 = 0.f, b1 = 0.f;
            if (bias) { b0 = bias[col]; b1 = bias[col + 1]; }
            float2 v0 = { acc[mt][nt][0] + b0, acc[mt][nt][1] + b1 };
            float2 v1 = { acc[mt][nt][2] + b0, acc[mt][nt][3] + b1 };
            *(float2*)(C + (size_t)row0 * Nn + col) = v0;
            *(float2*)(C + (size_t)(row0 + 8) * Nn + col) = v1;
        }
    }
}

// ---------------------------------------------------------------------------
// mask prefix scan: compact indices of unmasked keys per batch
// ---------------------------------------------------------------------------
__global__ void scan_mask(const int* __restrict__ mask, int* __restrict__ kidx,
                          int* __restrict__ kcnt)
{
    __shared__ int part[256];
    const int b = blockIdx.x, t = threadIdx.x;
    const int* m = mask + b * NN;
    int loc[8], c = 0;
    #pragma unroll
    for (int i = 0; i < 8; i++) { loc[i] = c; c += m[t * 8 + i]; }
    part[t] = c;
    __syncthreads();
    for (int off = 1; off < 256; off <<= 1) {
        int v = (t >= off) ? part[t - off] : 0;
        __syncthreads();
        part[t] += v;
        __syncthreads();
    }
    int excl = part[t] - c;
    #pragma unroll
    for (int i = 0; i < 8; i++)
        if (m[t * 8 + i]) kidx[b * NN + excl + loc[i]] = t * 8 + i;
    if (t == 255) kcnt[b] = part[255];
}

// ---------------------------------------------------------------------------
// Q: fp32 qkv -> scaled split bf16 [b][h][n][64]
// ---------------------------------------------------------------------------
__global__ void q_split(const float* __restrict__ qkv,
                        __nv_bfloat16* __restrict__ qhi,
                        __nv_bfloat16* __restrict__ qlo)
{
    int i = blockIdx.x * 256 + threadIdx.x;
    if (i >= BB * NN * CC) return;
    int b = i / (NN * CC), r = i % (NN * CC);
    int s = r / CC, c = r % CC;
    int h = c >> 6, d = c & 63;
    float v = qkv[(size_t)(b * NN + s) * QKVC + c] * 0.125f;
    __nv_bfloat16 hi = __float2bfloat16(v);
    size_t o = (((size_t)b * HH + h) * NN + s) * HD + d;
    qhi[o] = hi;
    qlo[o] = __float2bfloat16(v - __bfloat162float(hi));
}

// ---------------------------------------------------------------------------
// K,V: gather unmasked keys, split bf16; K row-major [b][h][j][64],
// V transposed [b][h][64][j]. Zero-pad [cnt, pad64).
// ---------------------------------------------------------------------------
__global__ void kv_gather(const float* __restrict__ qkv,
                          const int* __restrict__ kidx, const int* __restrict__ kcnt,
                          __nv_bfloat16* __restrict__ khi, __nv_bfloat16* __restrict__ klo,
                          __nv_bfloat16* __restrict__ vth, __nv_bfloat16* __restrict__ vtl)
{
    __shared__ float vs[128][65];
    const int b = blockIdx.z, h = blockIdx.y, j0 = blockIdx.x * 128;
    const int tid = threadIdx.x;
    const int cnt = kcnt[b];
    const int pad = ((cnt + 63) >> 6) << 6;
    if (j0 >= pad) return;
    const size_t bh = (size_t)b * HH + h;

    for (int it = 0; it < 32; it++) {
        int idx = it * 256 + tid;
        int jl = idx >> 6, d = idx & 63;
        int j = j0 + jl;
        float kv = 0.f, vv = 0.f;
        if (j < cnt) {
            int s = kidx[b * NN + j];
            const float* base = qkv + (size_t)(b * NN + s) * QKVC + h * HD;
            kv = base[CC + d];
            vv = base[2 * CC + d];
        }
        vs[jl][d] = vv;
        if (j < pad) {
            size_t o = (bh * NN + j) * HD + d;
            __nv_bfloat16 hi = __float2bfloat16(kv);
            khi[o] = hi;
            klo[o] = __float2bfloat16(kv - __bfloat162float(hi));
        }
    }
    __syncthreads();
    for (int it = 0; it < 32; it++) {
        int idx = it * 256 + tid;
        int d = idx >> 7, jl = idx & 127;
        if (j0 + jl < pad) {
            float v = vs[jl][d];
            __nv_bfloat16 hi = __float2bfloat16(v);
            size_t o = (bh * HD + d) * NN + j0 + jl;
            vth[o] = hi;
            vtl[o] = __float2bfloat16(v - __bfloat162float(hi));
        }
    }
}

// ---------------------------------------------------------------------------
// Tensor-core attention over packed keys — P now split hi/lo (R4 fix).
// S = Qsplit·Ksplit^T (3 MMAs); p = exp(s) fp32; Ph/Pl bf16 split;
// denom accumulated from exact fp32 p;
// O += Ph·Vh + Pl·Vh + Ph·Vl (3 MMAs); out = O/denom -> split bf16.
// ---------------------------------------------------------------------------
#define QT 128
#define KT 64
#define PADB 144                 // 72 bf16 per row
#define SM_QL   18432
#define SM_STG  36864
#define STG_SZ  36864            // Kh,Kl,VTh,VTl : 9216 each
#define SM_P    110592
#define SM_PL   129024
#define SM_DEN  147456
#define ATTN_SMEM (147456 + 512)

__global__ __launch_bounds__(256) void attn_mma(
    const uint4* __restrict__ Qh, const uint4* __restrict__ Ql,
    const uint4* __restrict__ Kh, const uint4* __restrict__ Kl,
    const uint4* __restrict__ Vth, const uint4* __restrict__ Vtl,
    const int* __restrict__ kcnt,
    __nv_bfloat16* __restrict__ ahi, __nv_bfloat16* __restrict__ alo)
{
    extern __shared__ char sm[];
    const uint32_t sb = smem_u32(sm);
    const int b = blockIdx.z, h = blockIdx.y, q0 = blockIdx.x * QT;
    const int tid = threadIdx.x, wid = tid >> 5, lane = tid & 31;
    const int wm = wid >> 1, wn = wid & 1;
    const int mb = wm * 32, nb = wn * 32;
    const int cnt = kcnt[b];
    const int ntiles = (cnt + KT - 1) / KT;
    const size_t bh = (size_t)b * HH + h;

    float* denom_s = (float*)(sm + SM_DEN);
    if (tid < 128) denom_s[tid] = 0.0f;

    // resident Q tile (hi/lo)
    #pragma unroll
    for (int it = 0; it < 4; it++) {
        int idx = it * 256 + tid;
        int r = idx >> 3, c = idx & 7;
        size_t gi = (bh * NN + q0 + r) * 8 + c;
        *(uint4*)(sm + r * PADB + c * 16) = Qh[gi];
        *(uint4*)(sm + SM_QL + r * PADB + c * 16) = Ql[gi];
    }

    auto prefetch = [&](int t, int s) {
        const uint32_t stg = sb + SM_STG + s * STG_SZ;
        const int k0 = t * KT;
        #pragma unroll
        for (int it = 0; it < 8; it++) {
            int idx = it * 256 + tid;
            int mat = idx >> 9;                // 0 Kh,1 Kl,2 VTh,3 VTl
            int r = (idx >> 3) & 63, c = idx & 7;
            uint32_t dst = stg + mat * 9216 + (uint32_t)(r * PADB + c * 16);
            const uint4* g;
            size_t gi;
            if (mat < 2) {
                g = (mat == 0) ? Kh : Kl;
                gi = (bh * NN + k0 + r) * 8 + c;
            } else {
                g = (mat == 2) ? Vth : Vtl;
                gi = (bh * HD + r) * (NN / 8) + (k0 >> 3) + c;
            }
            CP_ASYNC16(dst, g + gi);
        }
    };

    float accO[2][4][4] = {};
    float denA[2][2] = {};

    const int a_r = lane & 15, a_c = (lane >> 4) * 8;
    const int b_r = lane & 7,  b_c = ((lane >> 3) & 1) * 8;

    prefetch(0, 0);
    CP_COMMIT();

    for (int t = 0; t < ntiles; t++) {
        const int s = t & 1;
        const int k0 = t * KT;
        if (t + 1 < ntiles) { prefetch(t + 1, 1 - s); CP_COMMIT(); CP_WAIT(1); }
        else { CP_WAIT(0); }
        __syncthreads();

        const uint32_t Ksh = sb + SM_STG + s * STG_SZ;
        const uint32_t Ksl = Ksh + 9216;
        const uint32_t Vsh = Ksh + 18432;
        const uint32_t Vsl = Ksh + 27648;

        // S = Q K^T (split bf16, 3 products)
        float accS[2][4][4] = {};
        #pragma unroll
        for (int ks = 0; ks < 4; ks++) {
            uint32_t ah[2][4], al[2][4];
            #pragma unroll
            for (int mt = 0; mt < 2; mt++) {
                uint32_t ao = sb + (uint32_t)((mb + mt * 16 + a_r) * PADB +
                                              (ks * 16 + a_c) * 2);
                LDSM_X4(ah[mt][0], ah[mt][1], ah[mt][2], ah[mt][3], ao);
                LDSM_X4(al[mt][0], al[mt][1], al[mt][2], al[mt][3], ao + SM_QL);
            }
            #pragma unroll
            for (int nt = 0; nt < 4; nt++) {
                uint32_t bo = (uint32_t)((nb + nt * 8 + b_r) * PADB +
                                         (ks * 16 + b_c) * 2);
                uint32_t bhv[2], blv[2];
                LDSM_X2(bhv[0], bhv[1], Ksh + bo);
                LDSM_X2(blv[0], blv[1], Ksl + bo);
                #pragma unroll
                for (int mt = 0; mt < 2; mt++) {
                    MMA16816(accS[mt][nt], ah[mt], bhv);
                    MMA16816(accS[mt][nt], ah[mt], blv);
                    MMA16816(accS[mt][nt], al[mt], bhv);
                }
            }
        }

        // p = exp(s)*(j<cnt) in fp32; split to Ph/Pl; denom from exact p
        #pragma unroll
        for (int mt = 0; mt < 2; mt++) {
            #pragma unroll
            for (int nt = 0; nt < 4; nt++) {
                int c0 = nb + nt * 8 + (lane & 3) * 2;
                float m0v = (k0 + c0     < cnt) ? 1.f : 0.f;
                float m1v = (k0 + c0 + 1 < cnt) ? 1.f : 0.f;
                #pragma unroll
                for (int h2 = 0; h2 < 2; h2++) {
                    int r = mb + mt * 16 + h2 * 8 + (lane >> 2);
                    float p0 = __expf(accS[mt][nt][h2 * 2 + 0]) * m0v;
                    float p1 = __expf(accS[mt][nt][h2 * 2 + 1]) * m1v;
                    denA[mt][h2] += p0 + p1;
                    __nv_bfloat16 h0 = __float2bfloat16(p0);
                    __nv_bfloat16 h1 = __float2bfloat16(p1);
                    __nv_bfloat16 l0 = __float2bfloat16(p0 - __bfloat162float(h0));
                    __nv_bfloat16 l1 = __float2bfloat16(p1 - __bfloat162float(h1));
                    uint32_t pkh = ((uint32_t)__bfloat16_as_ushort(h1) << 16) |
                                   (uint32_t)__bfloat16_as_ushort(h0);
                    uint32_t pkl = ((uint32_t)__bfloat16_as_ushort(l1) << 16) |
                                   (uint32_t)__bfloat16_as_ushort(l0);
                    *(uint32_t*)(sm + SM_P  + r * PADB + c0 * 2) = pkh;
                    *(uint32_t*)(sm + SM_PL + r * PADB + c0 * 2) = pkl;
                }
            }
        }
        __syncthreads();

        // O += Ph·Vh + Pl·Vh + Ph·Vl
        #pragma unroll
        for (int kk = 0; kk < 4; kk++) {
            uint32_t aph[2][4], apl[2][4];
            #pragma unroll
            for (int mt = 0; mt < 2; mt++) {
                uint32_t ao = (uint32_t)((mb + mt * 16 + a_r) * PADB +
                                         (kk * 16 + a_c) * 2);
                LDSM_X4(aph[mt][0], aph[mt][1], aph[mt][2], aph[mt][3],
                        sb + SM_P + ao);
                LDSM_X4(apl[mt][0], apl[mt][1], apl[mt][2], apl[mt][3],
                        sb + SM_PL + ao);
            }
            #pragma unroll
            for (int nt = 0; nt < 4; nt++) {
                uint32_t bo = (uint32_t)((nb + nt * 8 + b_r) * PADB +
                                         (kk * 16 + b_c) * 2);
                uint32_t bvh[2], bvl[2];
                LDSM_X2(bvh[0], bvh[1], Vsh + bo);
                LDSM_X2(bvl[0], bvl[1], Vsl + bo);
                #pragma unroll
                for (int mt = 0; mt < 2; mt++) {
                    MMA16816(accO[mt][nt], aph[mt], bvh);
                    MMA16816(accO[mt][nt], apl[mt], bvh);
                    MMA16816(accO[mt][nt], aph[mt], bvl);
                }
            }
        }
        __syncthreads();
    }

    // denom: quad-reduce then smem atomics
    #pragma unroll
    for (int mt = 0; mt < 2; mt++)
        #pragma unroll
        for (int h2 = 0; h2 < 2; h2++) {
            float v = denA[mt][h2];
            v += __shfl_xor_sync(0xffffffffu, v, 1);
            v += __shfl_xor_sync(0xffffffffu, v, 2);
            if ((lane & 3) == 0)
                atomicAdd(&denom_s[mb + mt * 16 + h2 * 8 + (lane >> 2)], v);
        }
    __syncthreads();

    // epilogue: divide, split to bf16 hi/lo for proj GEMM
    #pragma unroll
    for (int mt = 0; mt < 2; mt++) {
        #pragma unroll
        for (int h2 = 0; h2 < 2; h2++) {
            int r = mb + mt * 16 + h2 * 8 + (lane >> 2);
            float inv = 1.0f / denom_s[r];
            size_t rowg = (size_t)(b * NN + q0 + r) * CC + h * HD;
            #pragma unroll
            for (int nt = 0; nt < 4; nt++) {
                int c0 = nb + nt * 8 + (lane & 3) * 2;
                float v0 = accO[mt][nt][h2 * 2 + 0] * inv;
                float v1 = accO[mt][nt][h2 * 2 + 1] * inv;
                __nv_bfloat16 h0 = __float2bfloat16(v0);
                __nv_bfloat16 h1 = __float2bfloat16(v1);
                __nv_bfloat16 l0 = __float2bfloat16(v0 - __bfloat162float(h0));
                __nv_bfloat16 l1 = __float2bfloat16(v1 - __bfloat162float(h1));
                uint32_t pkh = ((uint32_t)__bfloat16_as_ushort(h1) << 16) |
                               (uint32_t)__bfloat16_as_ushort(h0);
                uint32_t pkl = ((uint32_t)__bfloat16_as_ushort(l1) << 16) |
                               (uint32_t)__bfloat16_as_ushort(l0);
                *(uint32_t*)((char*)ahi + (rowg + c0) * 2) = pkh;
                *(uint32_t*)((char*)alo + (rowg + c0) * 2) = pkl;
            }
        }
    }
}

// ---------------------------------------------------------------------------
// pre-pass splits
// ---------------------------------------------------------------------------
__global__ void split_fp32(const float* __restrict__ in,
                           __nv_bfloat16* __restrict__ hi,
                           __nv_bfloat16* __restrict__ lo, int n)
{
    int i = blockIdx.x * blockDim.x + threadIdx.x;
    if (i < n) {
        float v = in[i];
        __nv_bfloat16 h = __float2bfloat16(v);
        hi[i] = h;
        lo[i] = __float2bfloat16(v - __bfloat162float(h));
    }
}

__global__ void transpose_split(const float* __restrict__ W,
                                __nv_bfloat16* __restrict__ hi,
                                __nv_bfloat16* __restrict__ lo, int K, int N)
{
    __shared__ float t[32][33];
    const int n0 = blockIdx.x * 32, k0 = blockIdx.y * 32;
    const int tx = threadIdx.x, ty = threadIdx.y;
    #pragma unroll
    for (int j = 0; j < 4; j++)
        t[ty + 8 * j][tx] = W[(size_t)(k0 + ty + 8 * j) * N + n0 + tx];
    __syncthreads();
    #pragma unroll
    for (int j = 0; j < 4; j++) {
        int nl = ty + 8 * j;
        float v = t[tx][nl];
        __nv_bfloat16 h = __float2bfloat16(v);
        size_t o = (size_t)(n0 + nl) * K + k0 + tx;
        hi[o] = h;
        lo[o] = __float2bfloat16(v - __bfloat162float(h));
    }
}

// ---------------------------------------------------------------------------
extern "C" void kernel_launch(void* const* d_in, const int* in_sizes, int n_in,
                              void* d_out, int out_size)
{
    const float* x      = (const float*)d_in[0];
    const int*   mask   = (const int*)  d_in[1];
    const float* w_qkv  = (const float*)d_in[2];
    const float* w_proj = (const float*)d_in[3];
    const float* b_proj = (const float*)d_in[4];
    float* out = (float*)d_out;

    float* qkv_p;
    __nv_bfloat16 *xhi, *xlo, *wqhi, *wqlo, *wphi, *wplo, *ahi, *alo;
    __nv_bfloat16 *qhi, *qlo, *khi, *klo, *vth, *vtl;
    int *kidx, *kcnt;
    cudaGetSymbolAddress((void**)&qkv_p, g_qkv);
    cudaGetSymbolAddress((void**)&xhi, g_xhi);
    cudaGetSymbolAddress((void**)&xlo, g_xlo);
    cudaGetSymbolAddress((void**)&wqhi, g_wqhi);
    cudaGetSymbolAddress((void**)&wqlo, g_wqlo);
    cudaGetSymbolAddress((void**)&wphi, g_wphi);
    cudaGetSymbolAddress((void**)&wplo, g_wplo);
    cudaGetSymbolAddress((void**)&ahi, g_ahi);
    cudaGetSymbolAddress((void**)&alo, g_alo);
    cudaGetSymbolAddress((void**)&qhi, g_qhi);
    cudaGetSymbolAddress((void**)&qlo, g_qlo);
    cudaGetSymbolAddress((void**)&khi, g_khi);
    cudaGetSymbolAddress((void**)&klo, g_klo);
    cudaGetSymbolAddress((void**)&vth, g_vth);
    cudaGetSymbolAddress((void**)&vtl, g_vtl);
    cudaGetSymbolAddress((void**)&kidx, g_kidx);
    cudaGetSymbolAddress((void**)&kcnt, g_kcnt);

    cudaFuncSetAttribute(gemm_mma, cudaFuncAttributeMaxDynamicSharedMemorySize, GEMM_SMEM);
    cudaFuncSetAttribute(attn_mma, cudaFuncAttributeMaxDynamicSharedMemorySize, ATTN_SMEM);

    // 0) pre-pass splits / transposes / mask scan
    split_fp32<<<(BN * CC + 255) / 256, 256>>>(x, xhi, xlo, BN * CC);
    transpose_split<<<dim3(QKVC / 32, CC / 32), dim3(32, 8)>>>(w_qkv, wqhi, wqlo, CC, QKVC);
    transpose_split<<<dim3(CC / 32, CC / 32), dim3(32, 8)>>>(w_proj, wphi, wplo, CC, CC);
    scan_mask<<<BB, 256>>>(mask, kidx, kcnt);

    // 1) QKV GEMM
    gemm_mma<<<dim3(QKVC / 128, BN / 128), 256, GEMM_SMEM>>>(
        (const uint4*)xhi, (const uint4*)xlo, (const uint4*)wqhi, (const uint4*)wqlo,
        qkv_p, BN, QKVC, CC, nullptr);

    // 2) attention operand prep
    q_split<<<(BB * NN * CC + 255) / 256, 256>>>(qkv_p, qhi, qlo);
    kv_gather<<<dim3(NN / 128, HH, BB), 256>>>(qkv_p, kidx, kcnt, khi, klo, vth, vtl);

    // 3) tensor-core attention over packed keys
    attn_mma<<<dim3(NN / QT, HH, BB), 256, ATTN_SMEM>>>(
        (const uint4*)qhi, (const uint4*)qlo, (const uint4*)khi, (const uint4*)klo,
        (const uint4*)vth, (const uint4*)vtl, kcnt, ahi, alo);

    // 4) projection GEMM + bias
    gemm_mma<<<dim3(CC / 128, BN / 128), 256, GEMM_SMEM>>>(
        (const uint4*)ahi, (const uint4*)alo, (const uint4*)wphi, (const uint4*)wplo,
        out, BN, CC, CC, b_proj);
}

// round 7
// speedup vs baseline: 4.0448x; 1.0250x over previous
#include <cuda_runtime.h>
#include <cuda_bf16.h>
#include <cstdint>
#include <cstddef>

#define BB 2
#define NN 2048
#define CC 768
#define HH 12
#define HD 64
#define BN (BB * NN)          // 4096
#define QKVC (3 * CC)         // 2304

// ---------------------------------------------------------------------------
// Scratch (device globals — no allocation allowed anywhere)
// ---------------------------------------------------------------------------
__device__ __align__(16) __nv_bfloat16 g_xhi[(size_t)BN * CC];
__device__ __align__(16) __nv_bfloat16 g_xlo[(size_t)BN * CC];
__device__ __align__(16) __nv_bfloat16 g_wqhi[(size_t)QKVC * CC]; // Wqkv^T [2304,768]
__device__ __align__(16) __nv_bfloat16 g_wqlo[(size_t)QKVC * CC];
__device__ __align__(16) __nv_bfloat16 g_wphi[(size_t)CC * CC];   // Wproj^T [768,768]
__device__ __align__(16) __nv_bfloat16 g_wplo[(size_t)CC * CC];
__device__ __align__(16) __nv_bfloat16 g_ahi[(size_t)BN * CC];    // attention out hi
__device__ __align__(16) __nv_bfloat16 g_alo[(size_t)BN * CC];    // attention out lo
// attention operands: [b][h][token][64] row-major, split hi/lo
__device__ __align__(16) __nv_bfloat16 g_qhi[(size_t)BB * HH * NN * HD];
__device__ __align__(16) __nv_bfloat16 g_qlo[(size_t)BB * HH * NN * HD];
__device__ __align__(16) __nv_bfloat16 g_khi[(size_t)BB * HH * NN * HD];
__device__ __align__(16) __nv_bfloat16 g_klo[(size_t)BB * HH * NN * HD];
__device__ __align__(16) __nv_bfloat16 g_vhi[(size_t)BB * HH * NN * HD];
__device__ __align__(16) __nv_bfloat16 g_vlo[(size_t)BB * HH * NN * HD];
__device__ int g_kidx[BB * NN];
__device__ int g_kcnt[BB];

// ---------------------------------------------------------------------------
// Family-common PTX helpers (ptxas target is sm_103 w/o 'a' — no tcgen05)
// ---------------------------------------------------------------------------
__device__ __forceinline__ uint32_t smem_u32(const void* p) {
    uint32_t a;
    asm("{ .reg .u64 t; cvta.to.shared.u64 t, %1; cvt.u32.u64 %0, t; }"
        : "=r"(a) : "l"(p));
    return a;
}
#define CP_ASYNC16(dst, src) \
    asm volatile("cp.async.cg.shared.global [%0], [%1], 16;" :: "r"(dst), "l"(src))
#define CP_COMMIT() asm volatile("cp.async.commit_group;" ::: "memory")
#define CP_WAIT(n)  asm volatile("cp.async.wait_group %0;" :: "n"(n) : "memory")

#define LDSM_X4(r0, r1, r2, r3, addr)                                          \
    asm volatile("ldmatrix.sync.aligned.m8n8.x4.shared.b16 {%0,%1,%2,%3}, [%4];" \
                 : "=r"(r0), "=r"(r1), "=r"(r2), "=r"(r3) : "r"(addr))
#define LDSM_X2(r0, r1, addr)                                                  \
    asm volatile("ldmatrix.sync.aligned.m8n8.x2.shared.b16 {%0,%1}, [%2];"     \
                 : "=r"(r0), "=r"(r1) : "r"(addr))
#define LDSM_X2_T(r0, r1, addr)                                                \
    asm volatile("ldmatrix.sync.aligned.m8n8.x2.trans.shared.b16 {%0,%1}, [%2];" \
                 : "=r"(r0), "=r"(r1) : "r"(addr))

#define MMA16816(d, a, b)                                                      \
    asm volatile("mma.sync.aligned.m16n8k16.row.col.f32.bf16.bf16.f32 "        \
                 "{%0,%1,%2,%3}, {%4,%5,%6,%7}, {%8,%9}, {%0,%1,%2,%3};"       \
                 : "+f"((d)[0]), "+f"((d)[1]), "+f"((d)[2]), "+f"((d)[3])      \
                 : "r"((a)[0]), "r"((a)[1]), "r"((a)[2]), "r"((a)[3]),         \
                   "r"((b)[0]), "r"((b)[1]))

__device__ __forceinline__ uint32_t pack_split(float v0, float v1,
                                               uint32_t& lopk) {
    __nv_bfloat16 h0 = __float2bfloat16(v0);
    __nv_bfloat16 h1 = __float2bfloat16(v1);
    __nv_bfloat16 l0 = __float2bfloat16(v0 - __bfloat162float(h0));
    __nv_bfloat16 l1 = __float2bfloat16(v1 - __bfloat162float(h1));
    lopk = ((uint32_t)__bfloat16_as_ushort(l1) << 16) |
           (uint32_t)__bfloat16_as_ushort(l0);
    return ((uint32_t)__bfloat16_as_ushort(h1) << 16) |
           (uint32_t)__bfloat16_as_ushort(h0);
}

// ---------------------------------------------------------------------------
// Shared GEMM mainloop pieces (128x128 tile, 8 warps, K-chunk 32, 2 stages)
// ---------------------------------------------------------------------------
#define RS 40
#define MAT_BYTES (128 * RS * 2)
#define STAGE_BYTES (4 * MAT_BYTES)
#define GEMM_SMEM (2 * STAGE_BYTES)

#define GEMM_MAINLOOP(NCH)                                                     \
    for (int c = 0; c < (NCH); c++) {                                          \
        const int s = c & 1;                                                   \
        if (c + 1 < (NCH)) { prefetch(c + 1, 1 - s); CP_COMMIT(); CP_WAIT(1); }\
        else { CP_WAIT(0); }                                                   \
        __syncthreads();                                                       \
        const uint32_t As_h = sb + s * STAGE_BYTES;                            \
        const uint32_t As_l = As_h + MAT_BYTES;                                \
        const uint32_t Bs_h = As_h + 2 * MAT_BYTES;                            \
        const uint32_t Bs_l = As_h + 3 * MAT_BYTES;                            \
        _Pragma("unroll")                                                      \
        for (int kk = 0; kk < 2; kk++) {                                       \
            uint32_t ah[2][4], al[2][4];                                       \
            _Pragma("unroll")                                                  \
            for (int mt = 0; mt < 2; mt++) {                                   \
                const uint32_t ao =                                            \
                    (uint32_t)((m_base + mt * 16 + a_r) * (RS * 2) +           \
                               (kk * 16 + a_c) * 2);                           \
                LDSM_X4(ah[mt][0], ah[mt][1], ah[mt][2], ah[mt][3], As_h + ao);\
                LDSM_X4(al[mt][0], al[mt][1], al[mt][2], al[mt][3], As_l + ao);\
            }                                                                  \
            _Pragma("unroll")                                                  \
            for (int nt = 0; nt < 8; nt++) {                                   \
                const uint32_t bo =                                            \
                    (uint32_t)((n_base + nt * 8 + b_r) * (RS * 2) +            \
                               (kk * 16 + b_c) * 2);                           \
                uint32_t bh[2], bl[2];                                         \
                LDSM_X2(bh[0], bh[1], Bs_h + bo);                              \
                LDSM_X2(bl[0], bl[1], Bs_l + bo);                              \
                _Pragma("unroll")                                              \
                for (int mt = 0; mt < 2; mt++) {                               \
                    MMA16816(acc[mt][nt], ah[mt], bh);                         \
                    MMA16816(acc[mt][nt], ah[mt], bl);                         \
                    MMA16816(acc[mt][nt], al[mt], bh);                         \
                }                                                              \
            }                                                                  \
        }                                                                      \
        __syncthreads();                                                       \
    }

#define GEMM_COMMON_DECLS                                                      \
    extern __shared__ char smem[];                                             \
    const uint32_t sb = smem_u32(smem);                                        \
    const int tid = threadIdx.x, wid = tid >> 5, lane = tid & 31;              \
    const int wm = wid >> 1, wn = wid & 1;                                     \
    const int m_base = wm * 32, n_base = wn * 64;                              \
    const int a_r = (lane & 15);                                               \
    const int a_c = (lane >> 4) * 8;                                           \
    const int b_r = (lane & 7);                                                \
    const int b_c = ((lane >> 3) & 1) * 8;

// ---------------------------------------------------------------------------
// Proj GEMM: C[M,Nn] = A[M,K]·B[Nn,K]^T + bias (fp32 out)
// ---------------------------------------------------------------------------
__global__ __launch_bounds__(256) void gemm_mma(
    const uint4* __restrict__ Ah, const uint4* __restrict__ Al,
    const uint4* __restrict__ Bh, const uint4* __restrict__ Bl,
    float* __restrict__ C, int M, int Nn, int K,
    const float* __restrict__ bias)
{
    GEMM_COMMON_DECLS
    const int m0 = blockIdx.y * 128, n0 = blockIdx.x * 128;
    const int Krow = K >> 3;
    const int nch = K >> 5;

    auto prefetch = [&](int c, int s) {
        const uint32_t stage = sb + s * STAGE_BYTES;
        const int r = tid >> 2, q = tid & 3;
        const uint32_t doff = (uint32_t)(r * (RS * 2) + q * 16);
        #pragma unroll
        for (int half = 0; half < 2; half++) {
            const int rr = r + half * 64;
            const uint32_t d2 = doff + (uint32_t)(half * 64 * RS * 2);
            const size_t ga = (size_t)(m0 + rr) * Krow + c * 4 + q;
            const size_t gb = (size_t)(n0 + rr) * Krow + c * 4 + q;
            CP_ASYNC16(stage +                 d2, Ah + ga);
            CP_ASYNC16(stage + MAT_BYTES +     d2, Al + ga);
            CP_ASYNC16(stage + 2 * MAT_BYTES + d2, Bh + gb);
            CP_ASYNC16(stage + 3 * MAT_BYTES + d2, Bl + gb);
        }
    };

    float acc[2][8][4] = {};
    prefetch(0, 0);
    CP_COMMIT();
    GEMM_MAINLOOP(nch)

    #pragma unroll
    for (int mt = 0; mt < 2; mt++) {
        const int row0 = m0 + m_base + mt * 16 + (lane >> 2);
        #pragma unroll
        for (int nt = 0; nt < 8; nt++) {
            const int col = n0 + n_base + nt * 8 + (lane & 3) * 2;
            float b0 = bias[col], b1 = bias[col + 1];
            float2 v0 = { acc[mt][nt][0] + b0, acc[mt][nt][1] + b1 };
            float2 v1 = { acc[mt][nt][2] + b0, acc[mt][nt][3] + b1 };
            *(float2*)(C + (size_t)row0 * Nn + col) = v0;
            *(float2*)(C + (size_t)(row0 + 8) * Nn + col) = v1;
        }
    }
}

// ---------------------------------------------------------------------------
// Q GEMM: Q = x·Wq^T, scaled by 0.125, written split-bf16 [b][h][n][64]
// ---------------------------------------------------------------------------
__global__ __launch_bounds__(256) void qgemm(
    const uint4* __restrict__ Ah, const uint4* __restrict__ Al,
    const uint4* __restrict__ Bh, const uint4* __restrict__ Bl,
    __nv_bfloat16* __restrict__ qhi, __nv_bfloat16* __restrict__ qlo)
{
    GEMM_COMMON_DECLS
    const int m0 = blockIdx.y * 128, n0 = blockIdx.x * 128;
    const int Krow = CC >> 3;            // 96
    const int nch = CC >> 5;             // 24

    auto prefetch = [&](int c, int s) {
        const uint32_t stage = sb + s * STAGE_BYTES;
        const int r = tid >> 2, q = tid & 3;
        const uint32_t doff = (uint32_t)(r * (RS * 2) + q * 16);
        #pragma unroll
        for (int half = 0; half < 2; half++) {
            const int rr = r + half * 64;
            const uint32_t d2 = doff + (uint32_t)(half * 64 * RS * 2);
            const size_t ga = (size_t)(m0 + rr) * Krow + c * 4 + q;
            const size_t gb = (size_t)(n0 + rr) * Krow + c * 4 + q;
            CP_ASYNC16(stage +                 d2, Ah + ga);
            CP_ASYNC16(stage + MAT_BYTES +     d2, Al + ga);
            CP_ASYNC16(stage + 2 * MAT_BYTES + d2, Bh + gb);
            CP_ASYNC16(stage + 3 * MAT_BYTES + d2, Bl + gb);
        }
    };

    float acc[2][8][4] = {};
    prefetch(0, 0);
    CP_COMMIT();
    GEMM_MAINLOOP(nch)

    #pragma unroll
    for (int mt = 0; mt < 2; mt++) {
        #pragma unroll
        for (int h2 = 0; h2 < 2; h2++) {
            const int r = m0 + m_base + mt * 16 + h2 * 8 + (lane >> 2);
            const int b = r >> 11, n = r & (NN - 1);
            #pragma unroll
            for (int nt = 0; nt < 8; nt++) {
                const int c = n0 + n_base + nt * 8 + (lane & 3) * 2;
                const int h = c >> 6, d = c & 63;
                const size_t o = (((size_t)b * HH + h) * NN + n) * HD + d;
                uint32_t lopk;
                uint32_t hipk = pack_split(acc[mt][nt][h2 * 2] * 0.125f,
                                           acc[mt][nt][h2 * 2 + 1] * 0.125f, lopk);
                *(uint32_t*)((char*)qhi + o * 2) = hipk;
                *(uint32_t*)((char*)qlo + o * 2) = lopk;
            }
        }
    }
}

// ---------------------------------------------------------------------------
// KV GEMM over mask-packed tokens: A rows gathered via kidx; only blocks
// below the packed count run. B = wq rows [768,2304) (K then V).
// Output split-bf16 [b][h][j][64] (j = packed key index), K and V.
// ---------------------------------------------------------------------------
__global__ __launch_bounds__(256) void kvgemm(
    const uint4* __restrict__ Ah, const uint4* __restrict__ Al,
    const uint4* __restrict__ Bh, const uint4* __restrict__ Bl,
    const int* __restrict__ kidx, const int* __restrict__ kcnt,
    __nv_bfloat16* __restrict__ khi, __nv_bfloat16* __restrict__ klo,
    __nv_bfloat16* __restrict__ vhi, __nv_bfloat16* __restrict__ vlo)
{
    const int bz = blockIdx.z;
    const int cnt = kcnt[bz];
    const int pad = (cnt + 63) & ~63;
    const int m0 = blockIdx.y * 128;
    if (m0 >= pad) return;

    GEMM_COMMON_DECLS
    const int n0 = blockIdx.x * 128;
    const int Krow = CC >> 3;            // 96
    const int nch = CC >> 5;             // 24

    // gathered source rows (chunk-invariant)
    const int pr = tid >> 2, pq = tid & 3;
    const int j1 = m0 + pr, j2 = j1 + 64;
    const int s1 = (j1 < cnt) ? kidx[bz * NN + j1] : 0;
    const int s2 = (j2 < cnt) ? kidx[bz * NN + j2] : 0;

    auto prefetch = [&](int c, int s) {
        const uint32_t stage = sb + s * STAGE_BYTES;
        const uint32_t doff = (uint32_t)(pr * (RS * 2) + pq * 16);
        #pragma unroll
        for (int half = 0; half < 2; half++) {
            const int srow = half ? s2 : s1;
            const uint32_t d2 = doff + (uint32_t)(half * 64 * RS * 2);
            const size_t ga = (size_t)(bz * NN + srow) * Krow + c * 4 + pq;
            const size_t gb = (size_t)(n0 + pr + half * 64) * Krow + c * 4 + pq;
            CP_ASYNC16(stage +                 d2, Ah + ga);
            CP_ASYNC16(stage + MAT_BYTES +     d2, Al + ga);
            CP_ASYNC16(stage + 2 * MAT_BYTES + d2, Bh + gb);
            CP_ASYNC16(stage + 3 * MAT_BYTES + d2, Bl + gb);
        }
    };

    float acc[2][8][4] = {};
    prefetch(0, 0);
    CP_COMMIT();
    GEMM_MAINLOOP(nch)

    #pragma unroll
    for (int mt = 0; mt < 2; mt++) {
        #pragma unroll
        for (int h2 = 0; h2 < 2; h2++) {
            const int j = m0 + m_base + mt * 16 + h2 * 8 + (lane >> 2);
            #pragma unroll
            for (int nt = 0; nt < 8; nt++) {
                const int c = n0 + n_base + nt * 8 + (lane & 3) * 2;
                const int isV = c >= CC;
                const int cc = isV ? c - CC : c;   // R6 fix: CC=768 is NOT pow2
                const int h = cc >> 6, d = cc & 63;
                const size_t o = (((size_t)bz * HH + h) * NN + j) * HD + d;
                uint32_t lopk;
                uint32_t hipk = pack_split(acc[mt][nt][h2 * 2],
                                           acc[mt][nt][h2 * 2 + 1], lopk);
                __nv_bfloat16* dh = isV ? vhi : khi;
                __nv_bfloat16* dl = isV ? vlo : klo;
                *(uint32_t*)((char*)dh + o * 2) = hipk;
                *(uint32_t*)((char*)dl + o * 2) = lopk;
            }
        }
    }
}

// ---------------------------------------------------------------------------
// mask prefix scan: compact indices of unmasked keys per batch
// ---------------------------------------------------------------------------
__global__ void scan_mask(const int* __restrict__ mask, int* __restrict__ kidx,
                          int* __restrict__ kcnt)
{
    __shared__ int part[256];
    const int b = blockIdx.x, t = threadIdx.x;
    const int* m = mask + b * NN;
    int loc[8], c = 0;
    #pragma unroll
    for (int i = 0; i < 8; i++) { loc[i] = c; c += m[t * 8 + i]; }
    part[t] = c;
    __syncthreads();
    for (int off = 1; off < 256; off <<= 1) {
        int v = (t >= off) ? part[t - off] : 0;
        __syncthreads();
        part[t] += v;
        __syncthreads();
    }
    int excl = part[t] - c;
    #pragma unroll
    for (int i = 0; i < 8; i++)
        if (m[t * 8 + i]) kidx[b * NN + excl + loc[i]] = t * 8 + i;
    if (t == 255) kcnt[b] = part[255];
}

// ---------------------------------------------------------------------------
// Tensor-core attention over packed keys (V row-major, ldmatrix.trans for PV).
// ---------------------------------------------------------------------------
#define QT 128
#define KT 64
#define PADB 144                 // 72 bf16 per row
#define SM_QL   18432
#define SM_STG  36864
#define STG_SZ  36864            // Kh,Kl,Vh,Vl : 9216 each
#define SM_P    110592
#define SM_PL   129024
#define SM_DEN  147456
#define ATTN_SMEM (147456 + 512)

__global__ __launch_bounds__(256) void attn_mma(
    const uint4* __restrict__ Qh, const uint4* __restrict__ Ql,
    const uint4* __restrict__ Kh, const uint4* __restrict__ Kl,
    const uint4* __restrict__ Vh, const uint4* __restrict__ Vl,
    const int* __restrict__ kcnt,
    __nv_bfloat16* __restrict__ ahi, __nv_bfloat16* __restrict__ alo)
{
    extern __shared__ char sm[];
    const uint32_t sb = smem_u32(sm);
    const int b = blockIdx.z, h = blockIdx.y, q0 = blockIdx.x * QT;
    const int tid = threadIdx.x, wid = tid >> 5, lane = tid & 31;
    const int wm = wid >> 1, wn = wid & 1;
    const int mb = wm * 32, nb = wn * 32;
    const int cnt = kcnt[b];
    const int ntiles = (cnt + KT - 1) / KT;
    const size_t bh = (size_t)b * HH + h;

    float* denom_s = (float*)(sm + SM_DEN);
    if (tid < 128) denom_s[tid] = 0.0f;

    // resident Q tile (hi/lo)
    #pragma unroll
    for (int it = 0; it < 4; it++) {
        int idx = it * 256 + tid;
        int r = idx >> 3, c = idx & 7;
        size_t gi = (bh * NN + q0 + r) * 8 + c;
        *(uint4*)(sm + r * PADB + c * 16) = Qh[gi];
        *(uint4*)(sm + SM_QL + r * PADB + c * 16) = Ql[gi];
    }

    auto prefetch = [&](int t, int s) {
        const uint32_t stg = sb + SM_STG + s * STG_SZ;
        const int k0 = t * KT;
        #pragma unroll
        for (int it = 0; it < 8; it++) {
            int idx = it * 256 + tid;
            int mat = idx >> 9;                // 0 Kh,1 Kl,2 Vh,3 Vl
            int r = (idx >> 3) & 63, c = idx & 7;
            uint32_t dst = stg + mat * 9216 + (uint32_t)(r * PADB + c * 16);
            const uint4* g = (mat == 0) ? Kh : (mat == 1) ? Kl
                           : (mat == 2) ? Vh : Vl;
            size_t gi = (bh * NN + k0 + r) * 8 + c;
            CP_ASYNC16(dst, g + gi);
        }
    };

    float accO[2][4][4] = {};
    float denA[2][2] = {};

    const int a_r = lane & 15, a_c = (lane >> 4) * 8;
    const int b_r = lane & 7,  b_c = ((lane >> 3) & 1) * 8;
    const int t_r = lane & 15;                 // trans ldmatrix: j-rows

    prefetch(0, 0);
    CP_COMMIT();

    for (int t = 0; t < ntiles; t++) {
        const int s = t & 1;
        const int k0 = t * KT;
        if (t + 1 < ntiles) { prefetch(t + 1, 1 - s); CP_COMMIT(); CP_WAIT(1); }
        else { CP_WAIT(0); }
        __syncthreads();

        const uint32_t Ksh = sb + SM_STG + s * STG_SZ;
        const uint32_t Ksl = Ksh + 9216;
        const uint32_t Vsh = Ksh + 18432;
        const uint32_t Vsl = Ksh + 27648;

        // S = Q K^T (split bf16, 3 products)
        float accS[2][4][4] = {};
        #pragma unroll
        for (int ks = 0; ks < 4; ks++) {
            uint32_t ah[2][4], al[2][4];
            #pragma unroll
            for (int mt = 0; mt < 2; mt++) {
                uint32_t ao = sb + (uint32_t)((mb + mt * 16 + a_r) * PADB +
                                              (ks * 16 + a_c) * 2);
                LDSM_X4(ah[mt][0], ah[mt][1], ah[mt][2], ah[mt][3], ao);
                LDSM_X4(al[mt][0], al[mt][1], al[mt][2], al[mt][3], ao + SM_QL);
            }
            #pragma unroll
            for (int nt = 0; nt < 4; nt++) {
                uint32_t bo = (uint32_t)((nb + nt * 8 + b_r) * PADB +
                                         (ks * 16 + b_c) * 2);
                uint32_t bhv[2], blv[2];
                LDSM_X2(bhv[0], bhv[1], Ksh + bo);
                LDSM_X2(blv[0], blv[1], Ksl + bo);
                #pragma unroll
                for (int mt = 0; mt < 2; mt++) {
                    MMA16816(accS[mt][nt], ah[mt], bhv);
                    MMA16816(accS[mt][nt], ah[mt], blv);
                    MMA16816(accS[mt][nt], al[mt], bhv);
                }
            }
        }

        // p = exp(s)*(j<cnt) fp32; split Ph/Pl; denom from exact p
        #pragma unroll
        for (int mt = 0; mt < 2; mt++) {
            #pragma unroll
            for (int nt = 0; nt < 4; nt++) {
                int c0 = nb + nt * 8 + (lane & 3) * 2;
                float m0v = (k0 + c0     < cnt) ? 1.f : 0.f;
                float m1v = (k0 + c0 + 1 < cnt) ? 1.f : 0.f;
                #pragma unroll
                for (int h2 = 0; h2 < 2; h2++) {
                    int r = mb + mt * 16 + h2 * 8 + (lane >> 2);
                    float p0 = __expf(accS[mt][nt][h2 * 2 + 0]) * m0v;
                    float p1 = __expf(accS[mt][nt][h2 * 2 + 1]) * m1v;
                    denA[mt][h2] += p0 + p1;
                    uint32_t lopk;
                    uint32_t hipk = pack_split(p0, p1, lopk);
                    *(uint32_t*)(sm + SM_P  + r * PADB + c0 * 2) = hipk;
                    *(uint32_t*)(sm + SM_PL + r * PADB + c0 * 2) = lopk;
                }
            }
        }
        __syncthreads();

        // O += Ph·Vh + Pl·Vh + Ph·Vl   (V row-major [j][d] via ldmatrix.trans)
        #pragma unroll
        for (int kk = 0; kk < 4; kk++) {
            uint32_t aph[2][4], apl[2][4];
            #pragma unroll
            for (int mt = 0; mt < 2; mt++) {
                uint32_t ao = (uint32_t)((mb + mt * 16 + a_r) * PADB +
                                         (kk * 16 + a_c) * 2);
                LDSM_X4(aph[mt][0], aph[mt][1], aph[mt][2], aph[mt][3],
                        sb + SM_P + ao);
                LDSM_X4(apl[mt][0], apl[mt][1], apl[mt][2], apl[mt][3],
                        sb + SM_PL + ao);
            }
            #pragma unroll
            for (int nt = 0; nt < 4; nt++) {
                uint32_t bo = (uint32_t)((kk * 16 + t_r) * PADB +
                                         (nb + nt * 8) * 2);
                uint32_t bvh[2], bvl[2];
                LDSM_X2_T(bvh[0], bvh[1], Vsh + bo);
                LDSM_X2_T(bvl[0], bvl[1], Vsl + bo);
                #pragma unroll
                for (int mt = 0; mt < 2; mt++) {
                    MMA16816(accO[mt][nt], aph[mt], bvh);
                    MMA16816(accO[mt][nt], apl[mt], bvh);
                    MMA16816(accO[mt][nt], aph[mt], bvl);
                }
            }
        }
        __syncthreads();
    }

    // denom: quad-reduce then smem atomics
    #pragma unroll
    for (int mt = 0; mt < 2; mt++)
        #pragma unroll
        for (int h2 = 0; h2 < 2; h2++) {
            float v = denA[mt][h2];
            v += __shfl_xor_sync(0xffffffffu, v, 1);
            v += __shfl_xor_sync(0xffffffffu, v, 2);
            if ((lane & 3) == 0)
                atomicAdd(&denom_s[mb + mt * 16 + h2 * 8 + (lane >> 2)], v);
        }
    __syncthreads();

    // epilogue: divide, split to bf16 hi/lo for proj GEMM
    #pragma unroll
    for (int mt = 0; mt < 2; mt++) {
        #pragma unroll
        for (int h2 = 0; h2 < 2; h2++) {
            int r = mb + mt * 16 + h2 * 8 + (lane >> 2);
            float inv = 1.0f / denom_s[r];
            size_t rowg = (size_t)(b * NN + q0 + r) * CC + h * HD;
            #pragma unroll
            for (int nt = 0; nt < 4; nt++) {
                int c0 = nb + nt * 8 + (lane & 3) * 2;
                uint32_t lopk;
                uint32_t hipk = pack_split(accO[mt][nt][h2 * 2 + 0] * inv,
                                           accO[mt][nt][h2 * 2 + 1] * inv, lopk);
                *(uint32_t*)((char*)ahi + (rowg + c0) * 2) = hipk;
                *(uint32_t*)((char*)alo + (rowg + c0) * 2) = lopk;
            }
        }
    }
}

// ---------------------------------------------------------------------------
// pre-pass splits
// ---------------------------------------------------------------------------
__global__ void split_fp32(const float* __restrict__ in,
                           __nv_bfloat16* __restrict__ hi,
                           __nv_bfloat16* __restrict__ lo, int n)
{
    int i = blockIdx.x * blockDim.x + threadIdx.x;
    if (i < n) {
        float v = in[i];
        __nv_bfloat16 h = __float2bfloat16(v);
        hi[i] = h;
        lo[i] = __float2bfloat16(v - __bfloat162float(h));
    }
}

__global__ void transpose_split(const float* __restrict__ W,
                                __nv_bfloat16* __restrict__ hi,
                                __nv_bfloat16* __restrict__ lo, int K, int N)
{
    __shared__ float t[32][33];
    const int n0 = blockIdx.x * 32, k0 = blockIdx.y * 32;
    const int tx = threadIdx.x, ty = threadIdx.y;
    #pragma unroll
    for (int j = 0; j < 4; j++)
        t[ty + 8 * j][tx] = W[(size_t)(k0 + ty + 8 * j) * N + n0 + tx];
    __syncthreads();
    #pragma unroll
    for (int j = 0; j < 4; j++) {
        int nl = ty + 8 * j;
        float v = t[tx][nl];
        __nv_bfloat16 h = __float2bfloat16(v);
        size_t o = (size_t)(n0 + nl) * K + k0 + tx;
        hi[o] = h;
        lo[o] = __float2bfloat16(v - __bfloat162float(h));
    }
}

// ---------------------------------------------------------------------------
extern "C" void kernel_launch(void* const* d_in, const int* in_sizes, int n_in,
                              void* d_out, int out_size)
{
    const float* x      = (const float*)d_in[0];
    const int*   mask   = (const int*)  d_in[1];
    const float* w_qkv  = (const float*)d_in[2];
    const float* w_proj = (const float*)d_in[3];
    const float* b_proj = (const float*)d_in[4];
    float* out = (float*)d_out;

    __nv_bfloat16 *xhi, *xlo, *wqhi, *wqlo, *wphi, *wplo, *ahi, *alo;
    __nv_bfloat16 *qhi, *qlo, *khi, *klo, *vhi, *vlo;
    int *kidx, *kcnt;
    cudaGetSymbolAddress((void**)&xhi, g_xhi);
    cudaGetSymbolAddress((void**)&xlo, g_xlo);
    cudaGetSymbolAddress((void**)&wqhi, g_wqhi);
    cudaGetSymbolAddress((void**)&wqlo, g_wqlo);
    cudaGetSymbolAddress((void**)&wphi, g_wphi);
    cudaGetSymbolAddress((void**)&wplo, g_wplo);
    cudaGetSymbolAddress((void**)&ahi, g_ahi);
    cudaGetSymbolAddress((void**)&alo, g_alo);
    cudaGetSymbolAddress((void**)&qhi, g_qhi);
    cudaGetSymbolAddress((void**)&qlo, g_qlo);
    cudaGetSymbolAddress((void**)&khi, g_khi);
    cudaGetSymbolAddress((void**)&klo, g_klo);
    cudaGetSymbolAddress((void**)&vhi, g_vhi);
    cudaGetSymbolAddress((void**)&vlo, g_vlo);
    cudaGetSymbolAddress((void**)&kidx, g_kidx);
    cudaGetSymbolAddress((void**)&kcnt, g_kcnt);

    cudaFuncSetAttribute(gemm_mma, cudaFuncAttributeMaxDynamicSharedMemorySize, GEMM_SMEM);
    cudaFuncSetAttribute(qgemm, cudaFuncAttributeMaxDynamicSharedMemorySize, GEMM_SMEM);
    cudaFuncSetAttribute(kvgemm, cudaFuncAttributeMaxDynamicSharedMemorySize, GEMM_SMEM);
    cudaFuncSetAttribute(attn_mma, cudaFuncAttributeMaxDynamicSharedMemorySize, ATTN_SMEM);

    // 0) pre-pass splits / transposes / mask scan
    split_fp32<<<(BN * CC + 255) / 256, 256>>>(x, xhi, xlo, BN * CC);
    transpose_split<<<dim3(QKVC / 32, CC / 32), dim3(32, 8)>>>(w_qkv, wqhi, wqlo, CC, QKVC);
    transpose_split<<<dim3(CC / 32, CC / 32), dim3(32, 8)>>>(w_proj, wphi, wplo, CC, CC);
    scan_mask<<<BB, 256>>>(mask, kidx, kcnt);

    // 1) Q GEMM (fused scale+split epilogue)
    qgemm<<<dim3(CC / 128, BN / 128), 256, GEMM_SMEM>>>(
        (const uint4*)xhi, (const uint4*)xlo, (const uint4*)wqhi, (const uint4*)wqlo,
        qhi, qlo);

    // 2) KV GEMM over packed tokens (gathered input, split epilogue)
    kvgemm<<<dim3(2 * CC / 128, NN / 128, BB), 256, GEMM_SMEM>>>(
        (const uint4*)xhi, (const uint4*)xlo,
        (const uint4*)(wqhi + (size_t)CC * CC), (const uint4*)(wqlo + (size_t)CC * CC),
        kidx, kcnt, khi, klo, vhi, vlo);

    // 3) tensor-core attention over packed keys
    attn_mma<<<dim3(NN / QT, HH, BB), 256, ATTN_SMEM>>>(
        (const uint4*)qhi, (const uint4*)qlo, (const uint4*)khi, (const uint4*)klo,
        (const uint4*)vhi, (const uint4*)vlo, kcnt, ahi, alo);

    // 4) projection GEMM + bias
    gemm_mma<<<dim3(CC / 128, BN / 128), 256, GEMM_SMEM>>>(
        (const uint4*)ahi, (const uint4*)alo, (const uint4*)wphi, (const uint4*)wplo,
        out, BN, CC, CC, b_proj);
}

// round 8
// speedup vs baseline: 4.2312x; 1.0461x over previous
#include <cuda_runtime.h>
#include <cuda_bf16.h>
#include <cstdint>
#include <cstddef>

#define BB 2
#define NN 2048
#define CC 768
#define HH 12
#define HD 64
#define BN (BB * NN)          // 4096
#define QKVC (3 * CC)         // 2304

// ---------------------------------------------------------------------------
// Scratch (device globals — no allocation allowed anywhere)
// ---------------------------------------------------------------------------
__device__ __align__(16) __nv_bfloat16 g_xhi[(size_t)BN * CC];
__device__ __align__(16) __nv_bfloat16 g_xlo[(size_t)BN * CC];
__device__ __align__(16) __nv_bfloat16 g_wqhi[(size_t)QKVC * CC]; // Wqkv^T [2304,768]
__device__ __align__(16) __nv_bfloat16 g_wqlo[(size_t)QKVC * CC];
__device__ __align__(16) __nv_bfloat16 g_wphi[(size_t)CC * CC];   // Wproj^T [768,768]
__device__ __align__(16) __nv_bfloat16 g_wplo[(size_t)CC * CC];
__device__ __align__(16) __nv_bfloat16 g_ahi[(size_t)BN * CC];    // attention out hi
__device__ __align__(16) __nv_bfloat16 g_alo[(size_t)BN * CC];    // attention out lo
// attention operands: [b][h][token][64] row-major, split hi/lo
__device__ __align__(16) __nv_bfloat16 g_qhi[(size_t)BB * HH * NN * HD];
__device__ __align__(16) __nv_bfloat16 g_qlo[(size_t)BB * HH * NN * HD];
__device__ __align__(16) __nv_bfloat16 g_khi[(size_t)BB * HH * NN * HD];
__device__ __align__(16) __nv_bfloat16 g_klo[(size_t)BB * HH * NN * HD];
__device__ __align__(16) __nv_bfloat16 g_vhi[(size_t)BB * HH * NN * HD];
__device__ __align__(16) __nv_bfloat16 g_vlo[(size_t)BB * HH * NN * HD];
__device__ int g_kidx[BB * NN];
__device__ int g_kcnt[BB];

// ---------------------------------------------------------------------------
// Family-common PTX helpers (ptxas target is sm_103 w/o 'a' — no tcgen05)
// ---------------------------------------------------------------------------
__device__ __forceinline__ uint32_t smem_u32(const void* p) {
    uint32_t a;
    asm("{ .reg .u64 t; cvta.to.shared.u64 t, %1; cvt.u32.u64 %0, t; }"
        : "=r"(a) : "l"(p));
    return a;
}
#define CP_ASYNC16(dst, src) \
    asm volatile("cp.async.cg.shared.global [%0], [%1], 16;" :: "r"(dst), "l"(src))
#define CP_COMMIT() asm volatile("cp.async.commit_group;" ::: "memory")
#define CP_WAIT(n)  asm volatile("cp.async.wait_group %0;" :: "n"(n) : "memory")

#define LDSM_X4(r0, r1, r2, r3, addr)                                          \
    asm volatile("ldmatrix.sync.aligned.m8n8.x4.shared.b16 {%0,%1,%2,%3}, [%4];" \
                 : "=r"(r0), "=r"(r1), "=r"(r2), "=r"(r3) : "r"(addr))
#define LDSM_X2(r0, r1, addr)                                                  \
    asm volatile("ldmatrix.sync.aligned.m8n8.x2.shared.b16 {%0,%1}, [%2];"     \
                 : "=r"(r0), "=r"(r1) : "r"(addr))
#define LDSM_X2_T(r0, r1, addr)                                                \
    asm volatile("ldmatrix.sync.aligned.m8n8.x2.trans.shared.b16 {%0,%1}, [%2];" \
                 : "=r"(r0), "=r"(r1) : "r"(addr))

#define MMA16816(d, a, b)                                                      \
    asm volatile("mma.sync.aligned.m16n8k16.row.col.f32.bf16.bf16.f32 "        \
                 "{%0,%1,%2,%3}, {%4,%5,%6,%7}, {%8,%9}, {%0,%1,%2,%3};"       \
                 : "+f"((d)[0]), "+f"((d)[1]), "+f"((d)[2]), "+f"((d)[3])      \
                 : "r"((a)[0]), "r"((a)[1]), "r"((a)[2]), "r"((a)[3]),         \
                   "r"((b)[0]), "r"((b)[1]))

__device__ __forceinline__ uint32_t pack_split(float v0, float v1,
                                               uint32_t& lopk) {
    __nv_bfloat16 h0 = __float2bfloat16(v0);
    __nv_bfloat16 h1 = __float2bfloat16(v1);
    __nv_bfloat16 l0 = __float2bfloat16(v0 - __bfloat162float(h0));
    __nv_bfloat16 l1 = __float2bfloat16(v1 - __bfloat162float(h1));
    lopk = ((uint32_t)__bfloat16_as_ushort(l1) << 16) |
           (uint32_t)__bfloat16_as_ushort(l0);
    return ((uint32_t)__bfloat16_as_ushort(h1) << 16) |
           (uint32_t)__bfloat16_as_ushort(h0);
}

// ---------------------------------------------------------------------------
// Shared GEMM mainloop pieces (128x128 tile, 8 warps, K-chunk 32, 2 stages)
// ---------------------------------------------------------------------------
#define RS 40
#define MAT_BYTES (128 * RS * 2)
#define STAGE_BYTES (4 * MAT_BYTES)
#define GEMM_SMEM (2 * STAGE_BYTES)

#define GEMM_MAINLOOP(NCH)                                                     \
    for (int c = 0; c < (NCH); c++) {                                          \
        const int s = c & 1;                                                   \
        if (c + 1 < (NCH)) { prefetch(c + 1, 1 - s); CP_COMMIT(); CP_WAIT(1); }\
        else { CP_WAIT(0); }                                                   \
        __syncthreads();                                                       \
        const uint32_t As_h = sb + s * STAGE_BYTES;                            \
        const uint32_t As_l = As_h + MAT_BYTES;                                \
        const uint32_t Bs_h = As_h + 2 * MAT_BYTES;                            \
        const uint32_t Bs_l = As_h + 3 * MAT_BYTES;                            \
        _Pragma("unroll")                                                      \
        for (int kk = 0; kk < 2; kk++) {                                       \
            uint32_t ah[2][4], al[2][4];                                       \
            _Pragma("unroll")                                                  \
            for (int mt = 0; mt < 2; mt++) {                                   \
                const uint32_t ao =                                            \
                    (uint32_t)((m_base + mt * 16 + a_r) * (RS * 2) +           \
                               (kk * 16 + a_c) * 2);                           \
                LDSM_X4(ah[mt][0], ah[mt][1], ah[mt][2], ah[mt][3], As_h + ao);\
                LDSM_X4(al[mt][0], al[mt][1], al[mt][2], al[mt][3], As_l + ao);\
            }                                                                  \
            _Pragma("unroll")                                                  \
            for (int nt = 0; nt < 8; nt++) {                                   \
                const uint32_t bo =                                            \
                    (uint32_t)((n_base + nt * 8 + b_r) * (RS * 2) +            \
                               (kk * 16 + b_c) * 2);                           \
                uint32_t bh[2], bl[2];                                         \
                LDSM_X2(bh[0], bh[1], Bs_h + bo);                              \
                LDSM_X2(bl[0], bl[1], Bs_l + bo);                              \
                _Pragma("unroll")                                              \
                for (int mt = 0; mt < 2; mt++) {                               \
                    MMA16816(acc[mt][nt], ah[mt], bh);                         \
                    MMA16816(acc[mt][nt], ah[mt], bl);                         \
                    MMA16816(acc[mt][nt], al[mt], bh);                         \
                }                                                              \
            }                                                                  \
        }                                                                      \
        __syncthreads();                                                       \
    }

#define GEMM_COMMON_DECLS                                                      \
    extern __shared__ char smem[];                                             \
    const uint32_t sb = smem_u32(smem);                                        \
    const int tid = threadIdx.x, wid = tid >> 5, lane = tid & 31;              \
    const int wm = wid >> 1, wn = wid & 1;                                     \
    const int m_base = wm * 32, n_base = wn * 64;                              \
    const int a_r = (lane & 15);                                               \
    const int a_c = (lane >> 4) * 8;                                           \
    const int b_r = (lane & 7);                                                \
    const int b_c = ((lane >> 3) & 1) * 8;

// ---------------------------------------------------------------------------
// Proj GEMM: C[M,Nn] = A[M,K]·B[Nn,K]^T + bias (fp32 out)
// ---------------------------------------------------------------------------
__global__ __launch_bounds__(256) void gemm_mma(
    const uint4* __restrict__ Ah, const uint4* __restrict__ Al,
    const uint4* __restrict__ Bh, const uint4* __restrict__ Bl,
    float* __restrict__ C, int M, int Nn, int K,
    const float* __restrict__ bias)
{
    GEMM_COMMON_DECLS
    const int m0 = blockIdx.y * 128, n0 = blockIdx.x * 128;
    const int Krow = K >> 3;
    const int nch = K >> 5;

    auto prefetch = [&](int c, int s) {
        const uint32_t stage = sb + s * STAGE_BYTES;
        const int r = tid >> 2, q = tid & 3;
        const uint32_t doff = (uint32_t)(r * (RS * 2) + q * 16);
        #pragma unroll
        for (int half = 0; half < 2; half++) {
            const int rr = r + half * 64;
            const uint32_t d2 = doff + (uint32_t)(half * 64 * RS * 2);
            const size_t ga = (size_t)(m0 + rr) * Krow + c * 4 + q;
            const size_t gb = (size_t)(n0 + rr) * Krow + c * 4 + q;
            CP_ASYNC16(stage +                 d2, Ah + ga);
            CP_ASYNC16(stage + MAT_BYTES +     d2, Al + ga);
            CP_ASYNC16(stage + 2 * MAT_BYTES + d2, Bh + gb);
            CP_ASYNC16(stage + 3 * MAT_BYTES + d2, Bl + gb);
        }
    };

    float acc[2][8][4] = {};
    prefetch(0, 0);
    CP_COMMIT();
    GEMM_MAINLOOP(nch)

    #pragma unroll
    for (int mt = 0; mt < 2; mt++) {
        const int row0 = m0 + m_base + mt * 16 + (lane >> 2);
        #pragma unroll
        for (int nt = 0; nt < 8; nt++) {
            const int col = n0 + n_base + nt * 8 + (lane & 3) * 2;
            float b0 = bias[col], b1 = bias[col + 1];
            float2 v0 = { acc[mt][nt][0] + b0, acc[mt][nt][1] + b1 };
            float2 v1 = { acc[mt][nt][2] + b0, acc[mt][nt][3] + b1 };
            *(float2*)(C + (size_t)row0 * Nn + col) = v0;
            *(float2*)(C + (size_t)(row0 + 8) * Nn + col) = v1;
        }
    }
}

// ---------------------------------------------------------------------------
// Q GEMM: Q = x·Wq^T, scaled by 0.125, written split-bf16 [b][h][n][64]
// ---------------------------------------------------------------------------
__global__ __launch_bounds__(256) void qgemm(
    const uint4* __restrict__ Ah, const uint4* __restrict__ Al,
    const uint4* __restrict__ Bh, const uint4* __restrict__ Bl,
    __nv_bfloat16* __restrict__ qhi, __nv_bfloat16* __restrict__ qlo)
{
    GEMM_COMMON_DECLS
    const int m0 = blockIdx.y * 128, n0 = blockIdx.x * 128;
    const int Krow = CC >> 3;            // 96
    const int nch = CC >> 5;             // 24

    auto prefetch = [&](int c, int s) {
        const uint32_t stage = sb + s * STAGE_BYTES;
        const int r = tid >> 2, q = tid & 3;
        const uint32_t doff = (uint32_t)(r * (RS * 2) + q * 16);
        #pragma unroll
        for (int half = 0; half < 2; half++) {
            const int rr = r + half * 64;
            const uint32_t d2 = doff + (uint32_t)(half * 64 * RS * 2);
            const size_t ga = (size_t)(m0 + rr) * Krow + c * 4 + q;
            const size_t gb = (size_t)(n0 + rr) * Krow + c * 4 + q;
            CP_ASYNC16(stage +                 d2, Ah + ga);
            CP_ASYNC16(stage + MAT_BYTES +     d2, Al + ga);
            CP_ASYNC16(stage + 2 * MAT_BYTES + d2, Bh + gb);
            CP_ASYNC16(stage + 3 * MAT_BYTES + d2, Bl + gb);
        }
    };

    float acc[2][8][4] = {};
    prefetch(0, 0);
    CP_COMMIT();
    GEMM_MAINLOOP(nch)

    #pragma unroll
    for (int mt = 0; mt < 2; mt++) {
        #pragma unroll
        for (int h2 = 0; h2 < 2; h2++) {
            const int r = m0 + m_base + mt * 16 + h2 * 8 + (lane >> 2);
            const int b = r >> 11, n = r & (NN - 1);
            #pragma unroll
            for (int nt = 0; nt < 8; nt++) {
                const int c = n0 + n_base + nt * 8 + (lane & 3) * 2;
                const int h = c >> 6, d = c & 63;
                const size_t o = (((size_t)b * HH + h) * NN + n) * HD + d;
                uint32_t lopk;
                uint32_t hipk = pack_split(acc[mt][nt][h2 * 2] * 0.125f,
                                           acc[mt][nt][h2 * 2 + 1] * 0.125f, lopk);
                *(uint32_t*)((char*)qhi + o * 2) = hipk;
                *(uint32_t*)((char*)qlo + o * 2) = lopk;
            }
        }
    }
}

// ---------------------------------------------------------------------------
// KV GEMM over mask-packed tokens: A rows gathered via kidx; only blocks
// below the packed count run. B = wq rows [768,2304) (K then V).
// ---------------------------------------------------------------------------
__global__ __launch_bounds__(256) void kvgemm(
    const uint4* __restrict__ Ah, const uint4* __restrict__ Al,
    const uint4* __restrict__ Bh, const uint4* __restrict__ Bl,
    const int* __restrict__ kidx, const int* __restrict__ kcnt,
    __nv_bfloat16* __restrict__ khi, __nv_bfloat16* __restrict__ klo,
    __nv_bfloat16* __restrict__ vhi, __nv_bfloat16* __restrict__ vlo)
{
    const int bz = blockIdx.z;
    const int cnt = kcnt[bz];
    const int pad = (cnt + 63) & ~63;
    const int m0 = blockIdx.y * 128;
    if (m0 >= pad) return;

    GEMM_COMMON_DECLS
    const int n0 = blockIdx.x * 128;
    const int Krow = CC >> 3;            // 96
    const int nch = CC >> 5;             // 24

    const int pr = tid >> 2, pq = tid & 3;
    const int j1 = m0 + pr, j2 = j1 + 64;
    const int s1 = (j1 < cnt) ? kidx[bz * NN + j1] : 0;
    const int s2 = (j2 < cnt) ? kidx[bz * NN + j2] : 0;

    auto prefetch = [&](int c, int s) {
        const uint32_t stage = sb + s * STAGE_BYTES;
        const uint32_t doff = (uint32_t)(pr * (RS * 2) + pq * 16);
        #pragma unroll
        for (int half = 0; half < 2; half++) {
            const int srow = half ? s2 : s1;
            const uint32_t d2 = doff + (uint32_t)(half * 64 * RS * 2);
            const size_t ga = (size_t)(bz * NN + srow) * Krow + c * 4 + pq;
            const size_t gb = (size_t)(n0 + pr + half * 64) * Krow + c * 4 + pq;
            CP_ASYNC16(stage +                 d2, Ah + ga);
            CP_ASYNC16(stage + MAT_BYTES +     d2, Al + ga);
            CP_ASYNC16(stage + 2 * MAT_BYTES + d2, Bh + gb);
            CP_ASYNC16(stage + 3 * MAT_BYTES + d2, Bl + gb);
        }
    };

    float acc[2][8][4] = {};
    prefetch(0, 0);
    CP_COMMIT();
    GEMM_MAINLOOP(nch)

    #pragma unroll
    for (int mt = 0; mt < 2; mt++) {
        #pragma unroll
        for (int h2 = 0; h2 < 2; h2++) {
            const int j = m0 + m_base + mt * 16 + h2 * 8 + (lane >> 2);
            #pragma unroll
            for (int nt = 0; nt < 8; nt++) {
                const int c = n0 + n_base + nt * 8 + (lane & 3) * 2;
                const int isV = c >= CC;
                const int cc = isV ? c - CC : c;
                const int h = cc >> 6, d = cc & 63;
                const size_t o = (((size_t)bz * HH + h) * NN + j) * HD + d;
                uint32_t lopk;
                uint32_t hipk = pack_split(acc[mt][nt][h2 * 2],
                                           acc[mt][nt][h2 * 2 + 1], lopk);
                __nv_bfloat16* dh = isV ? vhi : khi;
                __nv_bfloat16* dl = isV ? vlo : klo;
                *(uint32_t*)((char*)dh + o * 2) = hipk;
                *(uint32_t*)((char*)dl + o * 2) = lopk;
            }
        }
    }
}

// ---------------------------------------------------------------------------
// mask prefix scan: compact indices of unmasked keys per batch
// ---------------------------------------------------------------------------
__global__ void scan_mask(const int* __restrict__ mask, int* __restrict__ kidx,
                          int* __restrict__ kcnt)
{
    __shared__ int part[256];
    const int b = blockIdx.x, t = threadIdx.x;
    const int* m = mask + b * NN;
    int loc[8], c = 0;
    #pragma unroll
    for (int i = 0; i < 8; i++) { loc[i] = c; c += m[t * 8 + i]; }
    part[t] = c;
    __syncthreads();
    for (int off = 1; off < 256; off <<= 1) {
        int v = (t >= off) ? part[t - off] : 0;
        __syncthreads();
        part[t] += v;
        __syncthreads();
    }
    int excl = part[t] - c;
    #pragma unroll
    for (int i = 0; i < 8; i++)
        if (m[t * 8 + i]) kidx[b * NN + excl + loc[i]] = t * 8 + i;
    if (t == 255) kcnt[b] = part[255];
}

// ---------------------------------------------------------------------------
// Tensor-core attention, P-in-registers (FA2-style fragment reuse).
// Warp (wm, wn): S for rows mb..mb+31 x keys nb..nb+31; exp+split packed
// directly into A fragments; PV over its 32-key half x full d=64;
// cross-pair O reduction through smem once at the end.
// ---------------------------------------------------------------------------
#define QT 128
#define KT 64
#define PADB 144                 // 72 bf16 per row
#define SM_STG  36864
#define STG_SZ  36864            // Kh,Kl,Vh,Vl : 9216 each
#define SM_RED  36864            // overlaid on stage0 (used only after loop)
#define SM_DEN  110592
#define ATTN_SMEM (110592 + 512)

__global__ __launch_bounds__(256) void attn_mma(
    const uint4* __restrict__ Qh, const uint4* __restrict__ Ql,
    const uint4* __restrict__ Kh, const uint4* __restrict__ Kl,
    const uint4* __restrict__ Vh, const uint4* __restrict__ Vl,
    const int* __restrict__ kcnt,
    __nv_bfloat16* __restrict__ ahi, __nv_bfloat16* __restrict__ alo)
{
    extern __shared__ char sm[];
    const uint32_t sb = smem_u32(sm);
    const int b = blockIdx.z, h = blockIdx.y, q0 = blockIdx.x * QT;
    const int tid = threadIdx.x, wid = tid >> 5, lane = tid & 31;
    const int wm = wid >> 1, wn = wid & 1;
    const int mb = wm * 32, nb = wn * 32;
    const int cnt = kcnt[b];
    const int ntiles = (cnt + KT - 1) / KT;
    const size_t bh = (size_t)b * HH + h;

    float* denom_s = (float*)(sm + SM_DEN);
    if (tid < 128) denom_s[tid] = 0.0f;

    // resident Q tile (hi at 0, lo at 18432)
    #pragma unroll
    for (int it = 0; it < 4; it++) {
        int idx = it * 256 + tid;
        int r = idx >> 3, c = idx & 7;
        size_t gi = (bh * NN + q0 + r) * 8 + c;
        *(uint4*)(sm + r * PADB + c * 16) = Qh[gi];
        *(uint4*)(sm + 18432 + r * PADB + c * 16) = Ql[gi];
    }

    auto prefetch = [&](int t, int s) {
        const uint32_t stg = sb + SM_STG + s * STG_SZ;
        const int k0 = t * KT;
        #pragma unroll
        for (int it = 0; it < 8; it++) {
            int idx = it * 256 + tid;
            int mat = idx >> 9;                // 0 Kh,1 Kl,2 Vh,3 Vl
            int r = (idx >> 3) & 63, c = idx & 7;
            uint32_t dst = stg + mat * 9216 + (uint32_t)(r * PADB + c * 16);
            const uint4* g = (mat == 0) ? Kh : (mat == 1) ? Kl
                           : (mat == 2) ? Vh : Vl;
            size_t gi = (bh * NN + k0 + r) * 8 + c;
            CP_ASYNC16(dst, g + gi);
        }
    };

    float accO[2][8][4] = {};
    float denA[2][2] = {};

    const int a_r = lane & 15, a_c = (lane >> 4) * 8;
    const int b_r = lane & 7,  b_c = ((lane >> 3) & 1) * 8;
    const int t_r = lane & 15;

    prefetch(0, 0);
    CP_COMMIT();

    for (int t = 0; t < ntiles; t++) {
        const int s = t & 1;
        const int k0 = t * KT;
        CP_WAIT(0);
        __syncthreads();              // stage s ready; all warps past stage 1-s
        if (t + 1 < ntiles) { prefetch(t + 1, 1 - s); CP_COMMIT(); }

        const uint32_t Ksh = sb + SM_STG + s * STG_SZ;
        const uint32_t Ksl = Ksh + 9216;
        const uint32_t Vsh = Ksh + 18432;
        const uint32_t Vsl = Ksh + 27648;

        // S = Q K^T over this warp's 32q x 32k (split bf16, 3 products)
        float accS[2][4][4] = {};
        #pragma unroll
        for (int ks = 0; ks < 4; ks++) {
            uint32_t ah[2][4], al[2][4];
            #pragma unroll
            for (int mt = 0; mt < 2; mt++) {
                uint32_t ao = sb + (uint32_t)((mb + mt * 16 + a_r) * PADB +
                                              (ks * 16 + a_c) * 2);
                LDSM_X4(ah[mt][0], ah[mt][1], ah[mt][2], ah[mt][3], ao);
                LDSM_X4(al[mt][0], al[mt][1], al[mt][2], al[mt][3], ao + 18432);
            }
            #pragma unroll
            for (int nt = 0; nt < 4; nt++) {
                uint32_t bo = (uint32_t)((nb + nt * 8 + b_r) * PADB +
                                         (ks * 16 + b_c) * 2);
                uint32_t bhv[2], blv[2];
                LDSM_X2(bhv[0], bhv[1], Ksh + bo);
                LDSM_X2(blv[0], blv[1], Ksl + bo);
                #pragma unroll
                for (int mt = 0; mt < 2; mt++) {
                    MMA16816(accS[mt][nt], ah[mt], bhv);
                    MMA16816(accS[mt][nt], ah[mt], blv);
                    MMA16816(accS[mt][nt], al[mt], bhv);
                }
            }
        }

        // exp + mask; pack Ph/Pl straight into A fragments (C->A identity)
        uint32_t aPh[2][2][4], aPl[2][2][4];
        #pragma unroll
        for (int mt = 0; mt < 2; mt++) {
            #pragma unroll
            for (int nt = 0; nt < 4; nt++) {
                int c0i = nb + nt * 8 + (lane & 3) * 2;
                float m0v = (k0 + c0i     < cnt) ? 1.f : 0.f;
                float m1v = (k0 + c0i + 1 < cnt) ? 1.f : 0.f;
                #pragma unroll
                for (int h2 = 0; h2 < 2; h2++) {
                    float p0 = __expf(accS[mt][nt][h2 * 2 + 0]) * m0v;
                    float p1 = __expf(accS[mt][nt][h2 * 2 + 1]) * m1v;
                    denA[mt][h2] += p0 + p1;
                    uint32_t lo;
                    uint32_t hi = pack_split(p0, p1, lo);
                    aPh[mt][nt >> 1][(nt & 1) * 2 + h2] = hi;
                    aPl[mt][nt >> 1][(nt & 1) * 2 + h2] = lo;
                }
            }
        }

        // O += Ph·Vh + Pl·Vh + Ph·Vl over this warp's 32 keys, full d=64
        #pragma unroll
        for (int kt = 0; kt < 2; kt++) {
            #pragma unroll
            for (int dt = 0; dt < 8; dt++) {
                uint32_t bo = (uint32_t)((nb + kt * 16 + t_r) * PADB + dt * 16);
                uint32_t bvh[2], bvl[2];
                LDSM_X2_T(bvh[0], bvh[1], Vsh + bo);
                LDSM_X2_T(bvl[0], bvl[1], Vsl + bo);
                #pragma unroll
                for (int mt = 0; mt < 2; mt++) {
                    MMA16816(accO[mt][dt], aPh[mt][kt], bvh);
                    MMA16816(accO[mt][dt], aPl[mt][kt], bvh);
                    MMA16816(accO[mt][dt], aPh[mt][kt], bvl);
                }
            }
        }
    }

    // denom: quad-reduce then smem atomics
    #pragma unroll
    for (int mt = 0; mt < 2; mt++)
        #pragma unroll
        for (int h2 = 0; h2 < 2; h2++) {
            float v = denA[mt][h2];
            v += __shfl_xor_sync(0xffffffffu, v, 1);
            v += __shfl_xor_sync(0xffffffffu, v, 2);
            if ((lane & 3) == 0)
                atomicAdd(&denom_s[mb + mt * 16 + h2 * 8 + (lane >> 2)], v);
        }
    __syncthreads();   // denoms final; all warps done reading stage smem

    // cross-pair O reduction: wn=1 stores to REDBUF (overlaid on stage0)
    float* red = (float*)(sm + SM_RED);
    if (wn == 1) {
        #pragma unroll
        for (int mt = 0; mt < 2; mt++) {
            const int r = mb + mt * 16 + (lane >> 2);
            #pragma unroll
            for (int dt = 0; dt < 8; dt++) {
                const int cc = dt * 8 + (lane & 3) * 2;
                *(float2*)&red[(size_t)r * 64 + cc] =
                    make_float2(accO[mt][dt][0], accO[mt][dt][1]);
                *(float2*)&red[(size_t)(r + 8) * 64 + cc] =
                    make_float2(accO[mt][dt][2], accO[mt][dt][3]);
            }
        }
    }
    __syncthreads();

    // wn=0 finalizes: add pair partial, divide, split-bf16 store
    if (wn == 0) {
        #pragma unroll
        for (int mt = 0; mt < 2; mt++) {
            const int r = mb + mt * 16 + (lane >> 2);
            const float inv0 = 1.0f / denom_s[r];
            const float inv1 = 1.0f / denom_s[r + 8];
            const size_t row0 = (size_t)(b * NN + q0 + r) * CC + h * HD;
            const size_t row1 = (size_t)(b * NN + q0 + r + 8) * CC + h * HD;
            #pragma unroll
            for (int dt = 0; dt < 8; dt++) {
                const int cc = dt * 8 + (lane & 3) * 2;
                float2 pr0 = *(float2*)&red[(size_t)r * 64 + cc];
                float2 pr1 = *(float2*)&red[(size_t)(r + 8) * 64 + cc];
                float v0 = (accO[mt][dt][0] + pr0.x) * inv0;
                float v1 = (accO[mt][dt][1] + pr0.y) * inv0;
                float v2 = (accO[mt][dt][2] + pr1.x) * inv1;
                float v3 = (accO[mt][dt][3] + pr1.y) * inv1;
                uint32_t lo0, lo1;
                uint32_t hi0 = pack_split(v0, v1, lo0);
                uint32_t hi1 = pack_split(v2, v3, lo1);
                *(uint32_t*)((char*)ahi + (row0 + cc) * 2) = hi0;
                *(uint32_t*)((char*)alo + (row0 + cc) * 2) = lo0;
                *(uint32_t*)((char*)ahi + (row1 + cc) * 2) = hi1;
                *(uint32_t*)((char*)alo + (row1 + cc) * 2) = lo1;
            }
        }
    }
}

// ---------------------------------------------------------------------------
// pre-pass splits
// ---------------------------------------------------------------------------
__global__ void split_fp32(const float* __restrict__ in,
                           __nv_bfloat16* __restrict__ hi,
                           __nv_bfloat16* __restrict__ lo, int n)
{
    int i = blockIdx.x * blockDim.x + threadIdx.x;
    if (i < n) {
        float v = in[i];
        __nv_bfloat16 h = __float2bfloat16(v);
        hi[i] = h;
        lo[i] = __float2bfloat16(v - __bfloat162float(h));
    }
}

__global__ void transpose_split(const float* __restrict__ W,
                                __nv_bfloat16* __restrict__ hi,
                                __nv_bfloat16* __restrict__ lo, int K, int N)
{
    __shared__ float t[32][33];
    const int n0 = blockIdx.x * 32, k0 = blockIdx.y * 32;
    const int tx = threadIdx.x, ty = threadIdx.y;
    #pragma unroll
    for (int j = 0; j < 4; j++)
        t[ty + 8 * j][tx] = W[(size_t)(k0 + ty + 8 * j) * N + n0 + tx];
    __syncthreads();
    #pragma unroll
    for (int j = 0; j < 4; j++) {
        int nl = ty + 8 * j;
        float v = t[tx][nl];
        __nv_bfloat16 h = __float2bfloat16(v);
        size_t o = (size_t)(n0 + nl) * K + k0 + tx;
        hi[o] = h;
        lo[o] = __float2bfloat16(v - __bfloat162float(h));
    }
}

// ---------------------------------------------------------------------------
extern "C" void kernel_launch(void* const* d_in, const int* in_sizes, int n_in,
                              void* d_out, int out_size)
{
    const float* x      = (const float*)d_in[0];
    const int*   mask   = (const int*)  d_in[1];
    const float* w_qkv  = (const float*)d_in[2];
    const float* w_proj = (const float*)d_in[3];
    const float* b_proj = (const float*)d_in[4];
    float* out = (float*)d_out;

    __nv_bfloat16 *xhi, *xlo, *wqhi, *wqlo, *wphi, *wplo, *ahi, *alo;
    __nv_bfloat16 *qhi, *qlo, *khi, *klo, *vhi, *vlo;
    int *kidx, *kcnt;
    cudaGetSymbolAddress((void**)&xhi, g_xhi);
    cudaGetSymbolAddress((void**)&xlo, g_xlo);
    cudaGetSymbolAddress((void**)&wqhi, g_wqhi);
    cudaGetSymbolAddress((void**)&wqlo, g_wqlo);
    cudaGetSymbolAddress((void**)&wphi, g_wphi);
    cudaGetSymbolAddress((void**)&wplo, g_wplo);
    cudaGetSymbolAddress((void**)&ahi, g_ahi);
    cudaGetSymbolAddress((void**)&alo, g_alo);
    cudaGetSymbolAddress((void**)&qhi, g_qhi);
    cudaGetSymbolAddress((void**)&qlo, g_qlo);
    cudaGetSymbolAddress((void**)&khi, g_khi);
    cudaGetSymbolAddress((void**)&klo, g_klo);
    cudaGetSymbolAddress((void**)&vhi, g_vhi);
    cudaGetSymbolAddress((void**)&vlo, g_vlo);
    cudaGetSymbolAddress((void**)&kidx, g_kidx);
    cudaGetSymbolAddress((void**)&kcnt, g_kcnt);

    cudaFuncSetAttribute(gemm_mma, cudaFuncAttributeMaxDynamicSharedMemorySize, GEMM_SMEM);
    cudaFuncSetAttribute(qgemm, cudaFuncAttributeMaxDynamicSharedMemorySize, GEMM_SMEM);
    cudaFuncSetAttribute(kvgemm, cudaFuncAttributeMaxDynamicSharedMemorySize, GEMM_SMEM);
    cudaFuncSetAttribute(attn_mma, cudaFuncAttributeMaxDynamicSharedMemorySize, ATTN_SMEM);

    // 0) pre-pass splits / transposes / mask scan
    split_fp32<<<(BN * CC + 255) / 256, 256>>>(x, xhi, xlo, BN * CC);
    transpose_split<<<dim3(QKVC / 32, CC / 32), dim3(32, 8)>>>(w_qkv, wqhi, wqlo, CC, QKVC);
    transpose_split<<<dim3(CC / 32, CC / 32), dim3(32, 8)>>>(w_proj, wphi, wplo, CC, CC);
    scan_mask<<<BB, 256>>>(mask, kidx, kcnt);

    // 1) Q GEMM (fused scale+split epilogue)
    qgemm<<<dim3(CC / 128, BN / 128), 256, GEMM_SMEM>>>(
        (const uint4*)xhi, (const uint4*)xlo, (const uint4*)wqhi, (const uint4*)wqlo,
        qhi, qlo);

    // 2) KV GEMM over packed tokens (gathered input, split epilogue)
    kvgemm<<<dim3(2 * CC / 128, NN / 128, BB), 256, GEMM_SMEM>>>(
        (const uint4*)xhi, (const uint4*)xlo,
        (const uint4*)(wqhi + (size_t)CC * CC), (const uint4*)(wqlo + (size_t)CC * CC),
        kidx, kcnt, khi, klo, vhi, vlo);

    // 3) tensor-core attention over packed keys (P-in-registers)
    attn_mma<<<dim3(NN / QT, HH, BB), 256, ATTN_SMEM>>>(
        (const uint4*)qhi, (const uint4*)qlo, (const uint4*)khi, (const uint4*)klo,
        (const uint4*)vhi, (const uint4*)vlo, kcnt, ahi, alo);

    // 4) projection GEMM + bias
    gemm_mma<<<dim3(CC / 128, BN / 128), 256, GEMM_SMEM>>>(
        (const uint4*)ahi, (const uint4*)alo, (const uint4*)wphi, (const uint4*)wplo,
        out, BN, CC, CC, b_proj);
}

// round 9
// speedup vs baseline: 4.9993x; 1.1815x over previous
#include <cuda_runtime.h>
#include <cuda_bf16.h>
#include <cuda_fp16.h>
#include <cstdint>
#include <cstddef>

#define BB 2
#define NN 2048
#define CC 768
#define HH 12
#define HD 64
#define BN (BB * NN)          // 4096
#define QKVC (3 * CC)         // 2304

// ---------------------------------------------------------------------------
// Scratch (device globals — no allocation allowed anywhere)
// ---------------------------------------------------------------------------
__device__ __align__(16) __nv_bfloat16 g_xhi[(size_t)BN * CC];
__device__ __align__(16) __nv_bfloat16 g_xlo[(size_t)BN * CC];
__device__ __align__(16) __nv_bfloat16 g_wqhi[(size_t)QKVC * CC]; // Wqkv^T [2304,768]
__device__ __align__(16) __nv_bfloat16 g_wqlo[(size_t)QKVC * CC];
__device__ __align__(16) __nv_bfloat16 g_wphi[(size_t)CC * CC];   // Wproj^T [768,768]
__device__ __align__(16) __nv_bfloat16 g_wplo[(size_t)CC * CC];
__device__ __align__(16) __nv_bfloat16 g_ahi[(size_t)BN * CC];    // attention out hi
__device__ __align__(16) __nv_bfloat16 g_alo[(size_t)BN * CC];    // attention out lo
// attention operands: [b][h][token][64] row-major
__device__ __align__(16) __nv_bfloat16 g_qhi[(size_t)BB * HH * NN * HD];
__device__ __align__(16) __nv_bfloat16 g_qlo[(size_t)BB * HH * NN * HD];
__device__ __align__(16) __nv_bfloat16 g_khi[(size_t)BB * HH * NN * HD];
__device__ __align__(16) __nv_bfloat16 g_klo[(size_t)BB * HH * NN * HD];
__device__ __align__(16) __half        g_vhi[(size_t)BB * HH * NN * HD];  // fp16 split
__device__ __align__(16) __half        g_vlo[(size_t)BB * HH * NN * HD];
__device__ int g_kidx[BB * NN];
__device__ int g_kcnt[BB];

// ---------------------------------------------------------------------------
// Family-common PTX helpers (ptxas target is sm_103 w/o 'a' — no tcgen05)
// ---------------------------------------------------------------------------
__device__ __forceinline__ uint32_t smem_u32(const void* p) {
    uint32_t a;
    asm("{ .reg .u64 t; cvta.to.shared.u64 t, %1; cvt.u32.u64 %0, t; }"
        : "=r"(a) : "l"(p));
    return a;
}
#define CP_ASYNC16(dst, src) \
    asm volatile("cp.async.cg.shared.global [%0], [%1], 16;" :: "r"(dst), "l"(src))
#define CP_COMMIT() asm volatile("cp.async.commit_group;" ::: "memory")
#define CP_WAIT(n)  asm volatile("cp.async.wait_group %0;" :: "n"(n) : "memory")

#define LDSM_X4(r0, r1, r2, r3, addr)                                          \
    asm volatile("ldmatrix.sync.aligned.m8n8.x4.shared.b16 {%0,%1,%2,%3}, [%4];" \
                 : "=r"(r0), "=r"(r1), "=r"(r2), "=r"(r3) : "r"(addr))
#define LDSM_X2(r0, r1, addr)                                                  \
    asm volatile("ldmatrix.sync.aligned.m8n8.x2.shared.b16 {%0,%1}, [%2];"     \
                 : "=r"(r0), "=r"(r1) : "r"(addr))
#define LDSM_X2_T(r0, r1, addr)                                                \
    asm volatile("ldmatrix.sync.aligned.m8n8.x2.trans.shared.b16 {%0,%1}, [%2];" \
                 : "=r"(r0), "=r"(r1) : "r"(addr))

#define MMA16816(d, a, b)                                                      \
    asm volatile("mma.sync.aligned.m16n8k16.row.col.f32.bf16.bf16.f32 "        \
                 "{%0,%1,%2,%3}, {%4,%5,%6,%7}, {%8,%9}, {%0,%1,%2,%3};"       \
                 : "+f"((d)[0]), "+f"((d)[1]), "+f"((d)[2]), "+f"((d)[3])      \
                 : "r"((a)[0]), "r"((a)[1]), "r"((a)[2]), "r"((a)[3]),         \
                   "r"((b)[0]), "r"((b)[1]))
#define MMA16816H(d, a, b)                                                     \
    asm volatile("mma.sync.aligned.m16n8k16.row.col.f32.f16.f16.f32 "          \
                 "{%0,%1,%2,%3}, {%4,%5,%6,%7}, {%8,%9}, {%0,%1,%2,%3};"       \
                 : "+f"((d)[0]), "+f"((d)[1]), "+f"((d)[2]), "+f"((d)[3])      \
                 : "r"((a)[0]), "r"((a)[1]), "r"((a)[2]), "r"((a)[3]),         \
                   "r"((b)[0]), "r"((b)[1]))

__device__ __forceinline__ uint32_t pack_split(float v0, float v1,
                                               uint32_t& lopk) {
    __nv_bfloat16 h0 = __float2bfloat16(v0);
    __nv_bfloat16 h1 = __float2bfloat16(v1);
    __nv_bfloat16 l0 = __float2bfloat16(v0 - __bfloat162float(h0));
    __nv_bfloat16 l1 = __float2bfloat16(v1 - __bfloat162float(h1));
    lopk = ((uint32_t)__bfloat16_as_ushort(l1) << 16) |
           (uint32_t)__bfloat16_as_ushort(l0);
    return ((uint32_t)__bfloat16_as_ushort(h1) << 16) |
           (uint32_t)__bfloat16_as_ushort(h0);
}
__device__ __forceinline__ uint32_t pack_split_h(float v0, float v1,
                                                 uint32_t& lopk) {
    __half h0 = __float2half_rn(v0), h1 = __float2half_rn(v1);
    __half l0 = __float2half_rn(v0 - __half2float(h0));
    __half l1 = __float2half_rn(v1 - __half2float(h1));
    lopk = ((uint32_t)__half_as_ushort(l1) << 16) |
           (uint32_t)__half_as_ushort(l0);
    return ((uint32_t)__half_as_ushort(h1) << 16) |
           (uint32_t)__half_as_ushort(h0);
}
__device__ __forceinline__ uint32_t pack_h2(float v0, float v1) {
    __half2 h = __floats2half2_rn(v0, v1);
    return *(uint32_t*)&h;
}

// ---------------------------------------------------------------------------
// Shared GEMM mainloop pieces (128x128 tile, 8 warps, K-chunk 32, 2 stages)
// ---------------------------------------------------------------------------
#define RS 40
#define MAT_BYTES (128 * RS * 2)
#define STAGE_BYTES (4 * MAT_BYTES)
#define GEMM_SMEM (2 * STAGE_BYTES)

#define GEMM_MAINLOOP(NCH)                                                     \
    for (int c = 0; c < (NCH); c++) {                                          \
        const int s = c & 1;                                                   \
        if (c + 1 < (NCH)) { prefetch(c + 1, 1 - s); CP_COMMIT(); CP_WAIT(1); }\
        else { CP_WAIT(0); }                                                   \
        __syncthreads();                                                       \
        const uint32_t As_h = sb + s * STAGE_BYTES;                            \
        const uint32_t As_l = As_h + MAT_BYTES;                                \
        const uint32_t Bs_h = As_h + 2 * MAT_BYTES;                            \
        const uint32_t Bs_l = As_h + 3 * MAT_BYTES;                            \
        _Pragma("unroll")                                                      \
        for (int kk = 0; kk < 2; kk++) {                                       \
            uint32_t ah[2][4], al[2][4];                                       \
            _Pragma("unroll")                                                  \
            for (int mt = 0; mt < 2; mt++) {                                   \
                const uint32_t ao =                                            \
                    (uint32_t)((m_base + mt * 16 + a_r) * (RS * 2) +           \
                               (kk * 16 + a_c) * 2);                           \
                LDSM_X4(ah[mt][0], ah[mt][1], ah[mt][2], ah[mt][3], As_h + ao);\
                LDSM_X4(al[mt][0], al[mt][1], al[mt][2], al[mt][3], As_l + ao);\
            }                                                                  \
            _Pragma("unroll")                                                  \
            for (int nt = 0; nt < 8; nt++) {                                   \
                const uint32_t bo =                                            \
                    (uint32_t)((n_base + nt * 8 + b_r) * (RS * 2) +            \
                               (kk * 16 + b_c) * 2);                           \
                uint32_t bh[2], bl[2];                                         \
                LDSM_X2(bh[0], bh[1], Bs_h + bo);                              \
                LDSM_X2(bl[0], bl[1], Bs_l + bo);                              \
                _Pragma("unroll")                                              \
                for (int mt = 0; mt < 2; mt++) {                               \
                    MMA16816(acc[mt][nt], ah[mt], bh);                         \
                    MMA16816(acc[mt][nt], ah[mt], bl);                         \
                    MMA16816(acc[mt][nt], al[mt], bh);                         \
                }                                                              \
            }                                                                  \
        }                                                                      \
        __syncthreads();                                                       \
    }

#define GEMM_COMMON_DECLS                                                      \
    extern __shared__ char smem[];                                             \
    const uint32_t sb = smem_u32(smem);                                        \
    const int tid = threadIdx.x, wid = tid >> 5, lane = tid & 31;              \
    const int wm = wid >> 1, wn = wid & 1;                                     \
    const int m_base = wm * 32, n_base = wn * 64;                              \
    const int a_r = (lane & 15);                                               \
    const int a_c = (lane >> 4) * 8;                                           \
    const int b_r = (lane & 7);                                                \
    const int b_c = ((lane >> 3) & 1) * 8;

// ---------------------------------------------------------------------------
// Proj GEMM: C[M,Nn] = A[M,K]·B[Nn,K]^T + bias (fp32 out)
// ---------------------------------------------------------------------------
__global__ __launch_bounds__(256) void gemm_mma(
    const uint4* __restrict__ Ah, const uint4* __restrict__ Al,
    const uint4* __restrict__ Bh, const uint4* __restrict__ Bl,
    float* __restrict__ C, int M, int Nn, int K,
    const float* __restrict__ bias)
{
    GEMM_COMMON_DECLS
    const int m0 = blockIdx.y * 128, n0 = blockIdx.x * 128;
    const int Krow = K >> 3;
    const int nch = K >> 5;

    auto prefetch = [&](int c, int s) {
        const uint32_t stage = sb + s * STAGE_BYTES;
        const int r = tid >> 2, q = tid & 3;
        const uint32_t doff = (uint32_t)(r * (RS * 2) + q * 16);
        #pragma unroll
        for (int half = 0; half < 2; half++) {
            const int rr = r + half * 64;
            const uint32_t d2 = doff + (uint32_t)(half * 64 * RS * 2);
            const size_t ga = (size_t)(m0 + rr) * Krow + c * 4 + q;
            const size_t gb = (size_t)(n0 + rr) * Krow + c * 4 + q;
            CP_ASYNC16(stage +                 d2, Ah + ga);
            CP_ASYNC16(stage + MAT_BYTES +     d2, Al + ga);
            CP_ASYNC16(stage + 2 * MAT_BYTES + d2, Bh + gb);
            CP_ASYNC16(stage + 3 * MAT_BYTES + d2, Bl + gb);
        }
    };

    float acc[2][8][4] = {};
    prefetch(0, 0);
    CP_COMMIT();
    GEMM_MAINLOOP(nch)

    #pragma unroll
    for (int mt = 0; mt < 2; mt++) {
        const int row0 = m0 + m_base + mt * 16 + (lane >> 2);
        #pragma unroll
        for (int nt = 0; nt < 8; nt++) {
            const int col = n0 + n_base + nt * 8 + (lane & 3) * 2;
            float b0 = bias[col], b1 = bias[col + 1];
            float2 v0 = { acc[mt][nt][0] + b0, acc[mt][nt][1] + b1 };
            float2 v1 = { acc[mt][nt][2] + b0, acc[mt][nt][3] + b1 };
            *(float2*)(C + (size_t)row0 * Nn + col) = v0;
            *(float2*)(C + (size_t)(row0 + 8) * Nn + col) = v1;
        }
    }
}

// ---------------------------------------------------------------------------
// Fused QKV GEMM: blocks [0,192) compute Q (scaled, bf16 split, attn layout);
// blocks [192,576) compute K/V over mask-packed tokens (K bf16, V fp16 split).
// ---------------------------------------------------------------------------
__global__ __launch_bounds__(256) void qkv_fused(
    const uint4* __restrict__ Xh, const uint4* __restrict__ Xl,
    const uint4* __restrict__ Wh, const uint4* __restrict__ Wl,
    const int* __restrict__ kidx, const int* __restrict__ kcnt,
    __nv_bfloat16* __restrict__ qhi, __nv_bfloat16* __restrict__ qlo,
    __nv_bfloat16* __restrict__ khi, __nv_bfloat16* __restrict__ klo,
    __half* __restrict__ vhi, __half* __restrict__ vlo)
{
    GEMM_COMMON_DECLS
    const int bid = blockIdx.x;
    const int Krow = CC >> 3;            // 96
    const int nch = CC >> 5;             // 24

    if (bid < 192) {
        // ------------------- Q role -------------------
        const int m0 = (bid / 6) * 128, n0 = (bid % 6) * 128;
        auto prefetch = [&](int c, int s) {
            const uint32_t stage = sb + s * STAGE_BYTES;
            const int r = tid >> 2, q = tid & 3;
            const uint32_t doff = (uint32_t)(r * (RS * 2) + q * 16);
            #pragma unroll
            for (int half = 0; half < 2; half++) {
                const int rr = r + half * 64;
                const uint32_t d2 = doff + (uint32_t)(half * 64 * RS * 2);
                const size_t ga = (size_t)(m0 + rr) * Krow + c * 4 + q;
                const size_t gb = (size_t)(n0 + rr) * Krow + c * 4 + q;
                CP_ASYNC16(stage +                 d2, Xh + ga);
                CP_ASYNC16(stage + MAT_BYTES +     d2, Xl + ga);
                CP_ASYNC16(stage + 2 * MAT_BYTES + d2, Wh + gb);
                CP_ASYNC16(stage + 3 * MAT_BYTES + d2, Wl + gb);
            }
        };
        float acc[2][8][4] = {};
        prefetch(0, 0);
        CP_COMMIT();
        GEMM_MAINLOOP(nch)

        #pragma unroll
        for (int mt = 0; mt < 2; mt++) {
            #pragma unroll
            for (int h2 = 0; h2 < 2; h2++) {
                const int r = m0 + m_base + mt * 16 + h2 * 8 + (lane >> 2);
                const int b = r >> 11, n = r & (NN - 1);
                #pragma unroll
                for (int nt = 0; nt < 8; nt++) {
                    const int c = n0 + n_base + nt * 8 + (lane & 3) * 2;
                    const int h = c >> 6, d = c & 63;
                    const size_t o = (((size_t)b * HH + h) * NN + n) * HD + d;
                    uint32_t lopk;
                    uint32_t hipk = pack_split(acc[mt][nt][h2 * 2] * 0.125f,
                                               acc[mt][nt][h2 * 2 + 1] * 0.125f,
                                               lopk);
                    *(uint32_t*)((char*)qhi + o * 2) = hipk;
                    *(uint32_t*)((char*)qlo + o * 2) = lopk;
                }
            }
        }
    } else {
        // ------------------- KV role (packed tokens) -------------------
        const int idx = bid - 192;
        const int bz = idx / 192;
        const int rr2 = idx % 192;
        const int n0 = (rr2 % 12) * 128;      // within [0, 1536)
        const int m0 = (rr2 / 12) * 128;
        const int cnt = kcnt[bz];
        const int pad = (cnt + 63) & ~63;
        if (m0 >= pad) return;

        const uint4* Bh = Wh + (size_t)CC * CC / 8;  // wq rows [768,2304)
        const uint4* Bl = Wl + (size_t)CC * CC / 8;

        const int pr = tid >> 2, pq = tid & 3;
        const int j1 = m0 + pr, j2 = j1 + 64;
        const int s1 = (j1 < cnt) ? kidx[bz * NN + j1] : 0;
        const int s2 = (j2 < cnt) ? kidx[bz * NN + j2] : 0;

        auto prefetch = [&](int c, int s) {
            const uint32_t stage = sb + s * STAGE_BYTES;
            const uint32_t doff = (uint32_t)(pr * (RS * 2) + pq * 16);
            #pragma unroll
            for (int half = 0; half < 2; half++) {
                const int srow = half ? s2 : s1;
                const uint32_t d2 = doff + (uint32_t)(half * 64 * RS * 2);
                const size_t ga = (size_t)(bz * NN + srow) * Krow + c * 4 + pq;
                const size_t gb = (size_t)(n0 + pr + half * 64) * Krow + c * 4 + pq;
                CP_ASYNC16(stage +                 d2, Xh + ga);
                CP_ASYNC16(stage + MAT_BYTES +     d2, Xl + ga);
                CP_ASYNC16(stage + 2 * MAT_BYTES + d2, Bh + gb);
                CP_ASYNC16(stage + 3 * MAT_BYTES + d2, Bl + gb);
            }
        };
        float acc[2][8][4] = {};
        prefetch(0, 0);
        CP_COMMIT();
        GEMM_MAINLOOP(nch)

        #pragma unroll
        for (int mt = 0; mt < 2; mt++) {
            #pragma unroll
            for (int h2 = 0; h2 < 2; h2++) {
                const int j = m0 + m_base + mt * 16 + h2 * 8 + (lane >> 2);
                #pragma unroll
                for (int nt = 0; nt < 8; nt++) {
                    const int c = n0 + n_base + nt * 8 + (lane & 3) * 2;
                    const int isV = c >= CC;
                    const int cc = isV ? c - CC : c;
                    const int h = cc >> 6, d = cc & 63;
                    const size_t o = (((size_t)bz * HH + h) * NN + j) * HD + d;
                    uint32_t lopk, hipk;
                    if (isV) {
                        hipk = pack_split_h(acc[mt][nt][h2 * 2],
                                            acc[mt][nt][h2 * 2 + 1], lopk);
                        *(uint32_t*)((char*)vhi + o * 2) = hipk;
                        *(uint32_t*)((char*)vlo + o * 2) = lopk;
                    } else {
                        hipk = pack_split(acc[mt][nt][h2 * 2],
                                          acc[mt][nt][h2 * 2 + 1], lopk);
                        *(uint32_t*)((char*)khi + o * 2) = hipk;
                        *(uint32_t*)((char*)klo + o * 2) = lopk;
                    }
                }
            }
        }
    }
}

// ---------------------------------------------------------------------------
// Fused pre-pass: block ranges -> [split x][transpose wqkv][transpose wproj][scan]
// ---------------------------------------------------------------------------
#define PREP_SPLIT (BN * CC / 256)          // 12288
#define PREP_TQ (72 * 24)                   // 1728
#define PREP_TP (24 * 24)                   // 576
#define PREP_TOTAL (PREP_SPLIT + PREP_TQ + PREP_TP + BB)

__global__ __launch_bounds__(256) void prep_all(
    const float* __restrict__ x, const int* __restrict__ mask,
    const float* __restrict__ w_qkv, const float* __restrict__ w_proj,
    __nv_bfloat16* __restrict__ xhi, __nv_bfloat16* __restrict__ xlo,
    __nv_bfloat16* __restrict__ wqhi, __nv_bfloat16* __restrict__ wqlo,
    __nv_bfloat16* __restrict__ wphi, __nv_bfloat16* __restrict__ wplo,
    int* __restrict__ kidx, int* __restrict__ kcnt)
{
    __shared__ float tbuf[32][33];
    __shared__ int part[256];
    const int bid = blockIdx.x, tid = threadIdx.x;

    if (bid < PREP_SPLIT) {
        const int i = bid * 256 + tid;
        float v = x[i];
        __nv_bfloat16 h = __float2bfloat16(v);
        xhi[i] = h;
        xlo[i] = __float2bfloat16(v - __bfloat162float(h));
    } else if (bid < PREP_SPLIT + PREP_TQ + PREP_TP) {
        const bool isQ = bid < PREP_SPLIT + PREP_TQ;
        const int t = isQ ? bid - PREP_SPLIT : bid - (PREP_SPLIT + PREP_TQ);
        const float* W = isQ ? w_qkv : w_proj;
        __nv_bfloat16* hi = isQ ? wqhi : wphi;
        __nv_bfloat16* lo = isQ ? wqlo : wplo;
        const int N = isQ ? QKVC : CC;
        const int nblk = N / 32;
        const int n0 = (t % nblk) * 32, k0 = (t / nblk) * 32;
        const int tx = tid & 31, ty = tid >> 5;
        #pragma unroll
        for (int j = 0; j < 4; j++)
            tbuf[ty + 8 * j][tx] = W[(size_t)(k0 + ty + 8 * j) * N + n0 + tx];
        __syncthreads();
        #pragma unroll
        for (int j = 0; j < 4; j++) {
            const int nl = ty + 8 * j;
            float v = tbuf[tx][nl];
            __nv_bfloat16 h = __float2bfloat16(v);
            size_t o = (size_t)(n0 + nl) * CC + k0 + tx;
            hi[o] = h;
            lo[o] = __float2bfloat16(v - __bfloat162float(h));
        }
    } else {
        const int b = bid - (PREP_SPLIT + PREP_TQ + PREP_TP);
        const int* m = mask + b * NN;
        int loc[8], c = 0;
        #pragma unroll
        for (int i = 0; i < 8; i++) { loc[i] = c; c += m[tid * 8 + i]; }
        part[tid] = c;
        __syncthreads();
        for (int off = 1; off < 256; off <<= 1) {
            int v = (tid >= off) ? part[tid - off] : 0;
            __syncthreads();
            part[tid] += v;
            __syncthreads();
        }
        int excl = part[tid] - c;
        #pragma unroll
        for (int i = 0; i < 8; i++)
            if (m[tid * 8 + i]) kidx[b * NN + excl + loc[i]] = tid * 8 + i;
        if (tid == 255) kcnt[b] = part[255];
    }
}

// ---------------------------------------------------------------------------
// Tensor-core attention, P-in-registers; PV in fp16 (P single, V hi/lo).
// ---------------------------------------------------------------------------
#define QT 128
#define KT 64
#define PADB 144                 // 72 x 16-bit per row
#define SM_STG  36864
#define STG_SZ  36864            // Kh,Kl,Vh,Vl : 9216 each
#define SM_RED  36864            // overlaid on stage0 (used only after loop)
#define SM_DEN  110592
#define ATTN_SMEM (110592 + 512)

__global__ __launch_bounds__(256) void attn_mma(
    const uint4* __restrict__ Qh, const uint4* __restrict__ Ql,
    const uint4* __restrict__ Kh, const uint4* __restrict__ Kl,
    const uint4* __restrict__ Vh, const uint4* __restrict__ Vl,
    const int* __restrict__ kcnt,
    __nv_bfloat16* __restrict__ ahi, __nv_bfloat16* __restrict__ alo)
{
    extern __shared__ char sm[];
    const uint32_t sb = smem_u32(sm);
    const int b = blockIdx.z, h = blockIdx.y, q0 = blockIdx.x * QT;
    const int tid = threadIdx.x, wid = tid >> 5, lane = tid & 31;
    const int wm = wid >> 1, wn = wid & 1;
    const int mb = wm * 32, nb = wn * 32;
    const int cnt = kcnt[b];
    const int ntiles = (cnt + KT - 1) / KT;
    const size_t bh = (size_t)b * HH + h;

    float* denom_s = (float*)(sm + SM_DEN);
    if (tid < 128) denom_s[tid] = 0.0f;

    // resident Q tile (hi at 0, lo at 18432)
    #pragma unroll
    for (int it = 0; it < 4; it++) {
        int idx = it * 256 + tid;
        int r = idx >> 3, c = idx & 7;
        size_t gi = (bh * NN + q0 + r) * 8 + c;
        *(uint4*)(sm + r * PADB + c * 16) = Qh[gi];
        *(uint4*)(sm + 18432 + r * PADB + c * 16) = Ql[gi];
    }

    auto prefetch = [&](int t, int s) {
        const uint32_t stg = sb + SM_STG + s * STG_SZ;
        const int k0 = t * KT;
        #pragma unroll
        for (int it = 0; it < 8; it++) {
            int idx = it * 256 + tid;
            int mat = idx >> 9;                // 0 Kh,1 Kl,2 Vh,3 Vl
            int r = (idx >> 3) & 63, c = idx & 7;
            uint32_t dst = stg + mat * 9216 + (uint32_t)(r * PADB + c * 16);
            const uint4* g = (mat == 0) ? Kh : (mat == 1) ? Kl
                           : (mat == 2) ? Vh : Vl;
            size_t gi = (bh * NN + k0 + r) * 8 + c;
            CP_ASYNC16(dst, g + gi);
        }
    };

    float accO[2][8][4] = {};
    float denA[2][2] = {};

    const int a_r = lane & 15, a_c = (lane >> 4) * 8;
    const int b_r = lane & 7,  b_c = ((lane >> 3) & 1) * 8;
    const int t_r = lane & 15;

    prefetch(0, 0);
    CP_COMMIT();

    for (int t = 0; t < ntiles; t++) {
        const int s = t & 1;
        const int k0 = t * KT;
        CP_WAIT(0);
        __syncthreads();
        if (t + 1 < ntiles) { prefetch(t + 1, 1 - s); CP_COMMIT(); }

        const uint32_t Ksh = sb + SM_STG + s * STG_SZ;
        const uint32_t Ksl = Ksh + 9216;
        const uint32_t Vsh = Ksh + 18432;
        const uint32_t Vsl = Ksh + 27648;

        // S = Q K^T over this warp's 32q x 32k (split bf16, 3 products)
        float accS[2][4][4] = {};
        #pragma unroll
        for (int ks = 0; ks < 4; ks++) {
            uint32_t ah[2][4], al[2][4];
            #pragma unroll
            for (int mt = 0; mt < 2; mt++) {
                uint32_t ao = sb + (uint32_t)((mb + mt * 16 + a_r) * PADB +
                                              (ks * 16 + a_c) * 2);
                LDSM_X4(ah[mt][0], ah[mt][1], ah[mt][2], ah[mt][3], ao);
                LDSM_X4(al[mt][0], al[mt][1], al[mt][2], al[mt][3], ao + 18432);
            }
            #pragma unroll
            for (int nt = 0; nt < 4; nt++) {
                uint32_t bo = (uint32_t)((nb + nt * 8 + b_r) * PADB +
                                         (ks * 16 + b_c) * 2);
                uint32_t bhv[2], blv[2];
                LDSM_X2(bhv[0], bhv[1], Ksh + bo);
                LDSM_X2(blv[0], blv[1], Ksl + bo);
                #pragma unroll
                for (int mt = 0; mt < 2; mt++) {
                    MMA16816(accS[mt][nt], ah[mt], bhv);
                    MMA16816(accS[mt][nt], ah[mt], blv);
                    MMA16816(accS[mt][nt], al[mt], bhv);
                }
            }
        }

        // exp + mask; P packed to single fp16 A fragments
        uint32_t aP[2][2][4];
        #pragma unroll
        for (int mt = 0; mt < 2; mt++) {
            #pragma unroll
            for (int nt = 0; nt < 4; nt++) {
                int c0i = nb + nt * 8 + (lane & 3) * 2;
                float m0v = (k0 + c0i     < cnt) ? 1.f : 0.f;
                float m1v = (k0 + c0i + 1 < cnt) ? 1.f : 0.f;
                #pragma unroll
                for (int h2 = 0; h2 < 2; h2++) {
                    float p0 = __expf(accS[mt][nt][h2 * 2 + 0]) * m0v;
                    float p1 = __expf(accS[mt][nt][h2 * 2 + 1]) * m1v;
                    denA[mt][h2] += p0 + p1;
                    aP[mt][nt >> 1][(nt & 1) * 2 + h2] = pack_h2(p0, p1);
                }
            }
        }

        // O += P·Vh + P·Vl (fp16), this warp's 32 keys, full d=64
        #pragma unroll
        for (int kt = 0; kt < 2; kt++) {
            #pragma unroll
            for (int dt = 0; dt < 8; dt++) {
                uint32_t bo = (uint32_t)((nb + kt * 16 + t_r) * PADB + dt * 16);
                uint32_t bvh[2], bvl[2];
                LDSM_X2_T(bvh[0], bvh[1], Vsh + bo);
                LDSM_X2_T(bvl[0], bvl[1], Vsl + bo);
                #pragma unroll
                for (int mt = 0; mt < 2; mt++) {
                    MMA16816H(accO[mt][dt], aP[mt][kt], bvh);
                    MMA16816H(accO[mt][dt], aP[mt][kt], bvl);
                }
            }
        }
    }

    // denom: quad-reduce then smem atomics
    #pragma unroll
    for (int mt = 0; mt < 2; mt++)
        #pragma unroll
        for (int h2 = 0; h2 < 2; h2++) {
            float v = denA[mt][h2];
            v += __shfl_xor_sync(0xffffffffu, v, 1);
            v += __shfl_xor_sync(0xffffffffu, v, 2);
            if ((lane & 3) == 0)
                atomicAdd(&denom_s[mb + mt * 16 + h2 * 8 + (lane >> 2)], v);
        }
    __syncthreads();

    // cross-pair O reduction: wn=1 stores to REDBUF (overlaid on stage0)
    float* red = (float*)(sm + SM_RED);
    if (wn == 1) {
        #pragma unroll
        for (int mt = 0; mt < 2; mt++) {
            const int r = mb + mt * 16 + (lane >> 2);
            #pragma unroll
            for (int dt = 0; dt < 8; dt++) {
                const int cc = dt * 8 + (lane & 3) * 2;
                *(float2*)&red[(size_t)r * 64 + cc] =
                    make_float2(accO[mt][dt][0], accO[mt][dt][1]);
                *(float2*)&red[(size_t)(r + 8) * 64 + cc] =
                    make_float2(accO[mt][dt][2], accO[mt][dt][3]);
            }
        }
    }
    __syncthreads();

    // wn=0 finalizes: add pair partial, divide, split-bf16 store
    if (wn == 0) {
        #pragma unroll
        for (int mt = 0; mt < 2; mt++) {
            const int r = mb + mt * 16 + (lane >> 2);
            const float inv0 = 1.0f / denom_s[r];
            const float inv1 = 1.0f / denom_s[r + 8];
            const size_t row0 = (size_t)(b * NN + q0 + r) * CC + h * HD;
            const size_t row1 = (size_t)(b * NN + q0 + r + 8) * CC + h * HD;
            #pragma unroll
            for (int dt = 0; dt < 8; dt++) {
                const int cc = dt * 8 + (lane & 3) * 2;
                float2 pr0 = *(float2*)&red[(size_t)r * 64 + cc];
                float2 pr1 = *(float2*)&red[(size_t)(r + 8) * 64 + cc];
                float v0 = (accO[mt][dt][0] + pr0.x) * inv0;
                float v1 = (accO[mt][dt][1] + pr0.y) * inv0;
                float v2 = (accO[mt][dt][2] + pr1.x) * inv1;
                float v3 = (accO[mt][dt][3] + pr1.y) * inv1;
                uint32_t lo0, lo1;
                uint32_t hi0 = pack_split(v0, v1, lo0);
                uint32_t hi1 = pack_split(v2, v3, lo1);
                *(uint32_t*)((char*)ahi + (row0 + cc) * 2) = hi0;
                *(uint32_t*)((char*)alo + (row0 + cc) * 2) = lo0;
                *(uint32_t*)((char*)ahi + (row1 + cc) * 2) = hi1;
                *(uint32_t*)((char*)alo + (row1 + cc) * 2) = lo1;
            }
        }
    }
}

// ---------------------------------------------------------------------------
extern "C" void kernel_launch(void* const* d_in, const int* in_sizes, int n_in,
                              void* d_out, int out_size)
{
    const float* x      = (const float*)d_in[0];
    const int*   mask   = (const int*)  d_in[1];
    const float* w_qkv  = (const float*)d_in[2];
    const float* w_proj = (const float*)d_in[3];
    const float* b_proj = (const float*)d_in[4];
    float* out = (float*)d_out;

    __nv_bfloat16 *xhi, *xlo, *wqhi, *wqlo, *wphi, *wplo, *ahi, *alo;
    __nv_bfloat16 *qhi, *qlo, *khi, *klo;
    __half *vhi, *vlo;
    int *kidx, *kcnt;
    cudaGetSymbolAddress((void**)&xhi, g_xhi);
    cudaGetSymbolAddress((void**)&xlo, g_xlo);
    cudaGetSymbolAddress((void**)&wqhi, g_wqhi);
    cudaGetSymbolAddress((void**)&wqlo, g_wqlo);
    cudaGetSymbolAddress((void**)&wphi, g_wphi);
    cudaGetSymbolAddress((void**)&wplo, g_wplo);
    cudaGetSymbolAddress((void**)&ahi, g_ahi);
    cudaGetSymbolAddress((void**)&alo, g_alo);
    cudaGetSymbolAddress((void**)&qhi, g_qhi);
    cudaGetSymbolAddress((void**)&qlo, g_qlo);
    cudaGetSymbolAddress((void**)&khi, g_khi);
    cudaGetSymbolAddress((void**)&klo, g_klo);
    cudaGetSymbolAddress((void**)&vhi, g_vhi);
    cudaGetSymbolAddress((void**)&vlo, g_vlo);
    cudaGetSymbolAddress((void**)&kidx, g_kidx);
    cudaGetSymbolAddress((void**)&kcnt, g_kcnt);

    cudaFuncSetAttribute(gemm_mma, cudaFuncAttributeMaxDynamicSharedMemorySize, GEMM_SMEM);
    cudaFuncSetAttribute(qkv_fused, cudaFuncAttributeMaxDynamicSharedMemorySize, GEMM_SMEM);
    cudaFuncSetAttribute(attn_mma, cudaFuncAttributeMaxDynamicSharedMemorySize, ATTN_SMEM);

    // 0) fused pre-pass (split x, transpose+split weights, mask scan)
    prep_all<<<PREP_TOTAL, 256>>>(x, mask, w_qkv, w_proj,
                                  xhi, xlo, wqhi, wqlo, wphi, wplo, kidx, kcnt);

    // 1) fused Q + KV GEMM
    qkv_fused<<<576, 256, GEMM_SMEM>>>(
        (const uint4*)xhi, (const uint4*)xlo,
        (const uint4*)wqhi, (const uint4*)wqlo,
        kidx, kcnt, qhi, qlo, khi, klo, vhi, vlo);

    // 2) tensor-core attention over packed keys (P fp16 in registers)
    attn_mma<<<dim3(NN / QT, HH, BB), 256, ATTN_SMEM>>>(
        (const uint4*)qhi, (const uint4*)qlo, (const uint4*)khi, (const uint4*)klo,
        (const uint4*)vhi, (const uint4*)vlo, kcnt, ahi, alo);

    // 3) projection GEMM + bias
    gemm_mma<<<dim3(CC / 128, BN / 128), 256, GEMM_SMEM>>>(
        (const uint4*)ahi, (const uint4*)alo, (const uint4*)wphi, (const uint4*)wplo,
        out, BN, CC, CC, b_proj);
}

// round 10
// speedup vs baseline: 6.2107x; 1.2423x over previous
#include <cuda_runtime.h>
#include <cuda_bf16.h>
#include <cuda_fp16.h>
#include <cstdint>
#include <cstddef>

#define BB 2
#define NN 2048
#define CC 768
#define HH 12
#define HD 64
#define BN (BB * NN)          // 4096
#define QKVC (3 * CC)         // 2304

// ---------------------------------------------------------------------------
// Scratch (device globals — no allocation allowed anywhere)
// ---------------------------------------------------------------------------
__device__ __align__(16) __half g_xh [(size_t)BN * CC];           // x fp16 single
__device__ __align__(16) __half g_wqhi[(size_t)QKVC * CC];        // Wqkv^T fp16 split
__device__ __align__(16) __half g_wqlo[(size_t)QKVC * CC];
__device__ __align__(16) __half g_wphi[(size_t)CC * CC];          // Wproj^T fp16 split
__device__ __align__(16) __half g_wplo[(size_t)CC * CC];
__device__ __align__(16) __half g_ah [(size_t)BN * CC];           // attn out fp16 single
// attention operands: [b][h][token][64] row-major
__device__ __align__(16) __nv_bfloat16 g_qhi[(size_t)BB * HH * NN * HD];
__device__ __align__(16) __nv_bfloat16 g_qlo[(size_t)BB * HH * NN * HD];
__device__ __align__(16) __nv_bfloat16 g_khi[(size_t)BB * HH * NN * HD];
__device__ __align__(16) __nv_bfloat16 g_klo[(size_t)BB * HH * NN * HD];
__device__ __align__(16) __half        g_vhi[(size_t)BB * HH * NN * HD];
__device__ __align__(16) __half        g_vlo[(size_t)BB * HH * NN * HD];
__device__ int g_kidx[BB * NN];
__device__ int g_kcnt[BB];

// ---------------------------------------------------------------------------
// Family-common PTX helpers (ptxas target is sm_103 w/o 'a' — no tcgen05)
// ---------------------------------------------------------------------------
__device__ __forceinline__ uint32_t smem_u32(const void* p) {
    uint32_t a;
    asm("{ .reg .u64 t; cvta.to.shared.u64 t, %1; cvt.u32.u64 %0, t; }"
        : "=r"(a) : "l"(p));
    return a;
}
#define CP_ASYNC16(dst, src) \
    asm volatile("cp.async.cg.shared.global [%0], [%1], 16;" :: "r"(dst), "l"(src))
#define CP_COMMIT() asm volatile("cp.async.commit_group;" ::: "memory")
#define CP_WAIT(n)  asm volatile("cp.async.wait_group %0;" :: "n"(n) : "memory")

#define LDSM_X4(r0, r1, r2, r3, addr)                                          \
    asm volatile("ldmatrix.sync.aligned.m8n8.x4.shared.b16 {%0,%1,%2,%3}, [%4];" \
                 : "=r"(r0), "=r"(r1), "=r"(r2), "=r"(r3) : "r"(addr))
#define LDSM_X2(r0, r1, addr)                                                  \
    asm volatile("ldmatrix.sync.aligned.m8n8.x2.shared.b16 {%0,%1}, [%2];"     \
                 : "=r"(r0), "=r"(r1) : "r"(addr))
#define LDSM_X2_T(r0, r1, addr)                                                \
    asm volatile("ldmatrix.sync.aligned.m8n8.x2.trans.shared.b16 {%0,%1}, [%2];" \
                 : "=r"(r0), "=r"(r1) : "r"(addr))

#define MMA16816(d, a, b)                                                      \
    asm volatile("mma.sync.aligned.m16n8k16.row.col.f32.bf16.bf16.f32 "        \
                 "{%0,%1,%2,%3}, {%4,%5,%6,%7}, {%8,%9}, {%0,%1,%2,%3};"       \
                 : "+f"((d)[0]), "+f"((d)[1]), "+f"((d)[2]), "+f"((d)[3])      \
                 : "r"((a)[0]), "r"((a)[1]), "r"((a)[2]), "r"((a)[3]),         \
                   "r"((b)[0]), "r"((b)[1]))
#define MMA16816H(d, a, b)                                                     \
    asm volatile("mma.sync.aligned.m16n8k16.row.col.f32.f16.f16.f32 "          \
                 "{%0,%1,%2,%3}, {%4,%5,%6,%7}, {%8,%9}, {%0,%1,%2,%3};"       \
                 : "+f"((d)[0]), "+f"((d)[1]), "+f"((d)[2]), "+f"((d)[3])      \
                 : "r"((a)[0]), "r"((a)[1]), "r"((a)[2]), "r"((a)[3]),         \
                   "r"((b)[0]), "r"((b)[1]))

__device__ __forceinline__ uint32_t pack_split(float v0, float v1,
                                               uint32_t& lopk) {
    __nv_bfloat16 h0 = __float2bfloat16(v0);
    __nv_bfloat16 h1 = __float2bfloat16(v1);
    __nv_bfloat16 l0 = __float2bfloat16(v0 - __bfloat162float(h0));
    __nv_bfloat16 l1 = __float2bfloat16(v1 - __bfloat162float(h1));
    lopk = ((uint32_t)__bfloat16_as_ushort(l1) << 16) |
           (uint32_t)__bfloat16_as_ushort(l0);
    return ((uint32_t)__bfloat16_as_ushort(h1) << 16) |
           (uint32_t)__bfloat16_as_ushort(h0);
}
__device__ __forceinline__ uint32_t pack_split_h(float v0, float v1,
                                                 uint32_t& lopk) {
    __half h0 = __float2half_rn(v0), h1 = __float2half_rn(v1);
    __half l0 = __float2half_rn(v0 - __half2float(h0));
    __half l1 = __float2half_rn(v1 - __half2float(h1));
    lopk = ((uint32_t)__half_as_ushort(l1) << 16) |
           (uint32_t)__half_as_ushort(l0);
    return ((uint32_t)__half_as_ushort(h1) << 16) |
           (uint32_t)__half_as_ushort(h0);
}
__device__ __forceinline__ uint32_t pack_h2(float v0, float v1) {
    __half2 h = __floats2half2_rn(v0, v1);
    return *(uint32_t*)&h;
}

// ---------------------------------------------------------------------------
// fp16 2-MMA GEMM pieces: A single fp16, B fp16 hi/lo. 128x128 tile, 8 warps,
// K-chunk 32, double-buffered. Stage = 3 matrices.
// ---------------------------------------------------------------------------
#define RS 40
#define MAT_BYTES (128 * RS * 2)        // 10240
#define STAGE3 (3 * MAT_BYTES)          // 30720
#define GEMM_SMEM (2 * STAGE3)          // 61440

#define FP16_MAINLOOP(NCH)                                                     \
    for (int c = 0; c < (NCH); c++) {                                          \
        const int s = c & 1;                                                   \
        if (c + 1 < (NCH)) { prefetch(c + 1, 1 - s); CP_COMMIT(); CP_WAIT(1); }\
        else { CP_WAIT(0); }                                                   \
        __syncthreads();                                                       \
        const uint32_t As   = sb + s * STAGE3;                                 \
        const uint32_t Bs_h = As + MAT_BYTES;                                  \
        const uint32_t Bs_l = As + 2 * MAT_BYTES;                              \
        _Pragma("unroll")                                                      \
        for (int kk = 0; kk < 2; kk++) {                                       \
            uint32_t ah[2][4];                                                 \
            _Pragma("unroll")                                                  \
            for (int mt = 0; mt < 2; mt++) {                                   \
                const uint32_t ao =                                            \
                    (uint32_t)((m_base + mt * 16 + a_r) * (RS * 2) +           \
                               (kk * 16 + a_c) * 2);                           \
                LDSM_X4(ah[mt][0], ah[mt][1], ah[mt][2], ah[mt][3], As + ao);  \
            }                                                                  \
            _Pragma("unroll")                                                  \
            for (int nt = 0; nt < 8; nt++) {                                   \
                const uint32_t bo =                                            \
                    (uint32_t)((n_base + nt * 8 + b_r) * (RS * 2) +            \
                               (kk * 16 + b_c) * 2);                           \
                uint32_t bh[2], bl[2];                                         \
                LDSM_X2(bh[0], bh[1], Bs_h + bo);                              \
                LDSM_X2(bl[0], bl[1], Bs_l + bo);                              \
                _Pragma("unroll")                                              \
                for (int mt = 0; mt < 2; mt++) {                               \
                    MMA16816H(acc[mt][nt], ah[mt], bh);                        \
                    MMA16816H(acc[mt][nt], ah[mt], bl);                        \
                }                                                              \
            }                                                                  \
        }                                                                      \
        __syncthreads();                                                       \
    }

#define GEMM_COMMON_DECLS                                                      \
    extern __shared__ char smem[];                                             \
    const uint32_t sb = smem_u32(smem);                                        \
    const int tid = threadIdx.x, wid = tid >> 5, lane = tid & 31;              \
    const int wm = wid >> 1, wn = wid & 1;                                     \
    const int m_base = wm * 32, n_base = wn * 64;                              \
    const int a_r = (lane & 15);                                               \
    const int a_c = (lane >> 4) * 8;                                           \
    const int b_r = (lane & 7);                                                \
    const int b_c = ((lane >> 3) & 1) * 8;

// ---------------------------------------------------------------------------
// Proj GEMM: out[M,768] = A[M,768](fp16)·Wp^T(fp16 split) + bias (fp32 out)
// ---------------------------------------------------------------------------
__global__ __launch_bounds__(256) void gemm_mma(
    const uint4* __restrict__ Ah,
    const uint4* __restrict__ Bh, const uint4* __restrict__ Bl,
    float* __restrict__ C, const float* __restrict__ bias)
{
    GEMM_COMMON_DECLS
    const int m0 = blockIdx.y * 128, n0 = blockIdx.x * 128;
    const int Krow = CC >> 3;            // 96
    const int nch = CC >> 5;             // 24

    auto prefetch = [&](int c, int s) {
        const uint32_t stage = sb + s * STAGE3;
        #pragma unroll
        for (int it = 0; it < 6; it++) {
            const int idx = it * 256 + tid;
            const int mat = idx >> 9;
            const int rr = (idx & 511) >> 2, q = idx & 3;
            const uint32_t dst = stage + mat * MAT_BYTES +
                                 (uint32_t)(rr * (RS * 2) + q * 16);
            if (mat == 0)
                CP_ASYNC16(dst, Ah + (size_t)(m0 + rr) * Krow + c * 4 + q);
            else {
                const uint4* B = (mat == 1) ? Bh : Bl;
                CP_ASYNC16(dst, B + (size_t)(n0 + rr) * Krow + c * 4 + q);
            }
        }
    };

    float acc[2][8][4] = {};
    prefetch(0, 0);
    CP_COMMIT();
    FP16_MAINLOOP(nch)

    #pragma unroll
    for (int mt = 0; mt < 2; mt++) {
        const int row0 = m0 + m_base + mt * 16 + (lane >> 2);
        #pragma unroll
        for (int nt = 0; nt < 8; nt++) {
            const int col = n0 + n_base + nt * 8 + (lane & 3) * 2;
            float b0 = bias[col], b1 = bias[col + 1];
            float2 v0 = { acc[mt][nt][0] + b0, acc[mt][nt][1] + b1 };
            float2 v1 = { acc[mt][nt][2] + b0, acc[mt][nt][3] + b1 };
            *(float2*)(C + (size_t)row0 * CC + col) = v0;
            *(float2*)(C + (size_t)(row0 + 8) * CC + col) = v1;
        }
    }
}

// ---------------------------------------------------------------------------
// Fused QKV GEMM (fp16 2-MMA): blocks [0,192) Q; [192,576) packed K/V.
// ---------------------------------------------------------------------------
__global__ __launch_bounds__(256) void qkv_fused(
    const uint4* __restrict__ Xh,
    const uint4* __restrict__ Wh, const uint4* __restrict__ Wl,
    const int* __restrict__ kidx, const int* __restrict__ kcnt,
    __nv_bfloat16* __restrict__ qhi, __nv_bfloat16* __restrict__ qlo,
    __nv_bfloat16* __restrict__ khi, __nv_bfloat16* __restrict__ klo,
    __half* __restrict__ vhi, __half* __restrict__ vlo)
{
    GEMM_COMMON_DECLS
    const int bid = blockIdx.x;
    const int Krow = CC >> 3;            // 96
    const int nch = CC >> 5;             // 24

    if (bid < 192) {
        // ------------------- Q role -------------------
        const int m0 = (bid / 6) * 128, n0 = (bid % 6) * 128;
        auto prefetch = [&](int c, int s) {
            const uint32_t stage = sb + s * STAGE3;
            #pragma unroll
            for (int it = 0; it < 6; it++) {
                const int idx = it * 256 + tid;
                const int mat = idx >> 9;
                const int rr = (idx & 511) >> 2, q = idx & 3;
                const uint32_t dst = stage + mat * MAT_BYTES +
                                     (uint32_t)(rr * (RS * 2) + q * 16);
                if (mat == 0)
                    CP_ASYNC16(dst, Xh + (size_t)(m0 + rr) * Krow + c * 4 + q);
                else {
                    const uint4* B = (mat == 1) ? Wh : Wl;
                    CP_ASYNC16(dst, B + (size_t)(n0 + rr) * Krow + c * 4 + q);
                }
            }
        };
        float acc[2][8][4] = {};
        prefetch(0, 0);
        CP_COMMIT();
        FP16_MAINLOOP(nch)

        #pragma unroll
        for (int mt = 0; mt < 2; mt++) {
            #pragma unroll
            for (int h2 = 0; h2 < 2; h2++) {
                const int r = m0 + m_base + mt * 16 + h2 * 8 + (lane >> 2);
                const int b = r >> 11, n = r & (NN - 1);
                #pragma unroll
                for (int nt = 0; nt < 8; nt++) {
                    const int c = n0 + n_base + nt * 8 + (lane & 3) * 2;
                    const int h = c >> 6, d = c & 63;
                    const size_t o = (((size_t)b * HH + h) * NN + n) * HD + d;
                    uint32_t lopk;
                    uint32_t hipk = pack_split(acc[mt][nt][h2 * 2] * 0.125f,
                                               acc[mt][nt][h2 * 2 + 1] * 0.125f,
                                               lopk);
                    *(uint32_t*)((char*)qhi + o * 2) = hipk;
                    *(uint32_t*)((char*)qlo + o * 2) = lopk;
                }
            }
        }
    } else {
        // ------------------- KV role (packed tokens) -------------------
        const int idx0 = bid - 192;
        const int bz = idx0 / 192;
        const int rr2 = idx0 % 192;
        const int n0 = (rr2 % 12) * 128;
        const int m0 = (rr2 / 12) * 128;
        const int cnt = kcnt[bz];
        const int pad = (cnt + 63) & ~63;
        if (m0 >= pad) return;

        const uint4* Bh = Wh + (size_t)CC * CC / 8;  // wq rows [768,2304)
        const uint4* Bl = Wl + (size_t)CC * CC / 8;

        const int pr = tid >> 2;
        const int j1 = m0 + pr, j2 = j1 + 64;
        const int s1 = (j1 < cnt) ? kidx[bz * NN + j1] : 0;
        const int s2 = (j2 < cnt) ? kidx[bz * NN + j2] : 0;

        auto prefetch = [&](int c, int s) {
            const uint32_t stage = sb + s * STAGE3;
            #pragma unroll
            for (int it = 0; it < 6; it++) {
                const int idx = it * 256 + tid;
                const int mat = idx >> 9;
                const int rr = (idx & 511) >> 2, q = idx & 3;
                const uint32_t dst = stage + mat * MAT_BYTES +
                                     (uint32_t)(rr * (RS * 2) + q * 16);
                if (mat == 0) {
                    const int srow = (it == 0) ? s1 : s2;   // it 0: rows<64, it 1: rows>=64
                    CP_ASYNC16(dst, Xh + (size_t)(bz * NN + srow) * Krow + c * 4 + q);
                } else {
                    const uint4* B = (mat == 1) ? Bh : Bl;
                    CP_ASYNC16(dst, B + (size_t)(n0 + rr) * Krow + c * 4 + q);
                }
            }
        };
        float acc[2][8][4] = {};
        prefetch(0, 0);
        CP_COMMIT();
        FP16_MAINLOOP(nch)

        #pragma unroll
        for (int mt = 0; mt < 2; mt++) {
            #pragma unroll
            for (int h2 = 0; h2 < 2; h2++) {
                const int j = m0 + m_base + mt * 16 + h2 * 8 + (lane >> 2);
                #pragma unroll
                for (int nt = 0; nt < 8; nt++) {
                    const int c = n0 + n_base + nt * 8 + (lane & 3) * 2;
                    const int isV = c >= CC;
                    const int cc = isV ? c - CC : c;
                    const int h = cc >> 6, d = cc & 63;
                    const size_t o = (((size_t)bz * HH + h) * NN + j) * HD + d;
                    uint32_t lopk, hipk;
                    if (isV) {
                        hipk = pack_split_h(acc[mt][nt][h2 * 2],
                                            acc[mt][nt][h2 * 2 + 1], lopk);
                        *(uint32_t*)((char*)vhi + o * 2) = hipk;
                        *(uint32_t*)((char*)vlo + o * 2) = lopk;
                    } else {
                        hipk = pack_split(acc[mt][nt][h2 * 2],
                                          acc[mt][nt][h2 * 2 + 1], lopk);
                        *(uint32_t*)((char*)khi + o * 2) = hipk;
                        *(uint32_t*)((char*)klo + o * 2) = lopk;
                    }
                }
            }
        }
    }
}

// ---------------------------------------------------------------------------
// Fused pre-pass: [x->fp16][transpose+split wqkv][transpose+split wproj][scan]
// ---------------------------------------------------------------------------
#define PREP_SPLIT (BN * CC / 256)          // 12288
#define PREP_TQ (72 * 24)                   // 1728
#define PREP_TP (24 * 24)                   // 576
#define PREP_TOTAL (PREP_SPLIT + PREP_TQ + PREP_TP + BB)

__global__ __launch_bounds__(256) void prep_all(
    const float* __restrict__ x, const int* __restrict__ mask,
    const float* __restrict__ w_qkv, const float* __restrict__ w_proj,
    __half* __restrict__ xh,
    __half* __restrict__ wqhi, __half* __restrict__ wqlo,
    __half* __restrict__ wphi, __half* __restrict__ wplo,
    int* __restrict__ kidx, int* __restrict__ kcnt)
{
    __shared__ float tbuf[32][33];
    __shared__ int part[256];
    const int bid = blockIdx.x, tid = threadIdx.x;

    if (bid < PREP_SPLIT) {
        const int i = bid * 256 + tid;
        xh[i] = __float2half_rn(x[i]);
    } else if (bid < PREP_SPLIT + PREP_TQ + PREP_TP) {
        const bool isQ = bid < PREP_SPLIT + PREP_TQ;
        const int t = isQ ? bid - PREP_SPLIT : bid - (PREP_SPLIT + PREP_TQ);
        const float* W = isQ ? w_qkv : w_proj;
        __half* hi = isQ ? wqhi : wphi;
        __half* lo = isQ ? wqlo : wplo;
        const int N = isQ ? QKVC : CC;
        const int nblk = N / 32;
        const int n0 = (t % nblk) * 32, k0 = (t / nblk) * 32;
        const int tx = tid & 31, ty = tid >> 5;
        #pragma unroll
        for (int j = 0; j < 4; j++)
            tbuf[ty + 8 * j][tx] = W[(size_t)(k0 + ty + 8 * j) * N + n0 + tx];
        __syncthreads();
        #pragma unroll
        for (int j = 0; j < 4; j++) {
            const int nl = ty + 8 * j;
            float v = tbuf[tx][nl];
            __half h = __float2half_rn(v);
            size_t o = (size_t)(n0 + nl) * CC + k0 + tx;
            hi[o] = h;
            lo[o] = __float2half_rn(v - __half2float(h));
        }
    } else {
        const int b = bid - (PREP_SPLIT + PREP_TQ + PREP_TP);
        const int* m = mask + b * NN;
        int loc[8], c = 0;
        #pragma unroll
        for (int i = 0; i < 8; i++) { loc[i] = c; c += m[tid * 8 + i]; }
        part[tid] = c;
        __syncthreads();
        for (int off = 1; off < 256; off <<= 1) {
            int v = (tid >= off) ? part[tid - off] : 0;
            __syncthreads();
            part[tid] += v;
            __syncthreads();
        }
        int excl = part[tid] - c;
        #pragma unroll
        for (int i = 0; i < 8; i++)
            if (m[tid * 8 + i]) kidx[b * NN + excl + loc[i]] = tid * 8 + i;
        if (tid == 255) kcnt[b] = part[255];
    }
}

// ---------------------------------------------------------------------------
// Tensor-core attention, P-in-registers; PV in fp16; out single fp16.
// ---------------------------------------------------------------------------
#define QT 128
#define KT 64
#define PADB 144                 // 72 x 16-bit per row
#define SM_STG  36864
#define STG_SZ  36864            // Kh,Kl,Vh,Vl : 9216 each
#define SM_RED  36864            // overlaid on stage0 (used only after loop)
#define SM_DEN  110592
#define ATTN_SMEM (110592 + 512)

__global__ __launch_bounds__(256) void attn_mma(
    const uint4* __restrict__ Qh, const uint4* __restrict__ Ql,
    const uint4* __restrict__ Kh, const uint4* __restrict__ Kl,
    const uint4* __restrict__ Vh, const uint4* __restrict__ Vl,
    const int* __restrict__ kcnt, __half* __restrict__ aout)
{
    extern __shared__ char sm[];
    const uint32_t sb = smem_u32(sm);
    const int b = blockIdx.z, h = blockIdx.y, q0 = blockIdx.x * QT;
    const int tid = threadIdx.x, wid = tid >> 5, lane = tid & 31;
    const int wm = wid >> 1, wn = wid & 1;
    const int mb = wm * 32, nb = wn * 32;
    const int cnt = kcnt[b];
    const int ntiles = (cnt + KT - 1) / KT;
    const size_t bh = (size_t)b * HH + h;

    float* denom_s = (float*)(sm + SM_DEN);
    if (tid < 128) denom_s[tid] = 0.0f;

    // resident Q tile (hi at 0, lo at 18432)
    #pragma unroll
    for (int it = 0; it < 4; it++) {
        int idx = it * 256 + tid;
        int r = idx >> 3, c = idx & 7;
        size_t gi = (bh * NN + q0 + r) * 8 + c;
        *(uint4*)(sm + r * PADB + c * 16) = Qh[gi];
        *(uint4*)(sm + 18432 + r * PADB + c * 16) = Ql[gi];
    }

    auto prefetch = [&](int t, int s) {
        const uint32_t stg = sb + SM_STG + s * STG_SZ;
        const int k0 = t * KT;
        #pragma unroll
        for (int it = 0; it < 8; it++) {
            int idx = it * 256 + tid;
            int mat = idx >> 9;                // 0 Kh,1 Kl,2 Vh,3 Vl
            int r = (idx >> 3) & 63, c = idx & 7;
            uint32_t dst = stg + mat * 9216 + (uint32_t)(r * PADB + c * 16);
            const uint4* g = (mat == 0) ? Kh : (mat == 1) ? Kl
                           : (mat == 2) ? Vh : Vl;
            size_t gi = (bh * NN + k0 + r) * 8 + c;
            CP_ASYNC16(dst, g + gi);
        }
    };

    float accO[2][8][4] = {};
    float denA[2][2] = {};

    const int a_r = lane & 15, a_c = (lane >> 4) * 8;
    const int b_r = lane & 7,  b_c = ((lane >> 3) & 1) * 8;
    const int t_r = lane & 15;

    prefetch(0, 0);
    CP_COMMIT();

    for (int t = 0; t < ntiles; t++) {
        const int s = t & 1;
        const int k0 = t * KT;
        CP_WAIT(0);
        __syncthreads();
        if (t + 1 < ntiles) { prefetch(t + 1, 1 - s); CP_COMMIT(); }

        const uint32_t Ksh = sb + SM_STG + s * STG_SZ;
        const uint32_t Ksl = Ksh + 9216;
        const uint32_t Vsh = Ksh + 18432;
        const uint32_t Vsl = Ksh + 27648;

        // S = Q K^T over this warp's 32q x 32k (split bf16, 3 products)
        float accS[2][4][4] = {};
        #pragma unroll
        for (int ks = 0; ks < 4; ks++) {
            uint32_t ah[2][4], al[2][4];
            #pragma unroll
            for (int mt = 0; mt < 2; mt++) {
                uint32_t ao = sb + (uint32_t)((mb + mt * 16 + a_r) * PADB +
                                              (ks * 16 + a_c) * 2);
                LDSM_X4(ah[mt][0], ah[mt][1], ah[mt][2], ah[mt][3], ao);
                LDSM_X4(al[mt][0], al[mt][1], al[mt][2], al[mt][3], ao + 18432);
            }
            #pragma unroll
            for (int nt = 0; nt < 4; nt++) {
                uint32_t bo = (uint32_t)((nb + nt * 8 + b_r) * PADB +
                                         (ks * 16 + b_c) * 2);
                uint32_t bhv[2], blv[2];
                LDSM_X2(bhv[0], bhv[1], Ksh + bo);
                LDSM_X2(blv[0], blv[1], Ksl + bo);
                #pragma unroll
                for (int mt = 0; mt < 2; mt++) {
                    MMA16816(accS[mt][nt], ah[mt], bhv);
                    MMA16816(accS[mt][nt], ah[mt], blv);
                    MMA16816(accS[mt][nt], al[mt], bhv);
                }
            }
        }

        // exp + mask; P packed to single fp16 A fragments
        uint32_t aP[2][2][4];
        #pragma unroll
        for (int mt = 0; mt < 2; mt++) {
            #pragma unroll
            for (int nt = 0; nt < 4; nt++) {
                int c0i = nb + nt * 8 + (lane & 3) * 2;
                float m0v = (k0 + c0i     < cnt) ? 1.f : 0.f;
                float m1v = (k0 + c0i + 1 < cnt) ? 1.f : 0.f;
                #pragma unroll
                for (int h2 = 0; h2 < 2; h2++) {
                    float p0 = __expf(accS[mt][nt][h2 * 2 + 0]) * m0v;
                    float p1 = __expf(accS[mt][nt][h2 * 2 + 1]) * m1v;
                    denA[mt][h2] += p0 + p1;
                    aP[mt][nt >> 1][(nt & 1) * 2 + h2] = pack_h2(p0, p1);
                }
            }
        }

        // O += P·Vh + P·Vl (fp16), this warp's 32 keys, full d=64
        #pragma unroll
        for (int kt = 0; kt < 2; kt++) {
            #pragma unroll
            for (int dt = 0; dt < 8; dt++) {
                uint32_t bo = (uint32_t)((nb + kt * 16 + t_r) * PADB + dt * 16);
                uint32_t bvh[2], bvl[2];
                LDSM_X2_T(bvh[0], bvh[1], Vsh + bo);
                LDSM_X2_T(bvl[0], bvl[1], Vsl + bo);
                #pragma unroll
                for (int mt = 0; mt < 2; mt++) {
                    MMA16816H(accO[mt][dt], aP[mt][kt], bvh);
                    MMA16816H(accO[mt][dt], aP[mt][kt], bvl);
                }
            }
        }
    }

    // denom: quad-reduce then smem atomics
    #pragma unroll
    for (int mt = 0; mt < 2; mt++)
        #pragma unroll
        for (int h2 = 0; h2 < 2; h2++) {
            float v = denA[mt][h2];
            v += __shfl_xor_sync(0xffffffffu, v, 1);
            v += __shfl_xor_sync(0xffffffffu, v, 2);
            if ((lane & 3) == 0)
                atomicAdd(&denom_s[mb + mt * 16 + h2 * 8 + (lane >> 2)], v);
        }
    __syncthreads();

    // cross-pair O reduction: wn=1 stores to REDBUF (overlaid on stage0)
    float* red = (float*)(sm + SM_RED);
    if (wn == 1) {
        #pragma unroll
        for (int mt = 0; mt < 2; mt++) {
            const int r = mb + mt * 16 + (lane >> 2);
            #pragma unroll
            for (int dt = 0; dt < 8; dt++) {
                const int cc = dt * 8 + (lane & 3) * 2;
                *(float2*)&red[(size_t)r * 64 + cc] =
                    make_float2(accO[mt][dt][0], accO[mt][dt][1]);
                *(float2*)&red[(size_t)(r + 8) * 64 + cc] =
                    make_float2(accO[mt][dt][2], accO[mt][dt][3]);
            }
        }
    }
    __syncthreads();

    // wn=0 finalizes: add pair partial, divide, single-fp16 store
    if (wn == 0) {
        #pragma unroll
        for (int mt = 0; mt < 2; mt++) {
            const int r = mb + mt * 16 + (lane >> 2);
            const float inv0 = 1.0f / denom_s[r];
            const float inv1 = 1.0f / denom_s[r + 8];
            const size_t row0 = (size_t)(b * NN + q0 + r) * CC + h * HD;
            const size_t row1 = (size_t)(b * NN + q0 + r + 8) * CC + h * HD;
            #pragma unroll
            for (int dt = 0; dt < 8; dt++) {
                const int cc = dt * 8 + (lane & 3) * 2;
                float2 pr0 = *(float2*)&red[(size_t)r * 64 + cc];
                float2 pr1 = *(float2*)&red[(size_t)(r + 8) * 64 + cc];
                float v0 = (accO[mt][dt][0] + pr0.x) * inv0;
                float v1 = (accO[mt][dt][1] + pr0.y) * inv0;
                float v2 = (accO[mt][dt][2] + pr1.x) * inv1;
                float v3 = (accO[mt][dt][3] + pr1.y) * inv1;
                *(uint32_t*)((char*)aout + (row0 + cc) * 2) = pack_h2(v0, v1);
                *(uint32_t*)((char*)aout + (row1 + cc) * 2) = pack_h2(v2, v3);
            }
        }
    }
}

// ---------------------------------------------------------------------------
extern "C" void kernel_launch(void* const* d_in, const int* in_sizes, int n_in,
                              void* d_out, int out_size)
{
    const float* x      = (const float*)d_in[0];
    const int*   mask   = (const int*)  d_in[1];
    const float* w_qkv  = (const float*)d_in[2];
    const float* w_proj = (const float*)d_in[3];
    const float* b_proj = (const float*)d_in[4];
    float* out = (float*)d_out;

    __half *xh, *wqhi, *wqlo, *wphi, *wplo, *ah, *vhi, *vlo;
    __nv_bfloat16 *qhi, *qlo, *khi, *klo;
    int *kidx, *kcnt;
    cudaGetSymbolAddress((void**)&xh, g_xh);
    cudaGetSymbolAddress((void**)&wqhi, g_wqhi);
    cudaGetSymbolAddress((void**)&wqlo, g_wqlo);
    cudaGetSymbolAddress((void**)&wphi, g_wphi);
    cudaGetSymbolAddress((void**)&wplo, g_wplo);
    cudaGetSymbolAddress((void**)&ah, g_ah);
    cudaGetSymbolAddress((void**)&qhi, g_qhi);
    cudaGetSymbolAddress((void**)&qlo, g_qlo);
    cudaGetSymbolAddress((void**)&khi, g_khi);
    cudaGetSymbolAddress((void**)&klo, g_klo);
    cudaGetSymbolAddress((void**)&vhi, g_vhi);
    cudaGetSymbolAddress((void**)&vlo, g_vlo);
    cudaGetSymbolAddress((void**)&kidx, g_kidx);
    cudaGetSymbolAddress((void**)&kcnt, g_kcnt);

    cudaFuncSetAttribute(gemm_mma, cudaFuncAttributeMaxDynamicSharedMemorySize, GEMM_SMEM);
    cudaFuncSetAttribute(qkv_fused, cudaFuncAttributeMaxDynamicSharedMemorySize, GEMM_SMEM);
    cudaFuncSetAttribute(attn_mma, cudaFuncAttributeMaxDynamicSharedMemorySize, ATTN_SMEM);

    // 0) fused pre-pass
    prep_all<<<PREP_TOTAL, 256>>>(x, mask, w_qkv, w_proj,
                                  xh, wqhi, wqlo, wphi, wplo, kidx, kcnt);

    // 1) fused Q + KV GEMM (fp16 2-MMA)
    qkv_fused<<<576, 256, GEMM_SMEM>>>(
        (const uint4*)xh, (const uint4*)wqhi, (const uint4*)wqlo,
        kidx, kcnt, qhi, qlo, khi, klo, vhi, vlo);

    // 2) tensor-core attention over packed keys
    attn_mma<<<dim3(NN / QT, HH, BB), 256, ATTN_SMEM>>>(
        (const uint4*)qhi, (const uint4*)qlo, (const uint4*)khi, (const uint4*)klo,
        (const uint4*)vhi, (const uint4*)vlo, kcnt, ah);

    // 3) projection GEMM (fp16 2-MMA) + bias
    gemm_mma<<<dim3(CC / 128, BN / 128), 256, GEMM_SMEM>>>(
        (const uint4*)ah, (const uint4*)wphi, (const uint4*)wplo, out, b_proj);
}

// round 11
// speedup vs baseline: 7.6074x; 1.2249x over previous
#include <cuda_runtime.h>
#include <cuda_bf16.h>
#include <cuda_fp16.h>
#include <cstdint>
#include <cstddef>

#define BB 2
#define NN 2048
#define CC 768
#define HH 12
#define HD 64
#define BN (BB * NN)          // 4096
#define QKVC (3 * CC)         // 2304

// ---------------------------------------------------------------------------
// Scratch (device globals — no allocation allowed anywhere)
// ---------------------------------------------------------------------------
__device__ __align__(16) __half g_xh  [(size_t)BN * CC];          // x fp16
__device__ __align__(16) __half g_wqhi[(size_t)QKVC * CC];        // Wqkv^T split
__device__ __align__(16) __half g_wqlo[(size_t)QKVC * CC];
__device__ __align__(16) __half g_wphi[(size_t)CC * CC];          // Wproj^T split
__device__ __align__(16) __half g_wplo[(size_t)CC * CC];
__device__ __align__(16) __half g_ah  [(size_t)BN * CC];          // attn out fp16
// attention operands: [b][h][token][64] row-major, single fp16
__device__ __align__(16) __half g_qh[(size_t)BB * HH * NN * HD];
__device__ __align__(16) __half g_kh[(size_t)BB * HH * NN * HD];
__device__ __align__(16) __half g_vh[(size_t)BB * HH * NN * HD];
__device__ int g_kidx[BB * NN];
__device__ int g_kcnt[BB];

// ---------------------------------------------------------------------------
// PTX helpers (family-common; ptxas target is sm_103 w/o 'a')
// ---------------------------------------------------------------------------
__device__ __forceinline__ uint32_t smem_u32(const void* p) {
    uint32_t a;
    asm("{ .reg .u64 t; cvta.to.shared.u64 t, %1; cvt.u32.u64 %0, t; }"
        : "=r"(a) : "l"(p));
    return a;
}
#define CP_ASYNC16(dst, src) \
    asm volatile("cp.async.cg.shared.global [%0], [%1], 16;" :: "r"(dst), "l"(src))
#define CP_COMMIT() asm volatile("cp.async.commit_group;" ::: "memory")
#define CP_WAIT(n)  asm volatile("cp.async.wait_group %0;" :: "n"(n) : "memory")

#define LDSM_X4(r0, r1, r2, r3, addr)                                          \
    asm volatile("ldmatrix.sync.aligned.m8n8.x4.shared.b16 {%0,%1,%2,%3}, [%4];" \
                 : "=r"(r0), "=r"(r1), "=r"(r2), "=r"(r3) : "r"(addr))
#define LDSM_X2(r0, r1, addr)                                                  \
    asm volatile("ldmatrix.sync.aligned.m8n8.x2.shared.b16 {%0,%1}, [%2];"     \
                 : "=r"(r0), "=r"(r1) : "r"(addr))
#define LDSM_X2_T(r0, r1, addr)                                                \
    asm volatile("ldmatrix.sync.aligned.m8n8.x2.trans.shared.b16 {%0,%1}, [%2];" \
                 : "=r"(r0), "=r"(r1) : "r"(addr))

#define MMA16816H(d, a, b)                                                     \
    asm volatile("mma.sync.aligned.m16n8k16.row.col.f32.f16.f16.f32 "          \
                 "{%0,%1,%2,%3}, {%4,%5,%6,%7}, {%8,%9}, {%0,%1,%2,%3};"       \
                 : "+f"((d)[0]), "+f"((d)[1]), "+f"((d)[2]), "+f"((d)[3])      \
                 : "r"((a)[0]), "r"((a)[1]), "r"((a)[2]), "r"((a)[3]),         \
                   "r"((b)[0]), "r"((b)[1]))

__device__ __forceinline__ uint32_t pack_h2(float v0, float v1) {
    __half2 h = __floats2half2_rn(v0, v1);
    return *(uint32_t*)&h;
}

// ---------------------------------------------------------------------------
// MT1 fp16 GEMM pieces: 64x128 tile, 8 warps (4M x 2N), warp tile 16x64,
// K-chunk 32, double-buffered. A single fp16, B fp16 hi/lo (2 MMAs).
// ---------------------------------------------------------------------------
#define RS 40
#define MAT_A  (64 * RS * 2)            // 5120
#define MAT_B  (128 * RS * 2)           // 10240
#define STAGE_P (MAT_A + 2 * MAT_B)     // 25600
#define GEMM_SMEM (2 * STAGE_P)         // 51200

#define MT1_DECLS                                                              \
    extern __shared__ char smem[];                                             \
    const uint32_t sb = smem_u32(smem);                                        \
    const int tid = threadIdx.x, wid = tid >> 5, lane = tid & 31;              \
    const int wm = wid >> 1, wn = wid & 1;                                     \
    const int m_base = wm * 16, n_base = wn * 64;                              \
    const int a_r = (lane & 15);                                               \
    const int a_c = (lane >> 4) * 8;                                           \
    const int b_r = (lane & 7);                                                \
    const int b_c = ((lane >> 3) & 1) * 8;

#define MT1_MAINLOOP(NCH)                                                      \
    for (int c = 0; c < (NCH); c++) {                                          \
        const int s = c & 1;                                                   \
        if (c + 1 < (NCH)) { prefetch(c + 1, 1 - s); CP_COMMIT(); CP_WAIT(1); }\
        else { CP_WAIT(0); }                                                   \
        __syncthreads();                                                       \
        const uint32_t As   = sb + s * STAGE_P;                                \
        const uint32_t Bs_h = As + MAT_A;                                      \
        const uint32_t Bs_l = As + MAT_A + MAT_B;                              \
        _Pragma("unroll")                                                      \
        for (int kk = 0; kk < 2; kk++) {                                       \
            uint32_t ah[4];                                                    \
            const uint32_t ao =                                                \
                (uint32_t)((m_base + a_r) * (RS * 2) + (kk * 16 + a_c) * 2);   \
            LDSM_X4(ah[0], ah[1], ah[2], ah[3], As + ao);                      \
            _Pragma("unroll")                                                  \
            for (int nt = 0; nt < 8; nt++) {                                   \
                const uint32_t bo =                                            \
                    (uint32_t)((n_base + nt * 8 + b_r) * (RS * 2) +            \
                               (kk * 16 + b_c) * 2);                           \
                uint32_t bh[2], bl[2];                                         \
                LDSM_X2(bh[0], bh[1], Bs_h + bo);                              \
                LDSM_X2(bl[0], bl[1], Bs_l + bo);                              \
                MMA16816H(acc[nt], ah, bh);                                    \
                MMA16816H(acc[nt], ah, bl);                                    \
            }                                                                  \
        }                                                                      \
        __syncthreads();                                                       \
    }

// B prefetch shared by all MT1 kernels: 2 mats x 128 rows x 4 chunks
#define MT1_PREFETCH_B(stage, Bh, Bl, n0, c)                                   \
    _Pragma("unroll")                                                          \
    for (int it = 0; it < 4; it++) {                                           \
        const int idx = it * 256 + tid;                                        \
        const int mat = idx >> 9;                                              \
        const int rb = (idx >> 2) & 127, qb = idx & 3;                         \
        const uint4* Bp = (mat == 0) ? (Bh) : (Bl);                            \
        CP_ASYNC16((stage) + MAT_A + mat * MAT_B +                             \
                       (uint32_t)(rb * (RS * 2) + qb * 16),                    \
                   Bp + (size_t)((n0) + rb) * 96 + (c) * 4 + qb);              \
    }

// ---------------------------------------------------------------------------
// Proj GEMM: out[4096,768] = A(fp16)·Wp^T(split) + bias. Grid (6, 64).
// ---------------------------------------------------------------------------
__global__ __launch_bounds__(256) void gemm_proj(
    const uint4* __restrict__ Ah,
    const uint4* __restrict__ Bh, const uint4* __restrict__ Bl,
    float* __restrict__ C, const float* __restrict__ bias)
{
    MT1_DECLS
    const int m0 = blockIdx.y * 64, n0 = blockIdx.x * 128;
    const int nch = CC >> 5;             // 24

    auto prefetch = [&](int c, int s) {
        const uint32_t stage = sb + s * STAGE_P;
        const int r = tid >> 2, q = tid & 3;
        CP_ASYNC16(stage + (uint32_t)(r * (RS * 2) + q * 16),
                   Ah + (size_t)(m0 + r) * 96 + c * 4 + q);
        MT1_PREFETCH_B(stage, Bh, Bl, n0, c)
    };

    float acc[8][4] = {};
    prefetch(0, 0);
    CP_COMMIT();
    MT1_MAINLOOP(nch)

    const int row0 = m0 + m_base + (lane >> 2);
    #pragma unroll
    for (int nt = 0; nt < 8; nt++) {
        const int col = n0 + n_base + nt * 8 + (lane & 3) * 2;
        float b0 = bias[col], b1 = bias[col + 1];
        float2 v0 = { acc[nt][0] + b0, acc[nt][1] + b1 };
        float2 v1 = { acc[nt][2] + b0, acc[nt][3] + b1 };
        *(float2*)(C + (size_t)row0 * CC + col) = v0;
        *(float2*)(C + (size_t)(row0 + 8) * CC + col) = v1;
    }
}

// ---------------------------------------------------------------------------
// Fused QKV GEMM (MT1): blocks [0,384) Q; [384,1152) packed K/V.
// Outputs single fp16 in attention layout.
// ---------------------------------------------------------------------------
__global__ __launch_bounds__(256) void qkv_fused(
    const uint4* __restrict__ Xh,
    const uint4* __restrict__ Wh, const uint4* __restrict__ Wl,
    const int* __restrict__ kidx, const int* __restrict__ kcnt,
    __half* __restrict__ qh, __half* __restrict__ kh, __half* __restrict__ vh)
{
    MT1_DECLS
    const int bid = blockIdx.x;
    const int nch = CC >> 5;             // 24

    if (bid < 384) {
        // ------------------- Q role -------------------
        const int m0 = (bid / 6) * 64, n0 = (bid % 6) * 128;
        auto prefetch = [&](int c, int s) {
            const uint32_t stage = sb + s * STAGE_P;
            const int r = tid >> 2, q = tid & 3;
            CP_ASYNC16(stage + (uint32_t)(r * (RS * 2) + q * 16),
                       Xh + (size_t)(m0 + r) * 96 + c * 4 + q);
            MT1_PREFETCH_B(stage, Wh, Wl, n0, c)
        };
        float acc[8][4] = {};
        prefetch(0, 0);
        CP_COMMIT();
        MT1_MAINLOOP(nch)

        #pragma unroll
        for (int h2 = 0; h2 < 2; h2++) {
            const int r = m0 + m_base + h2 * 8 + (lane >> 2);
            const int b = r >> 11, n = r & (NN - 1);
            #pragma unroll
            for (int nt = 0; nt < 8; nt++) {
                const int c = n0 + n_base + nt * 8 + (lane & 3) * 2;
                const int h = c >> 6, d = c & 63;
                const size_t o = (((size_t)b * HH + h) * NN + n) * HD + d;
                *(uint32_t*)((char*)qh + o * 2) =
                    pack_h2(acc[nt][h2 * 2] * 0.125f,
                            acc[nt][h2 * 2 + 1] * 0.125f);
            }
        }
    } else {
        // ------------------- KV role (packed tokens) -------------------
        const int idx0 = bid - 384;
        const int bz = idx0 / 384;
        const int rr2 = idx0 % 384;
        const int m0 = (rr2 / 12) * 64;
        const int n0 = (rr2 % 12) * 128;
        const int cnt = kcnt[bz];
        const int pad = (cnt + 63) & ~63;
        if (m0 >= pad) return;

        const uint4* Bh = Wh + (size_t)CC * CC / 8;  // wq rows [768,2304)
        const uint4* Bl = Wl + (size_t)CC * CC / 8;

        const int pr = tid >> 2, pq = tid & 3;
        const int j1 = m0 + pr;
        const int s1 = (j1 < cnt) ? kidx[bz * NN + j1] : 0;

        auto prefetch = [&](int c, int s) {
            const uint32_t stage = sb + s * STAGE_P;
            CP_ASYNC16(stage + (uint32_t)(pr * (RS * 2) + pq * 16),
                       Xh + (size_t)(bz * NN + s1) * 96 + c * 4 + pq);
            MT1_PREFETCH_B(stage, Bh, Bl, n0, c)
        };
        float acc[8][4] = {};
        prefetch(0, 0);
        CP_COMMIT();
        MT1_MAINLOOP(nch)

        #pragma unroll
        for (int h2 = 0; h2 < 2; h2++) {
            const int j = m0 + m_base + h2 * 8 + (lane >> 2);
            #pragma unroll
            for (int nt = 0; nt < 8; nt++) {
                const int c = n0 + n_base + nt * 8 + (lane & 3) * 2;
                const int isV = c >= CC;
                const int cc = isV ? c - CC : c;
                const int h = cc >> 6, d = cc & 63;
                const size_t o = (((size_t)bz * HH + h) * NN + j) * HD + d;
                __half* dst = isV ? vh : kh;
                *(uint32_t*)((char*)dst + o * 2) =
                    pack_h2(acc[nt][h2 * 2], acc[nt][h2 * 2 + 1]);
            }
        }
    }
}

// ---------------------------------------------------------------------------
// Fused pre-pass: [x->fp16][transpose+split wqkv][transpose+split wproj][scan]
// ---------------------------------------------------------------------------
#define PREP_SPLIT (BN * CC / 256)          // 12288
#define PREP_TQ (72 * 24)                   // 1728
#define PREP_TP (24 * 24)                   // 576
#define PREP_TOTAL (PREP_SPLIT + PREP_TQ + PREP_TP + BB)

__global__ __launch_bounds__(256) void prep_all(
    const float* __restrict__ x, const int* __restrict__ mask,
    const float* __restrict__ w_qkv, const float* __restrict__ w_proj,
    __half* __restrict__ xh,
    __half* __restrict__ wqhi, __half* __restrict__ wqlo,
    __half* __restrict__ wphi, __half* __restrict__ wplo,
    int* __restrict__ kidx, int* __restrict__ kcnt)
{
    __shared__ float tbuf[32][33];
    __shared__ int part[256];
    const int bid = blockIdx.x, tid = threadIdx.x;

    if (bid < PREP_SPLIT) {
        const int i = bid * 256 + tid;
        xh[i] = __float2half_rn(x[i]);
    } else if (bid < PREP_SPLIT + PREP_TQ + PREP_TP) {
        const bool isQ = bid < PREP_SPLIT + PREP_TQ;
        const int t = isQ ? bid - PREP_SPLIT : bid - (PREP_SPLIT + PREP_TQ);
        const float* W = isQ ? w_qkv : w_proj;
        __half* hi = isQ ? wqhi : wphi;
        __half* lo = isQ ? wqlo : wplo;
        const int N = isQ ? QKVC : CC;
        const int nblk = N / 32;
        const int n0 = (t % nblk) * 32, k0 = (t / nblk) * 32;
        const int tx = tid & 31, ty = tid >> 5;
        #pragma unroll
        for (int j = 0; j < 4; j++)
            tbuf[ty + 8 * j][tx] = W[(size_t)(k0 + ty + 8 * j) * N + n0 + tx];
        __syncthreads();
        #pragma unroll
        for (int j = 0; j < 4; j++) {
            const int nl = ty + 8 * j;
            float v = tbuf[tx][nl];
            __half h = __float2half_rn(v);
            size_t o = (size_t)(n0 + nl) * CC + k0 + tx;
            hi[o] = h;
            lo[o] = __float2half_rn(v - __half2float(h));
        }
    } else {
        const int b = bid - (PREP_SPLIT + PREP_TQ + PREP_TP);
        const int* m = mask + b * NN;
        int loc[8], c = 0;
        #pragma unroll
        for (int i = 0; i < 8; i++) { loc[i] = c; c += m[tid * 8 + i]; }
        part[tid] = c;
        __syncthreads();
        for (int off = 1; off < 256; off <<= 1) {
            int v = (tid >= off) ? part[tid - off] : 0;
            __syncthreads();
            part[tid] += v;
            __syncthreads();
        }
        int excl = part[tid] - c;
        #pragma unroll
        for (int i = 0; i < 8; i++)
            if (m[tid * 8 + i]) kidx[b * NN + excl + loc[i]] = tid * 8 + i;
        if (tid == 255) kcnt[b] = part[255];
    }
}

// ---------------------------------------------------------------------------
// Tensor-core attention: Q/K/V single fp16 (S 1 MMA, PV 1 MMA),
// P-in-registers, cross-pair O reduction through smem.
// ---------------------------------------------------------------------------
#define QT 128
#define KT 64
#define PADB 144                 // 72 x 16-bit per row
#define SM_STG  18432            // after Q resident
#define STG_SZ  18432            // K 9216 + V 9216
#define SM_RED  18432            // overlaid on stage area (post-loop only)
#define SM_DEN  55296
#define ATTN_SMEM (55296 + 512)

__global__ __launch_bounds__(256) void attn_mma(
    const uint4* __restrict__ Qh, const uint4* __restrict__ Kh,
    const uint4* __restrict__ Vh, const int* __restrict__ kcnt,
    __half* __restrict__ aout)
{
    extern __shared__ char sm[];
    const uint32_t sb = smem_u32(sm);
    const int b = blockIdx.z, h = blockIdx.y, q0 = blockIdx.x * QT;
    const int tid = threadIdx.x, wid = tid >> 5, lane = tid & 31;
    const int wm = wid >> 1, wn = wid & 1;
    const int mb = wm * 32, nb = wn * 32;
    const int cnt = kcnt[b];
    const int ntiles = (cnt + KT - 1) / KT;
    const size_t bh = (size_t)b * HH + h;

    float* denom_s = (float*)(sm + SM_DEN);
    if (tid < 128) denom_s[tid] = 0.0f;

    // resident Q tile (single fp16)
    #pragma unroll
    for (int it = 0; it < 4; it++) {
        int idx = it * 256 + tid;
        int r = idx >> 3, c = idx & 7;
        *(uint4*)(sm + r * PADB + c * 16) = Qh[(bh * NN + q0 + r) * 8 + c];
    }

    auto prefetch = [&](int t, int s) {
        const uint32_t stg = sb + SM_STG + s * STG_SZ;
        const int k0 = t * KT;
        #pragma unroll
        for (int it = 0; it < 4; it++) {
            int idx = it * 256 + tid;
            int mat = idx >> 9;                // 0 K, 1 V
            int r = (idx >> 3) & 63, c = idx & 7;
            uint32_t dst = stg + mat * 9216 + (uint32_t)(r * PADB + c * 16);
            const uint4* g = (mat == 0) ? Kh : Vh;
            CP_ASYNC16(dst, g + (bh * NN + k0 + r) * 8 + c);
        }
    };

    float accO[2][8][4] = {};
    float denA[2][2] = {};

    const int a_r = lane & 15, a_c = (lane >> 4) * 8;
    const int b_r = lane & 7,  b_c = ((lane >> 3) & 1) * 8;
    const int t_r = lane & 15;

    prefetch(0, 0);
    CP_COMMIT();

    for (int t = 0; t < ntiles; t++) {
        const int s = t & 1;
        const int k0 = t * KT;
        CP_WAIT(0);
        __syncthreads();
        if (t + 1 < ntiles) { prefetch(t + 1, 1 - s); CP_COMMIT(); }

        const uint32_t Ks = sb + SM_STG + s * STG_SZ;
        const uint32_t Vs = Ks + 9216;

        // S = Q K^T over this warp's 32q x 32k (fp16, 1 MMA)
        float accS[2][4][4] = {};
        #pragma unroll
        for (int ks = 0; ks < 4; ks++) {
            uint32_t ah[2][4];
            #pragma unroll
            for (int mt = 0; mt < 2; mt++) {
                uint32_t ao = sb + (uint32_t)((mb + mt * 16 + a_r) * PADB +
                                              (ks * 16 + a_c) * 2);
                LDSM_X4(ah[mt][0], ah[mt][1], ah[mt][2], ah[mt][3], ao);
            }
            #pragma unroll
            for (int nt = 0; nt < 4; nt++) {
                uint32_t bo = (uint32_t)((nb + nt * 8 + b_r) * PADB +
                                         (ks * 16 + b_c) * 2);
                uint32_t bv[2];
                LDSM_X2(bv[0], bv[1], Ks + bo);
                #pragma unroll
                for (int mt = 0; mt < 2; mt++)
                    MMA16816H(accS[mt][nt], ah[mt], bv);
            }
        }

        // exp + mask; P packed to fp16 A fragments
        uint32_t aP[2][2][4];
        #pragma unroll
        for (int mt = 0; mt < 2; mt++) {
            #pragma unroll
            for (int nt = 0; nt < 4; nt++) {
                int c0i = nb + nt * 8 + (lane & 3) * 2;
                float m0v = (k0 + c0i     < cnt) ? 1.f : 0.f;
                float m1v = (k0 + c0i + 1 < cnt) ? 1.f : 0.f;
                #pragma unroll
                for (int h2 = 0; h2 < 2; h2++) {
                    float p0 = __expf(accS[mt][nt][h2 * 2 + 0]) * m0v;
                    float p1 = __expf(accS[mt][nt][h2 * 2 + 1]) * m1v;
                    denA[mt][h2] += p0 + p1;
                    aP[mt][nt >> 1][(nt & 1) * 2 + h2] = pack_h2(p0, p1);
                }
            }
        }

        // O += P·V (fp16, 1 MMA), this warp's 32 keys, full d=64
        #pragma unroll
        for (int kt = 0; kt < 2; kt++) {
            #pragma unroll
            for (int dt = 0; dt < 8; dt++) {
                uint32_t bo = (uint32_t)((nb + kt * 16 + t_r) * PADB + dt * 16);
                uint32_t bv[2];
                LDSM_X2_T(bv[0], bv[1], Vs + bo);
                #pragma unroll
                for (int mt = 0; mt < 2; mt++)
                    MMA16816H(accO[mt][dt], aP[mt][kt], bv);
            }
        }
    }

    // denom: quad-reduce then smem atomics
    #pragma unroll
    for (int mt = 0; mt < 2; mt++)
        #pragma unroll
        for (int h2 = 0; h2 < 2; h2++) {
            float v = denA[mt][h2];
            v += __shfl_xor_sync(0xffffffffu, v, 1);
            v += __shfl_xor_sync(0xffffffffu, v, 2);
            if ((lane & 3) == 0)
                atomicAdd(&denom_s[mb + mt * 16 + h2 * 8 + (lane >> 2)], v);
        }
    __syncthreads();

    // cross-pair O reduction: wn=1 stores to REDBUF (overlaid on stage area)
    float* red = (float*)(sm + SM_RED);
    if (wn == 1) {
        #pragma unroll
        for (int mt = 0; mt < 2; mt++) {
            const int r = mb + mt * 16 + (lane >> 2);
            #pragma unroll
            for (int dt = 0; dt < 8; dt++) {
                const int cc = dt * 8 + (lane & 3) * 2;
                *(float2*)&red[(size_t)r * 64 + cc] =
                    make_float2(accO[mt][dt][0], accO[mt][dt][1]);
                *(float2*)&red[(size_t)(r + 8) * 64 + cc] =
                    make_float2(accO[mt][dt][2], accO[mt][dt][3]);
            }
        }
    }
    __syncthreads();

    // wn=0 finalizes: add pair partial, divide, single-fp16 store
    if (wn == 0) {
        #pragma unroll
        for (int mt = 0; mt < 2; mt++) {
            const int r = mb + mt * 16 + (lane >> 2);
            const float inv0 = 1.0f / denom_s[r];
            const float inv1 = 1.0f / denom_s[r + 8];
            const size_t row0 = (size_t)(b * NN + q0 + r) * CC + h * HD;
            const size_t row1 = (size_t)(b * NN + q0 + r + 8) * CC + h * HD;
            #pragma unroll
            for (int dt = 0; dt < 8; dt++) {
                const int cc = dt * 8 + (lane & 3) * 2;
                float2 pr0 = *(float2*)&red[(size_t)r * 64 + cc];
                float2 pr1 = *(float2*)&red[(size_t)(r + 8) * 64 + cc];
                float v0 = (accO[mt][dt][0] + pr0.x) * inv0;
                float v1 = (accO[mt][dt][1] + pr0.y) * inv0;
                float v2 = (accO[mt][dt][2] + pr1.x) * inv1;
                float v3 = (accO[mt][dt][3] + pr1.y) * inv1;
                *(uint32_t*)((char*)aout + (row0 + cc) * 2) = pack_h2(v0, v1);
                *(uint32_t*)((char*)aout + (row1 + cc) * 2) = pack_h2(v2, v3);
            }
        }
    }
}

// ---------------------------------------------------------------------------
extern "C" void kernel_launch(void* const* d_in, const int* in_sizes, int n_in,
                              void* d_out, int out_size)
{
    const float* x      = (const float*)d_in[0];
    const int*   mask   = (const int*)  d_in[1];
    const float* w_qkv  = (const float*)d_in[2];
    const float* w_proj = (const float*)d_in[3];
    const float* b_proj = (const float*)d_in[4];
    float* out = (float*)d_out;

    __half *xh, *wqhi, *wqlo, *wphi, *wplo, *ah, *qh, *kh, *vh;
    int *kidx, *kcnt;
    cudaGetSymbolAddress((void**)&xh, g_xh);
    cudaGetSymbolAddress((void**)&wqhi, g_wqhi);
    cudaGetSymbolAddress((void**)&wqlo, g_wqlo);
    cudaGetSymbolAddress((void**)&wphi, g_wphi);
    cudaGetSymbolAddress((void**)&wplo, g_wplo);
    cudaGetSymbolAddress((void**)&ah, g_ah);
    cudaGetSymbolAddress((void**)&qh, g_qh);
    cudaGetSymbolAddress((void**)&kh, g_kh);
    cudaGetSymbolAddress((void**)&vh, g_vh);
    cudaGetSymbolAddress((void**)&kidx, g_kidx);
    cudaGetSymbolAddress((void**)&kcnt, g_kcnt);

    cudaFuncSetAttribute(gemm_proj, cudaFuncAttributeMaxDynamicSharedMemorySize, GEMM_SMEM);
    cudaFuncSetAttribute(qkv_fused, cudaFuncAttributeMaxDynamicSharedMemorySize, GEMM_SMEM);
    cudaFuncSetAttribute(attn_mma, cudaFuncAttributeMaxDynamicSharedMemorySize, ATTN_SMEM);

    // 0) fused pre-pass
    prep_all<<<PREP_TOTAL, 256>>>(x, mask, w_qkv, w_proj,
                                  xh, wqhi, wqlo, wphi, wplo, kidx, kcnt);

    // 1) fused Q + KV GEMM (MT1, 1152 blocks)
    qkv_fused<<<1152, 256, GEMM_SMEM>>>(
        (const uint4*)xh, (const uint4*)wqhi, (const uint4*)wqlo,
        kidx, kcnt, qh, kh, vh);

    // 2) tensor-core attention over packed keys (all-fp16)
    attn_mma<<<dim3(NN / QT, HH, BB), 256, ATTN_SMEM>>>(
        (const uint4*)qh, (const uint4*)kh, (const uint4*)vh, kcnt, ah);

    // 3) projection GEMM (MT1, 384 blocks) + bias
    gemm_proj<<<dim3(CC / 128, BN / 64), 256, GEMM_SMEM>>>(
        (const uint4*)ah, (const uint4*)wphi, (const uint4*)wplo, out, b_proj);
}

// round 12
// speedup vs baseline: 9.9142x; 1.3032x over previous
#include <cuda_runtime.h>
#include <cuda_bf16.h>
#include <cuda_fp16.h>
#include <cstdint>
#include <cstddef>

#define BB 2
#define NN 2048
#define CC 768
#define HH 12
#define HD 64
#define BN (BB * NN)          // 4096
#define QKVC (3 * CC)         // 2304

// ---------------------------------------------------------------------------
// Scratch (device globals — no allocation allowed anywhere)
// ---------------------------------------------------------------------------
__device__ __align__(16) __half g_xh [(size_t)BN * CC];           // x fp16
__device__ __align__(16) __half g_wq [(size_t)QKVC * CC];         // Wqkv^T fp16
__device__ __align__(16) __half g_wp [(size_t)CC * CC];           // Wproj^T fp16
__device__ __align__(16) __half g_ah [(size_t)BN * CC];           // attn out fp16
// attention operands: [b][h][token][64] row-major, single fp16
__device__ __align__(16) __half g_qh[(size_t)BB * HH * NN * HD];
__device__ __align__(16) __half g_kh[(size_t)BB * HH * NN * HD];
__device__ __align__(16) __half g_vh[(size_t)BB * HH * NN * HD];
__device__ int g_kidx[BB * NN];
__device__ int g_kcnt[BB];

// ---------------------------------------------------------------------------
// PTX helpers (family-common; ptxas target is sm_103 w/o 'a')
// ---------------------------------------------------------------------------
__device__ __forceinline__ uint32_t smem_u32(const void* p) {
    uint32_t a;
    asm("{ .reg .u64 t; cvta.to.shared.u64 t, %1; cvt.u32.u64 %0, t; }"
        : "=r"(a) : "l"(p));
    return a;
}
#define CP_ASYNC16(dst, src) \
    asm volatile("cp.async.cg.shared.global [%0], [%1], 16;" :: "r"(dst), "l"(src))
#define CP_COMMIT() asm volatile("cp.async.commit_group;" ::: "memory")
#define CP_WAIT(n)  asm volatile("cp.async.wait_group %0;" :: "n"(n) : "memory")

#define LDSM_X4(r0, r1, r2, r3, addr)                                          \
    asm volatile("ldmatrix.sync.aligned.m8n8.x4.shared.b16 {%0,%1,%2,%3}, [%4];" \
                 : "=r"(r0), "=r"(r1), "=r"(r2), "=r"(r3) : "r"(addr))
#define LDSM_X2(r0, r1, addr)                                                  \
    asm volatile("ldmatrix.sync.aligned.m8n8.x2.shared.b16 {%0,%1}, [%2];"     \
                 : "=r"(r0), "=r"(r1) : "r"(addr))
#define LDSM_X2_T(r0, r1, addr)                                                \
    asm volatile("ldmatrix.sync.aligned.m8n8.x2.trans.shared.b16 {%0,%1}, [%2];" \
                 : "=r"(r0), "=r"(r1) : "r"(addr))

#define MMA16816H(d, a, b)                                                     \
    asm volatile("mma.sync.aligned.m16n8k16.row.col.f32.f16.f16.f32 "          \
                 "{%0,%1,%2,%3}, {%4,%5,%6,%7}, {%8,%9}, {%0,%1,%2,%3};"       \
                 : "+f"((d)[0]), "+f"((d)[1]), "+f"((d)[2]), "+f"((d)[3])      \
                 : "r"((a)[0]), "r"((a)[1]), "r"((a)[2]), "r"((a)[3]),         \
                   "r"((b)[0]), "r"((b)[1]))

__device__ __forceinline__ uint32_t pack_h2(float v0, float v1) {
    __half2 h = __floats2half2_rn(v0, v1);
    return *(uint32_t*)&h;
}

// ---------------------------------------------------------------------------
// MT1 fp16 GEMM pieces: 64x128 tile, 8 warps (4M x 2N), warp tile 16x64,
// K-chunk 32, double-buffered. A and B single fp16 (1 MMA per tile).
// ---------------------------------------------------------------------------
#define RS 40
#define MAT_A  (64 * RS * 2)            // 5120
#define MAT_B  (128 * RS * 2)           // 10240
#define STAGE_P (MAT_A + MAT_B)         // 15360
#define GEMM_SMEM (2 * STAGE_P)         // 30720

#define MT1_DECLS                                                              \
    extern __shared__ char smem[];                                             \
    const uint32_t sb = smem_u32(smem);                                        \
    const int tid = threadIdx.x, wid = tid >> 5, lane = tid & 31;              \
    const int wm = wid >> 1, wn = wid & 1;                                     \
    const int m_base = wm * 16, n_base = wn * 64;                              \
    const int a_r = (lane & 15);                                               \
    const int a_c = (lane >> 4) * 8;                                           \
    const int b_r = (lane & 7);                                                \
    const int b_c = ((lane >> 3) & 1) * 8;

#define MT1_MAINLOOP(NCH)                                                      \
    for (int c = 0; c < (NCH); c++) {                                          \
        const int s = c & 1;                                                   \
        if (c + 1 < (NCH)) { prefetch(c + 1, 1 - s); CP_COMMIT(); CP_WAIT(1); }\
        else { CP_WAIT(0); }                                                   \
        __syncthreads();                                                       \
        const uint32_t As = sb + s * STAGE_P;                                  \
        const uint32_t Bs = As + MAT_A;                                        \
        _Pragma("unroll")                                                      \
        for (int kk = 0; kk < 2; kk++) {                                       \
            uint32_t ah[4];                                                    \
            const uint32_t ao =                                                \
                (uint32_t)((m_base + a_r) * (RS * 2) + (kk * 16 + a_c) * 2);   \
            LDSM_X4(ah[0], ah[1], ah[2], ah[3], As + ao);                      \
            _Pragma("unroll")                                                  \
            for (int nt = 0; nt < 8; nt++) {                                   \
                const uint32_t bo =                                            \
                    (uint32_t)((n_base + nt * 8 + b_r) * (RS * 2) +            \
                               (kk * 16 + b_c) * 2);                           \
                uint32_t bh[2];                                                \
                LDSM_X2(bh[0], bh[1], Bs + bo);                                \
                MMA16816H(acc[nt], ah, bh);                                    \
            }                                                                  \
        }                                                                      \
        __syncthreads();                                                       \
    }

// B prefetch: 128 rows x 4 chunks = 512 cp.async over 256 threads (2 iters)
#define MT1_PREFETCH_B(stage, Bp, n0, c)                                       \
    _Pragma("unroll")                                                          \
    for (int it = 0; it < 2; it++) {                                           \
        const int idx = it * 256 + tid;                                        \
        const int rb = idx >> 2, qb = idx & 3;                                 \
        CP_ASYNC16((stage) + MAT_A + (uint32_t)(rb * (RS * 2) + qb * 16),      \
                   (Bp) + (size_t)((n0) + rb) * 96 + (c) * 4 + qb);            \
    }

// ---------------------------------------------------------------------------
// Proj GEMM: out[4096,768] = A(fp16)·Wp^T(fp16) + bias. Grid (6, 64).
// ---------------------------------------------------------------------------
__global__ __launch_bounds__(256) void gemm_proj(
    const uint4* __restrict__ Ah, const uint4* __restrict__ Bp,
    float* __restrict__ C, const float* __restrict__ bias)
{
    MT1_DECLS
    const int m0 = blockIdx.y * 64, n0 = blockIdx.x * 128;
    const int nch = CC >> 5;             // 24

    auto prefetch = [&](int c, int s) {
        const uint32_t stage = sb + s * STAGE_P;
        const int r = tid >> 2, q = tid & 3;
        CP_ASYNC16(stage + (uint32_t)(r * (RS * 2) + q * 16),
                   Ah + (size_t)(m0 + r) * 96 + c * 4 + q);
        MT1_PREFETCH_B(stage, Bp, n0, c)
    };

    float acc[8][4] = {};
    prefetch(0, 0);
    CP_COMMIT();
    MT1_MAINLOOP(nch)

    const int row0 = m0 + m_base + (lane >> 2);
    #pragma unroll
    for (int nt = 0; nt < 8; nt++) {
        const int col = n0 + n_base + nt * 8 + (lane & 3) * 2;
        float b0 = bias[col], b1 = bias[col + 1];
        float2 v0 = { acc[nt][0] + b0, acc[nt][1] + b1 };
        float2 v1 = { acc[nt][2] + b0, acc[nt][3] + b1 };
        *(float2*)(C + (size_t)row0 * CC + col) = v0;
        *(float2*)(C + (size_t)(row0 + 8) * CC + col) = v1;
    }
}

// ---------------------------------------------------------------------------
// Fused QKV GEMM (MT1): blocks [0,384) Q; [384,1152) packed K/V.
// ---------------------------------------------------------------------------
__global__ __launch_bounds__(256) void qkv_fused(
    const uint4* __restrict__ Xh, const uint4* __restrict__ Wq,
    const int* __restrict__ kidx, const int* __restrict__ kcnt,
    __half* __restrict__ qh, __half* __restrict__ kh, __half* __restrict__ vh)
{
    MT1_DECLS
    const int bid = blockIdx.x;
    const int nch = CC >> 5;             // 24

    if (bid < 384) {
        // ------------------- Q role -------------------
        const int m0 = (bid / 6) * 64, n0 = (bid % 6) * 128;
        auto prefetch = [&](int c, int s) {
            const uint32_t stage = sb + s * STAGE_P;
            const int r = tid >> 2, q = tid & 3;
            CP_ASYNC16(stage + (uint32_t)(r * (RS * 2) + q * 16),
                       Xh + (size_t)(m0 + r) * 96 + c * 4 + q);
            MT1_PREFETCH_B(stage, Wq, n0, c)
        };
        float acc[8][4] = {};
        prefetch(0, 0);
        CP_COMMIT();
        MT1_MAINLOOP(nch)

        #pragma unroll
        for (int h2 = 0; h2 < 2; h2++) {
            const int r = m0 + m_base + h2 * 8 + (lane >> 2);
            const int b = r >> 11, n = r & (NN - 1);
            #pragma unroll
            for (int nt = 0; nt < 8; nt++) {
                const int c = n0 + n_base + nt * 8 + (lane & 3) * 2;
                const int h = c >> 6, d = c & 63;
                const size_t o = (((size_t)b * HH + h) * NN + n) * HD + d;
                *(uint32_t*)((char*)qh + o * 2) =
                    pack_h2(acc[nt][h2 * 2] * 0.125f,
                            acc[nt][h2 * 2 + 1] * 0.125f);
            }
        }
    } else {
        // ------------------- KV role (packed tokens) -------------------
        const int idx0 = bid - 384;
        const int bz = idx0 / 384;
        const int rr2 = idx0 % 384;
        const int m0 = (rr2 / 12) * 64;
        const int n0 = (rr2 % 12) * 128;
        const int cnt = kcnt[bz];
        const int pad = (cnt + 63) & ~63;
        if (m0 >= pad) return;

        const uint4* Bp = Wq + (size_t)CC * CC / 8;  // wq rows [768,2304)

        const int pr = tid >> 2, pq = tid & 3;
        const int j1 = m0 + pr;
        const int s1 = (j1 < cnt) ? kidx[bz * NN + j1] : 0;

        auto prefetch = [&](int c, int s) {
            const uint32_t stage = sb + s * STAGE_P;
            CP_ASYNC16(stage + (uint32_t)(pr * (RS * 2) + pq * 16),
                       Xh + (size_t)(bz * NN + s1) * 96 + c * 4 + pq);
            MT1_PREFETCH_B(stage, Bp, n0, c)
        };
        float acc[8][4] = {};
        prefetch(0, 0);
        CP_COMMIT();
        MT1_MAINLOOP(nch)

        #pragma unroll
        for (int h2 = 0; h2 < 2; h2++) {
            const int j = m0 + m_base + h2 * 8 + (lane >> 2);
            #pragma unroll
            for (int nt = 0; nt < 8; nt++) {
                const int c = n0 + n_base + nt * 8 + (lane & 3) * 2;
                const int isV = c >= CC;
                const int cc = isV ? c - CC : c;
                const int h = cc >> 6, d = cc & 63;
                const size_t o = (((size_t)bz * HH + h) * NN + j) * HD + d;
                __half* dst = isV ? vh : kh;
                *(uint32_t*)((char*)dst + o * 2) =
                    pack_h2(acc[nt][h2 * 2], acc[nt][h2 * 2 + 1]);
            }
        }
    }
}

// ---------------------------------------------------------------------------
// Fused pre-pass: [x->fp16][transpose wqkv->fp16][transpose wproj->fp16][scan]
// ---------------------------------------------------------------------------
#define PREP_SPLIT (BN * CC / 256)          // 12288
#define PREP_TQ (72 * 24)                   // 1728
#define PREP_TP (24 * 24)                   // 576
#define PREP_TOTAL (PREP_SPLIT + PREP_TQ + PREP_TP + BB)

__global__ __launch_bounds__(256) void prep_all(
    const float* __restrict__ x, const int* __restrict__ mask,
    const float* __restrict__ w_qkv, const float* __restrict__ w_proj,
    __half* __restrict__ xh, __half* __restrict__ wq, __half* __restrict__ wp,
    int* __restrict__ kidx, int* __restrict__ kcnt)
{
    __shared__ float tbuf[32][33];
    __shared__ int part[256];
    const int bid = blockIdx.x, tid = threadIdx.x;

    if (bid < PREP_SPLIT) {
        const int i = bid * 256 + tid;
        xh[i] = __float2half_rn(x[i]);
    } else if (bid < PREP_SPLIT + PREP_TQ + PREP_TP) {
        const bool isQ = bid < PREP_SPLIT + PREP_TQ;
        const int t = isQ ? bid - PREP_SPLIT : bid - (PREP_SPLIT + PREP_TQ);
        const float* W = isQ ? w_qkv : w_proj;
        __half* dst = isQ ? wq : wp;
        const int N = isQ ? QKVC : CC;
        const int nblk = N / 32;
        const int n0 = (t % nblk) * 32, k0 = (t / nblk) * 32;
        const int tx = tid & 31, ty = tid >> 5;
        #pragma unroll
        for (int j = 0; j < 4; j++)
            tbuf[ty + 8 * j][tx] = W[(size_t)(k0 + ty + 8 * j) * N + n0 + tx];
        __syncthreads();
        #pragma unroll
        for (int j = 0; j < 4; j++) {
            const int nl = ty + 8 * j;
            dst[(size_t)(n0 + nl) * CC + k0 + tx] = __float2half_rn(tbuf[tx][nl]);
        }
    } else {
        const int b = bid - (PREP_SPLIT + PREP_TQ + PREP_TP);
        const int* m = mask + b * NN;
        int loc[8], c = 0;
        #pragma unroll
        for (int i = 0; i < 8; i++) { loc[i] = c; c += m[tid * 8 + i]; }
        part[tid] = c;
        __syncthreads();
        for (int off = 1; off < 256; off <<= 1) {
            int v = (tid >= off) ? part[tid - off] : 0;
            __syncthreads();
            part[tid] += v;
            __syncthreads();
        }
        int excl = part[tid] - c;
        #pragma unroll
        for (int i = 0; i < 8; i++)
            if (m[tid * 8 + i]) kidx[b * NN + excl + loc[i]] = tid * 8 + i;
        if (tid == 255) kcnt[b] = part[255];
    }
}

// ---------------------------------------------------------------------------
// Tensor-core attention: Q/K/V single fp16 (S 1 MMA, PV 1 MMA),
// P-in-registers, cross-pair O reduction through smem.
// ---------------------------------------------------------------------------
#define QT 128
#define KT 64
#define PADB 144                 // 72 x 16-bit per row
#define SM_STG  18432            // after Q resident
#define STG_SZ  18432            // K 9216 + V 9216
#define SM_RED  18432            // overlaid on stage area (post-loop only)
#define SM_DEN  55296
#define ATTN_SMEM (55296 + 512)

__global__ __launch_bounds__(256) void attn_mma(
    const uint4* __restrict__ Qh, const uint4* __restrict__ Kh,
    const uint4* __restrict__ Vh, const int* __restrict__ kcnt,
    __half* __restrict__ aout)
{
    extern __shared__ char sm[];
    const uint32_t sb = smem_u32(sm);
    const int b = blockIdx.z, h = blockIdx.y, q0 = blockIdx.x * QT;
    const int tid = threadIdx.x, wid = tid >> 5, lane = tid & 31;
    const int wm = wid >> 1, wn = wid & 1;
    const int mb = wm * 32, nb = wn * 32;
    const int cnt = kcnt[b];
    const int ntiles = (cnt + KT - 1) / KT;
    const size_t bh = (size_t)b * HH + h;

    float* denom_s = (float*)(sm + SM_DEN);
    if (tid < 128) denom_s[tid] = 0.0f;

    // resident Q tile (single fp16)
    #pragma unroll
    for (int it = 0; it < 4; it++) {
        int idx = it * 256 + tid;
        int r = idx >> 3, c = idx & 7;
        *(uint4*)(sm + r * PADB + c * 16) = Qh[(bh * NN + q0 + r) * 8 + c];
    }

    auto prefetch = [&](int t, int s) {
        const uint32_t stg = sb + SM_STG + s * STG_SZ;
        const int k0 = t * KT;
        #pragma unroll
        for (int it = 0; it < 4; it++) {
            int idx = it * 256 + tid;
            int mat = idx >> 9;                // 0 K, 1 V
            int r = (idx >> 3) & 63, c = idx & 7;
            uint32_t dst = stg + mat * 9216 + (uint32_t)(r * PADB + c * 16);
            const uint4* g = (mat == 0) ? Kh : Vh;
            CP_ASYNC16(dst, g + (bh * NN + k0 + r) * 8 + c);
        }
    };

    float accO[2][8][4] = {};
    float denA[2][2] = {};

    const int a_r = lane & 15, a_c = (lane >> 4) * 8;
    const int b_r = lane & 7,  b_c = ((lane >> 3) & 1) * 8;
    const int t_r = lane & 15;

    prefetch(0, 0);
    CP_COMMIT();

    for (int t = 0; t < ntiles; t++) {
        const int s = t & 1;
        const int k0 = t * KT;
        CP_WAIT(0);
        __syncthreads();
        if (t + 1 < ntiles) { prefetch(t + 1, 1 - s); CP_COMMIT(); }

        const uint32_t Ks = sb + SM_STG + s * STG_SZ;
        const uint32_t Vs = Ks + 9216;

        // S = Q K^T over this warp's 32q x 32k (fp16, 1 MMA)
        float accS[2][4][4] = {};
        #pragma unroll
        for (int ks = 0; ks < 4; ks++) {
            uint32_t ah[2][4];
            #pragma unroll
            for (int mt = 0; mt < 2; mt++) {
                uint32_t ao = sb + (uint32_t)((mb + mt * 16 + a_r) * PADB +
                                              (ks * 16 + a_c) * 2);
                LDSM_X4(ah[mt][0], ah[mt][1], ah[mt][2], ah[mt][3], ao);
            }
            #pragma unroll
            for (int nt = 0; nt < 4; nt++) {
                uint32_t bo = (uint32_t)((nb + nt * 8 + b_r) * PADB +
                                         (ks * 16 + b_c) * 2);
                uint32_t bv[2];
                LDSM_X2(bv[0], bv[1], Ks + bo);
                #pragma unroll
                for (int mt = 0; mt < 2; mt++)
                    MMA16816H(accS[mt][nt], ah[mt], bv);
            }
        }

        // exp + mask; P packed to fp16 A fragments
        uint32_t aP[2][2][4];
        #pragma unroll
        for (int mt = 0; mt < 2; mt++) {
            #pragma unroll
            for (int nt = 0; nt < 4; nt++) {
                int c0i = nb + nt * 8 + (lane & 3) * 2;
                float m0v = (k0 + c0i     < cnt) ? 1.f : 0.f;
                float m1v = (k0 + c0i + 1 < cnt) ? 1.f : 0.f;
                #pragma unroll
                for (int h2 = 0; h2 < 2; h2++) {
                    float p0 = __expf(accS[mt][nt][h2 * 2 + 0]) * m0v;
                    float p1 = __expf(accS[mt][nt][h2 * 2 + 1]) * m1v;
                    denA[mt][h2] += p0 + p1;
                    aP[mt][nt >> 1][(nt & 1) * 2 + h2] = pack_h2(p0, p1);
                }
            }
        }

        // O += P·V (fp16, 1 MMA), this warp's 32 keys, full d=64
        #pragma unroll
        for (int kt = 0; kt < 2; kt++) {
            #pragma unroll
            for (int dt = 0; dt < 8; dt++) {
                uint32_t bo = (uint32_t)((nb + kt * 16 + t_r) * PADB + dt * 16);
                uint32_t bv[2];
                LDSM_X2_T(bv[0], bv[1], Vs + bo);
                #pragma unroll
                for (int mt = 0; mt < 2; mt++)
                    MMA16816H(accO[mt][dt], aP[mt][kt], bv);
            }
        }
    }

    // denom: quad-reduce then smem atomics
    #pragma unroll
    for (int mt = 0; mt < 2; mt++)
        #pragma unroll
        for (int h2 = 0; h2 < 2; h2++) {
            float v = denA[mt][h2];
            v += __shfl_xor_sync(0xffffffffu, v, 1);
            v += __shfl_xor_sync(0xffffffffu, v, 2);
            if ((lane & 3) == 0)
                atomicAdd(&denom_s[mb + mt * 16 + h2 * 8 + (lane >> 2)], v);
        }
    __syncthreads();

    // cross-pair O reduction: wn=1 stores to REDBUF (overlaid on stage area)
    float* red = (float*)(sm + SM_RED);
    if (wn == 1) {
        #pragma unroll
        for (int mt = 0; mt < 2; mt++) {
            const int r = mb + mt * 16 + (lane >> 2);
            #pragma unroll
            for (int dt = 0; dt < 8; dt++) {
                const int cc = dt * 8 + (lane & 3) * 2;
                *(float2*)&red[(size_t)r * 64 + cc] =
                    make_float2(accO[mt][dt][0], accO[mt][dt][1]);
                *(float2*)&red[(size_t)(r + 8) * 64 + cc] =
                    make_float2(accO[mt][dt][2], accO[mt][dt][3]);
            }
        }
    }
    __syncthreads();

    // wn=0 finalizes: add pair partial, divide, single-fp16 store
    if (wn == 0) {
        #pragma unroll
        for (int mt = 0; mt < 2; mt++) {
            const int r = mb + mt * 16 + (lane >> 2);
            const float inv0 = 1.0f / denom_s[r];
            const float inv1 = 1.0f / denom_s[r + 8];
            const size_t row0 = (size_t)(b * NN + q0 + r) * CC + h * HD;
            const size_t row1 = (size_t)(b * NN + q0 + r + 8) * CC + h * HD;
            #pragma unroll
            for (int dt = 0; dt < 8; dt++) {
                const int cc = dt * 8 + (lane & 3) * 2;
                float2 pr0 = *(float2*)&red[(size_t)r * 64 + cc];
                float2 pr1 = *(float2*)&red[(size_t)(r + 8) * 64 + cc];
                float v0 = (accO[mt][dt][0] + pr0.x) * inv0;
                float v1 = (accO[mt][dt][1] + pr0.y) * inv0;
                float v2 = (accO[mt][dt][2] + pr1.x) * inv1;
                float v3 = (accO[mt][dt][3] + pr1.y) * inv1;
                *(uint32_t*)((char*)aout + (row0 + cc) * 2) = pack_h2(v0, v1);
                *(uint32_t*)((char*)aout + (row1 + cc) * 2) = pack_h2(v2, v3);
            }
        }
    }
}

// ---------------------------------------------------------------------------
extern "C" void kernel_launch(void* const* d_in, const int* in_sizes, int n_in,
                              void* d_out, int out_size)
{
    const float* x      = (const float*)d_in[0];
    const int*   mask   = (const int*)  d_in[1];
    const float* w_qkv  = (const float*)d_in[2];
    const float* w_proj = (const float*)d_in[3];
    const float* b_proj = (const float*)d_in[4];
    float* out = (float*)d_out;

    __half *xh, *wq, *wp, *ah, *qh, *kh, *vh;
    int *kidx, *kcnt;
    cudaGetSymbolAddress((void**)&xh, g_xh);
    cudaGetSymbolAddress((void**)&wq, g_wq);
    cudaGetSymbolAddress((void**)&wp, g_wp);
    cudaGetSymbolAddress((void**)&ah, g_ah);
    cudaGetSymbolAddress((void**)&qh, g_qh);
    cudaGetSymbolAddress((void**)&kh, g_kh);
    cudaGetSymbolAddress((void**)&vh, g_vh);
    cudaGetSymbolAddress((void**)&kidx, g_kidx);
    cudaGetSymbolAddress((void**)&kcnt, g_kcnt);

    cudaFuncSetAttribute(gemm_proj, cudaFuncAttributeMaxDynamicSharedMemorySize, GEMM_SMEM);
    cudaFuncSetAttribute(qkv_fused, cudaFuncAttributeMaxDynamicSharedMemorySize, GEMM_SMEM);
    cudaFuncSetAttribute(attn_mma, cudaFuncAttributeMaxDynamicSharedMemorySize, ATTN_SMEM);

    // 0) fused pre-pass
    prep_all<<<PREP_TOTAL, 256>>>(x, mask, w_qkv, w_proj, xh, wq, wp, kidx, kcnt);

    // 1) fused Q + KV GEMM (MT1, 1152 blocks, single-fp16 weights)
    qkv_fused<<<1152, 256, GEMM_SMEM>>>(
        (const uint4*)xh, (const uint4*)wq, kidx, kcnt, qh, kh, vh);

    // 2) tensor-core attention over packed keys (all-fp16)
    attn_mma<<<dim3(NN / QT, HH, BB), 256, ATTN_SMEM>>>(
        (const uint4*)qh, (const uint4*)kh, (const uint4*)vh, kcnt, ah);

    // 3) projection GEMM (MT1, 384 blocks, single-fp16 weights) + bias
    gemm_proj<<<dim3(CC / 128, BN / 64), 256, GEMM_SMEM>>>(
        (const uint4*)ah, (const uint4*)wp, out, b_proj);
}

// round 13
// speedup vs baseline: 10.5424x; 1.0634x over previous
#include <cuda_runtime.h>
#include <cuda_bf16.h>
#include <cuda_fp16.h>
#include <cstdint>
#include <cstddef>

#define BB 2
#define NN 2048
#define CC 768
#define HH 12
#define HD 64
#define BN (BB * NN)          // 4096
#define QKVC (3 * CC)         // 2304

// ---------------------------------------------------------------------------
// Scratch (device globals — no allocation allowed anywhere)
// ---------------------------------------------------------------------------
__device__ __align__(16) __half g_xh [(size_t)BN * CC];           // x fp16
__device__ __align__(16) __half g_wq [(size_t)QKVC * CC];         // Wqkv^T fp16
__device__ __align__(16) __half g_wp [(size_t)CC * CC];           // Wproj^T fp16
__device__ __align__(16) __half g_ah [(size_t)BN * CC];           // attn out fp16
// attention operands: [b][h][token][64] row-major, single fp16
__device__ __align__(16) __half g_qh[(size_t)BB * HH * NN * HD];
__device__ __align__(16) __half g_kh[(size_t)BB * HH * NN * HD];
__device__ __align__(16) __half g_vh[(size_t)BB * HH * NN * HD];
__device__ int g_kidx[BB * NN];
__device__ int g_kcnt[BB];

// ---------------------------------------------------------------------------
// PTX helpers (family-common; ptxas target is sm_103 w/o 'a')
// ---------------------------------------------------------------------------
__device__ __forceinline__ uint32_t smem_u32(const void* p) {
    uint32_t a;
    asm("{ .reg .u64 t; cvta.to.shared.u64 t, %1; cvt.u32.u64 %0, t; }"
        : "=r"(a) : "l"(p));
    return a;
}
#define CP_ASYNC16(dst, src) \
    asm volatile("cp.async.cg.shared.global [%0], [%1], 16;" :: "r"(dst), "l"(src))
#define CP_COMMIT() asm volatile("cp.async.commit_group;" ::: "memory")
#define CP_WAIT(n)  asm volatile("cp.async.wait_group %0;" :: "n"(n) : "memory")

#define LDSM_X4(r0, r1, r2, r3, addr)                                          \
    asm volatile("ldmatrix.sync.aligned.m8n8.x4.shared.b16 {%0,%1,%2,%3}, [%4];" \
                 : "=r"(r0), "=r"(r1), "=r"(r2), "=r"(r3) : "r"(addr))
#define LDSM_X4_T(r0, r1, r2, r3, addr)                                        \
    asm volatile("ldmatrix.sync.aligned.m8n8.x4.trans.shared.b16 {%0,%1,%2,%3}, [%4];" \
                 : "=r"(r0), "=r"(r1), "=r"(r2), "=r"(r3) : "r"(addr))

#define MMA16816H(d, a, b)                                                     \
    asm volatile("mma.sync.aligned.m16n8k16.row.col.f32.f16.f16.f32 "          \
                 "{%0,%1,%2,%3}, {%4,%5,%6,%7}, {%8,%9}, {%0,%1,%2,%3};"       \
                 : "+f"((d)[0]), "+f"((d)[1]), "+f"((d)[2]), "+f"((d)[3])      \
                 : "r"((a)[0]), "r"((a)[1]), "r"((a)[2]), "r"((a)[3]),         \
                   "r"((b)[0]), "r"((b)[1]))

__device__ __forceinline__ uint32_t pack_h2(float v0, float v1) {
    __half2 h = __floats2half2_rn(v0, v1);
    return *(uint32_t*)&h;
}

// ---------------------------------------------------------------------------
// MT1 fp16 GEMM pieces: 64x128 tile, 8 warps (4M x 2N), warp tile 16x64,
// K-chunk 32, double-buffered. A,B single fp16. B loads via paired X4.
// ---------------------------------------------------------------------------
#define RS 40
#define MAT_A  (64 * RS * 2)            // 5120
#define MAT_B  (128 * RS * 2)           // 10240
#define STAGE_P (MAT_A + MAT_B)         // 15360
#define GEMM_SMEM (2 * STAGE_P)         // 30720

#define MT1_DECLS                                                              \
    extern __shared__ char smem[];                                             \
    const uint32_t sb = smem_u32(smem);                                        \
    const int tid = threadIdx.x, wid = tid >> 5, lane = tid & 31;              \
    const int wm = wid >> 1, wn = wid & 1;                                     \
    const int m_base = wm * 16, n_base = wn * 64;                              \
    const int a_r = (lane & 15);                                               \
    const int a_c = (lane >> 4) * 8;                                           \
    /* paired-B X4 lane addressing: lanes 0-15 -> nt, 16-31 -> nt+1 */         \
    const int b4_r = ((lane >> 4) << 3) + (lane & 7);                          \
    const int b4_c = ((lane >> 3) & 1) * 8;

#define MT1_MAINLOOP(NCH)                                                      \
    for (int c = 0; c < (NCH); c++) {                                          \
        const int s = c & 1;                                                   \
        if (c + 1 < (NCH)) { prefetch(c + 1, 1 - s); CP_COMMIT(); CP_WAIT(1); }\
        else { CP_WAIT(0); }                                                   \
        __syncthreads();                                                       \
        const uint32_t As = sb + s * STAGE_P;                                  \
        const uint32_t Bs = As + MAT_A;                                        \
        _Pragma("unroll")                                                      \
        for (int kk = 0; kk < 2; kk++) {                                       \
            uint32_t ah[4];                                                    \
            const uint32_t ao =                                                \
                (uint32_t)((m_base + a_r) * (RS * 2) + (kk * 16 + a_c) * 2);   \
            LDSM_X4(ah[0], ah[1], ah[2], ah[3], As + ao);                      \
            _Pragma("unroll")                                                  \
            for (int nt2 = 0; nt2 < 4; nt2++) {                                \
                const uint32_t bo =                                            \
                    (uint32_t)((n_base + nt2 * 16 + b4_r) * (RS * 2) +         \
                               (kk * 16 + b4_c) * 2);                          \
                uint32_t bv[4];                                                \
                LDSM_X4(bv[0], bv[1], bv[2], bv[3], Bs + bo);                  \
                MMA16816H(acc[2 * nt2],     ah, (bv));                         \
                MMA16816H(acc[2 * nt2 + 1], ah, (bv + 2));                     \
            }                                                                  \
        }                                                                      \
        __syncthreads();                                                       \
    }

// B prefetch: 128 rows x 4 chunks = 512 cp.async over 256 threads (2 iters)
#define MT1_PREFETCH_B(stage, Bp, n0, c)                                       \
    _Pragma("unroll")                                                          \
    for (int it = 0; it < 2; it++) {                                           \
        const int idx = it * 256 + tid;                                        \
        const int rb = idx >> 2, qb = idx & 3;                                 \
        CP_ASYNC16((stage) + MAT_A + (uint32_t)(rb * (RS * 2) + qb * 16),      \
                   (Bp) + (size_t)((n0) + rb) * 96 + (c) * 4 + qb);            \
    }

// ---------------------------------------------------------------------------
// Proj GEMM: out[4096,768] = A(fp16)·Wp^T(fp16) + bias. Grid (6, 64).
// ---------------------------------------------------------------------------
__global__ __launch_bounds__(256) void gemm_proj(
    const uint4* __restrict__ Ah, const uint4* __restrict__ Bp,
    float* __restrict__ C, const float* __restrict__ bias)
{
    MT1_DECLS
    const int m0 = blockIdx.y * 64, n0 = blockIdx.x * 128;
    const int nch = CC >> 5;             // 24

    auto prefetch = [&](int c, int s) {
        const uint32_t stage = sb + s * STAGE_P;
        const int r = tid >> 2, q = tid & 3;
        CP_ASYNC16(stage + (uint32_t)(r * (RS * 2) + q * 16),
                   Ah + (size_t)(m0 + r) * 96 + c * 4 + q);
        MT1_PREFETCH_B(stage, Bp, n0, c)
    };

    float acc[8][4] = {};
    prefetch(0, 0);
    CP_COMMIT();
    MT1_MAINLOOP(nch)

    const int row0 = m0 + m_base + (lane >> 2);
    #pragma unroll
    for (int nt = 0; nt < 8; nt++) {
        const int col = n0 + n_base + nt * 8 + (lane & 3) * 2;
        float b0 = bias[col], b1 = bias[col + 1];
        float2 v0 = { acc[nt][0] + b0, acc[nt][1] + b1 };
        float2 v1 = { acc[nt][2] + b0, acc[nt][3] + b1 };
        *(float2*)(C + (size_t)row0 * CC + col) = v0;
        *(float2*)(C + (size_t)(row0 + 8) * CC + col) = v1;
    }
}

// ---------------------------------------------------------------------------
// Fused QKV GEMM (MT1): blocks [0,384) Q; [384,1152) packed K/V.
// ---------------------------------------------------------------------------
__global__ __launch_bounds__(256) void qkv_fused(
    const uint4* __restrict__ Xh, const uint4* __restrict__ Wq,
    const int* __restrict__ kidx, const int* __restrict__ kcnt,
    __half* __restrict__ qh, __half* __restrict__ kh, __half* __restrict__ vh)
{
    MT1_DECLS
    const int bid = blockIdx.x;
    const int nch = CC >> 5;             // 24

    if (bid < 384) {
        // ------------------- Q role -------------------
        const int m0 = (bid / 6) * 64, n0 = (bid % 6) * 128;
        auto prefetch = [&](int c, int s) {
            const uint32_t stage = sb + s * STAGE_P;
            const int r = tid >> 2, q = tid & 3;
            CP_ASYNC16(stage + (uint32_t)(r * (RS * 2) + q * 16),
                       Xh + (size_t)(m0 + r) * 96 + c * 4 + q);
            MT1_PREFETCH_B(stage, Wq, n0, c)
        };
        float acc[8][4] = {};
        prefetch(0, 0);
        CP_COMMIT();
        MT1_MAINLOOP(nch)

        #pragma unroll
        for (int h2 = 0; h2 < 2; h2++) {
            const int r = m0 + m_base + h2 * 8 + (lane >> 2);
            const int b = r >> 11, n = r & (NN - 1);
            #pragma unroll
            for (int nt = 0; nt < 8; nt++) {
                const int c = n0 + n_base + nt * 8 + (lane & 3) * 2;
                const int h = c >> 6, d = c & 63;
                const size_t o = (((size_t)b * HH + h) * NN + n) * HD + d;
                *(uint32_t*)((char*)qh + o * 2) =
                    pack_h2(acc[nt][h2 * 2] * 0.125f,
                            acc[nt][h2 * 2 + 1] * 0.125f);
            }
        }
    } else {
        // ------------------- KV role (packed tokens) -------------------
        const int idx0 = bid - 384;
        const int bz = idx0 / 384;
        const int rr2 = idx0 % 384;
        const int m0 = (rr2 / 12) * 64;
        const int n0 = (rr2 % 12) * 128;
        const int cnt = kcnt[bz];
        const int pad = (cnt + 63) & ~63;
        if (m0 >= pad) return;

        const uint4* Bp = Wq + (size_t)CC * CC / 8;  // wq rows [768,2304)

        const int pr = tid >> 2, pq = tid & 3;
        const int j1 = m0 + pr;
        const int s1 = (j1 < cnt) ? kidx[bz * NN + j1] : 0;

        auto prefetch = [&](int c, int s) {
            const uint32_t stage = sb + s * STAGE_P;
            CP_ASYNC16(stage + (uint32_t)(pr * (RS * 2) + pq * 16),
                       Xh + (size_t)(bz * NN + s1) * 96 + c * 4 + pq);
            MT1_PREFETCH_B(stage, Bp, n0, c)
        };
        float acc[8][4] = {};
        prefetch(0, 0);
        CP_COMMIT();
        MT1_MAINLOOP(nch)

        #pragma unroll
        for (int h2 = 0; h2 < 2; h2++) {
            const int j = m0 + m_base + h2 * 8 + (lane >> 2);
            #pragma unroll
            for (int nt = 0; nt < 8; nt++) {
                const int c = n0 + n_base + nt * 8 + (lane & 3) * 2;
                const int isV = c >= CC;
                const int cc = isV ? c - CC : c;
                const int h = cc >> 6, d = cc & 63;
                const size_t o = (((size_t)bz * HH + h) * NN + j) * HD + d;
                __half* dst = isV ? vh : kh;
                *(uint32_t*)((char*)dst + o * 2) =
                    pack_h2(acc[nt][h2 * 2], acc[nt][h2 * 2 + 1]);
            }
        }
    }
}

// ---------------------------------------------------------------------------
// Fused pre-pass: [x->fp16 x8/thread][transpose wqkv][transpose wproj][scan]
// ---------------------------------------------------------------------------
#define PREP_SPLIT (BN * CC / 2048)         // 1536
#define PREP_TQ (72 * 24)                   // 1728
#define PREP_TP (24 * 24)                   // 576
#define PREP_TOTAL (PREP_SPLIT + PREP_TQ + PREP_TP + BB)

__global__ __launch_bounds__(256) void prep_all(
    const float* __restrict__ x, const int* __restrict__ mask,
    const float* __restrict__ w_qkv, const float* __restrict__ w_proj,
    __half* __restrict__ xh, __half* __restrict__ wq, __half* __restrict__ wp,
    int* __restrict__ kidx, int* __restrict__ kcnt)
{
    __shared__ float tbuf[32][33];
    __shared__ int part[256];
    const int bid = blockIdx.x, tid = threadIdx.x;

    if (bid < PREP_SPLIT) {
        const size_t i = ((size_t)bid * 256 + tid) * 8;
        float4 f0 = *(const float4*)(x + i);
        float4 f1 = *(const float4*)(x + i + 4);
        uint4 o;
        o.x = pack_h2(f0.x, f0.y);
        o.y = pack_h2(f0.z, f0.w);
        o.z = pack_h2(f1.x, f1.y);
        o.w = pack_h2(f1.z, f1.w);
        *(uint4*)(xh + i) = o;
    } else if (bid < PREP_SPLIT + PREP_TQ + PREP_TP) {
        const bool isQ = bid < PREP_SPLIT + PREP_TQ;
        const int t = isQ ? bid - PREP_SPLIT : bid - (PREP_SPLIT + PREP_TQ);
        const float* W = isQ ? w_qkv : w_proj;
        __half* dst = isQ ? wq : wp;
        const int N = isQ ? QKVC : CC;
        const int nblk = N / 32;
        const int n0 = (t % nblk) * 32, k0 = (t / nblk) * 32;
        const int tx = tid & 31, ty = tid >> 5;
        #pragma unroll
        for (int j = 0; j < 4; j++)
            tbuf[ty + 8 * j][tx] = W[(size_t)(k0 + ty + 8 * j) * N + n0 + tx];
        __syncthreads();
        #pragma unroll
        for (int j = 0; j < 4; j++) {
            const int nl = ty + 8 * j;
            dst[(size_t)(n0 + nl) * CC + k0 + tx] = __float2half_rn(tbuf[tx][nl]);
        }
    } else {
        const int b = bid - (PREP_SPLIT + PREP_TQ + PREP_TP);
        const int* m = mask + b * NN;
        int loc[8], c = 0;
        #pragma unroll
        for (int i = 0; i < 8; i++) { loc[i] = c; c += m[tid * 8 + i]; }
        part[tid] = c;
        __syncthreads();
        for (int off = 1; off < 256; off <<= 1) {
            int v = (tid >= off) ? part[tid - off] : 0;
            __syncthreads();
            part[tid] += v;
            __syncthreads();
        }
        int excl = part[tid] - c;
        #pragma unroll
        for (int i = 0; i < 8; i++)
            if (m[tid * 8 + i]) kidx[b * NN + excl + loc[i]] = tid * 8 + i;
        if (tid == 255) kcnt[b] = part[255];
    }
}

// ---------------------------------------------------------------------------
// Tensor-core attention: all-fp16, P-in-registers, paired X4 operand loads.
// ---------------------------------------------------------------------------
#define QT 128
#define KT 64
#define PADB 144                 // 72 x 16-bit per row
#define SM_STG  18432            // after Q resident
#define STG_SZ  18432            // K 9216 + V 9216
#define SM_RED  18432            // overlaid on stage area (post-loop only)
#define SM_DEN  55296
#define ATTN_SMEM (55296 + 512)

__global__ __launch_bounds__(256) void attn_mma(
    const uint4* __restrict__ Qh, const uint4* __restrict__ Kh,
    const uint4* __restrict__ Vh, const int* __restrict__ kcnt,
    __half* __restrict__ aout)
{
    extern __shared__ char sm[];
    const uint32_t sb = smem_u32(sm);
    const int b = blockIdx.z, h = blockIdx.y, q0 = blockIdx.x * QT;
    const int tid = threadIdx.x, wid = tid >> 5, lane = tid & 31;
    const int wm = wid >> 1, wn = wid & 1;
    const int mb = wm * 32, nb = wn * 32;
    const int cnt = kcnt[b];
    const int ntiles = (cnt + KT - 1) / KT;
    const size_t bh = (size_t)b * HH + h;

    float* denom_s = (float*)(sm + SM_DEN);
    if (tid < 128) denom_s[tid] = 0.0f;

    // resident Q tile (single fp16)
    #pragma unroll
    for (int it = 0; it < 4; it++) {
        int idx = it * 256 + tid;
        int r = idx >> 3, c = idx & 7;
        *(uint4*)(sm + r * PADB + c * 16) = Qh[(bh * NN + q0 + r) * 8 + c];
    }

    auto prefetch = [&](int t, int s) {
        const uint32_t stg = sb + SM_STG + s * STG_SZ;
        const int k0 = t * KT;
        #pragma unroll
        for (int it = 0; it < 4; it++) {
            int idx = it * 256 + tid;
            int mat = idx >> 9;                // 0 K, 1 V
            int r = (idx >> 3) & 63, c = idx & 7;
            uint32_t dst = stg + mat * 9216 + (uint32_t)(r * PADB + c * 16);
            const uint4* g = (mat == 0) ? Kh : Vh;
            CP_ASYNC16(dst, g + (bh * NN + k0 + r) * 8 + c);
        }
    };

    float accO[2][8][4] = {};
    float denA[2][2] = {};

    const int a_r = lane & 15, a_c = (lane >> 4) * 8;
    const int b4_r = ((lane >> 4) << 3) + (lane & 7);   // paired-K X4
    const int b4_c = ((lane >> 3) & 1) * 8;
    const int t_r = lane & 15;                          // V trans rows
    const int t_cext = (lane >> 4) * 16;                // V trans dt-pair col ext

    prefetch(0, 0);
    CP_COMMIT();

    for (int t = 0; t < ntiles; t++) {
        const int s = t & 1;
        const int k0 = t * KT;
        CP_WAIT(0);
        __syncthreads();
        if (t + 1 < ntiles) { prefetch(t + 1, 1 - s); CP_COMMIT(); }

        const uint32_t Ks = sb + SM_STG + s * STG_SZ;
        const uint32_t Vs = Ks + 9216;

        // S = Q K^T over this warp's 32q x 32k (fp16), K via paired X4
        float accS[2][4][4] = {};
        #pragma unroll
        for (int ks = 0; ks < 4; ks++) {
            uint32_t ah[2][4];
            #pragma unroll
            for (int mt = 0; mt < 2; mt++) {
                uint32_t ao = sb + (uint32_t)((mb + mt * 16 + a_r) * PADB +
                                              (ks * 16 + a_c) * 2);
                LDSM_X4(ah[mt][0], ah[mt][1], ah[mt][2], ah[mt][3], ao);
            }
            #pragma unroll
            for (int nt2 = 0; nt2 < 2; nt2++) {
                uint32_t bo = (uint32_t)((nb + nt2 * 16 + b4_r) * PADB +
                                         (ks * 16 + b4_c) * 2);
                uint32_t bv[4];
                LDSM_X4(bv[0], bv[1], bv[2], bv[3], Ks + bo);
                #pragma unroll
                for (int mt = 0; mt < 2; mt++) {
                    MMA16816H(accS[mt][2 * nt2],     ah[mt], (bv));
                    MMA16816H(accS[mt][2 * nt2 + 1], ah[mt], (bv + 2));
                }
            }
        }

        // exp + mask; P packed to fp16 A fragments
        uint32_t aP[2][2][4];
        #pragma unroll
        for (int mt = 0; mt < 2; mt++) {
            #pragma unroll
            for (int nt = 0; nt < 4; nt++) {
                int c0i = nb + nt * 8 + (lane & 3) * 2;
                float m0v = (k0 + c0i     < cnt) ? 1.f : 0.f;
                float m1v = (k0 + c0i + 1 < cnt) ? 1.f : 0.f;
                #pragma unroll
                for (int h2 = 0; h2 < 2; h2++) {
                    float p0 = __expf(accS[mt][nt][h2 * 2 + 0]) * m0v;
                    float p1 = __expf(accS[mt][nt][h2 * 2 + 1]) * m1v;
                    denA[mt][h2] += p0 + p1;
                    aP[mt][nt >> 1][(nt & 1) * 2 + h2] = pack_h2(p0, p1);
                }
            }
        }

        // O += P·V (fp16), V via paired X4 trans (two dt per load)
        #pragma unroll
        for (int kt = 0; kt < 2; kt++) {
            #pragma unroll
            for (int dt2 = 0; dt2 < 4; dt2++) {
                uint32_t bo = (uint32_t)((nb + kt * 16 + t_r) * PADB +
                                         dt2 * 32 + t_cext);
                uint32_t bv[4];
                LDSM_X4_T(bv[0], bv[1], bv[2], bv[3], Vs + bo);
                #pragma unroll
                for (int mt = 0; mt < 2; mt++) {
                    MMA16816H(accO[mt][2 * dt2],     aP[mt][kt], (bv));
                    MMA16816H(accO[mt][2 * dt2 + 1], aP[mt][kt], (bv + 2));
                }
            }
        }
    }

    // denom: quad-reduce then smem atomics
    #pragma unroll
    for (int mt = 0; mt < 2; mt++)
        #pragma unroll
        for (int h2 = 0; h2 < 2; h2++) {
            float v = denA[mt][h2];
            v += __shfl_xor_sync(0xffffffffu, v, 1);
            v += __shfl_xor_sync(0xffffffffu, v, 2);
            if ((lane & 3) == 0)
                atomicAdd(&denom_s[mb + mt * 16 + h2 * 8 + (lane >> 2)], v);
        }
    __syncthreads();

    // cross-pair O reduction: wn=1 stores to REDBUF (overlaid on stage area)
    float* red = (float*)(sm + SM_RED);
    if (wn == 1) {
        #pragma unroll
        for (int mt = 0; mt < 2; mt++) {
            const int r = mb + mt * 16 + (lane >> 2);
            #pragma unroll
            for (int dt = 0; dt < 8; dt++) {
                const int cc = dt * 8 + (lane & 3) * 2;
                *(float2*)&red[(size_t)r * 64 + cc] =
                    make_float2(accO[mt][dt][0], accO[mt][dt][1]);
                *(float2*)&red[(size_t)(r + 8) * 64 + cc] =
                    make_float2(accO[mt][dt][2], accO[mt][dt][3]);
            }
        }
    }
    __syncthreads();

    // wn=0 finalizes: add pair partial, divide, single-fp16 store
    if (wn == 0) {
        #pragma unroll
        for (int mt = 0; mt < 2; mt++) {
            const int r = mb + mt * 16 + (lane >> 2);
            const float inv0 = 1.0f / denom_s[r];
            const float inv1 = 1.0f / denom_s[r + 8];
            const size_t row0 = (size_t)(b * NN + q0 + r) * CC + h * HD;
            const size_t row1 = (size_t)(b * NN + q0 + r + 8) * CC + h * HD;
            #pragma unroll
            for (int dt = 0; dt < 8; dt++) {
                const int cc = dt * 8 + (lane & 3) * 2;
                float2 pr0 = *(float2*)&red[(size_t)r * 64 + cc];
                float2 pr1 = *(float2*)&red[(size_t)(r + 8) * 64 + cc];
                float v0 = (accO[mt][dt][0] + pr0.x) * inv0;
                float v1 = (accO[mt][dt][1] + pr0.y) * inv0;
                float v2 = (accO[mt][dt][2] + pr1.x) * inv1;
                float v3 = (accO[mt][dt][3] + pr1.y) * inv1;
                *(uint32_t*)((char*)aout + (row0 + cc) * 2) = pack_h2(v0, v1);
                *(uint32_t*)((char*)aout + (row1 + cc) * 2) = pack_h2(v2, v3);
            }
        }
    }
}

// ---------------------------------------------------------------------------
extern "C" void kernel_launch(void* const* d_in, const int* in_sizes, int n_in,
                              void* d_out, int out_size)
{
    const float* x      = (const float*)d_in[0];
    const int*   mask   = (const int*)  d_in[1];
    const float* w_qkv  = (const float*)d_in[2];
    const float* w_proj = (const float*)d_in[3];
    const float* b_proj = (const float*)d_in[4];
    float* out = (float*)d_out;

    __half *xh, *wq, *wp, *ah, *qh, *kh, *vh;
    int *kidx, *kcnt;
    cudaGetSymbolAddress((void**)&xh, g_xh);
    cudaGetSymbolAddress((void**)&wq, g_wq);
    cudaGetSymbolAddress((void**)&wp, g_wp);
    cudaGetSymbolAddress((void**)&ah, g_ah);
    cudaGetSymbolAddress((void**)&qh, g_qh);
    cudaGetSymbolAddress((void**)&kh, g_kh);
    cudaGetSymbolAddress((void**)&vh, g_vh);
    cudaGetSymbolAddress((void**)&kidx, g_kidx);
    cudaGetSymbolAddress((void**)&kcnt, g_kcnt);

    cudaFuncSetAttribute(gemm_proj, cudaFuncAttributeMaxDynamicSharedMemorySize, GEMM_SMEM);
    cudaFuncSetAttribute(qkv_fused, cudaFuncAttributeMaxDynamicSharedMemorySize, GEMM_SMEM);
    cudaFuncSetAttribute(attn_mma, cudaFuncAttributeMaxDynamicSharedMemorySize, ATTN_SMEM);

    // 0) fused pre-pass (vectorized x convert)
    prep_all<<<PREP_TOTAL, 256>>>(x, mask, w_qkv, w_proj, xh, wq, wp, kidx, kcnt);

    // 1) fused Q + KV GEMM (MT1, 1152 blocks)
    qkv_fused<<<1152, 256, GEMM_SMEM>>>(
        (const uint4*)xh, (const uint4*)wq, kidx, kcnt, qh, kh, vh);

    // 2) tensor-core attention over packed keys (all-fp16, paired X4)
    attn_mma<<<dim3(NN / QT, HH, BB), 256, ATTN_SMEM>>>(
        (const uint4*)qh, (const uint4*)kh, (const uint4*)vh, kcnt, ah);

    // 3) projection GEMM (MT1, 384 blocks) + bias
    gemm_proj<<<dim3(CC / 128, BN / 64), 256, GEMM_SMEM>>>(
        (const uint4*)ah, (const uint4*)wp, out, b_proj);
}

// round 14
// speedup vs baseline: 11.5325x; 1.0939x over previous
#include <cuda_runtime.h>
#include <cuda_bf16.h>
#include <cuda_fp16.h>
#include <cstdint>
#include <cstddef>

#define BB 2
#define NN 2048
#define CC 768
#define HH 12
#define HD 64
#define BN (BB * NN)          // 4096
#define QKVC (3 * CC)         // 2304

// ---------------------------------------------------------------------------
// Scratch (device globals — no allocation allowed anywhere)
// ---------------------------------------------------------------------------
__device__ __align__(16) __half g_xh [(size_t)BN * CC];           // x fp16
__device__ __align__(16) __half g_wq [(size_t)QKVC * CC];         // Wqkv^T fp16
__device__ __align__(16) __half g_wp [(size_t)CC * CC];           // Wproj^T fp16
__device__ __align__(16) __half g_ah [(size_t)BN * CC];           // attn out fp16
// attention operands: [b][h][token][64] row-major, single fp16
__device__ __align__(16) __half g_qh[(size_t)BB * HH * NN * HD];
__device__ __align__(16) __half g_kh[(size_t)BB * HH * NN * HD];
__device__ __align__(16) __half g_vh[(size_t)BB * HH * NN * HD];
__device__ int g_kidx[BB * NN];
__device__ int g_kcnt[BB];

// ---------------------------------------------------------------------------
// PTX helpers (family-common; ptxas target is sm_103 w/o 'a')
// ---------------------------------------------------------------------------
__device__ __forceinline__ uint32_t smem_u32(const void* p) {
    uint32_t a;
    asm("{ .reg .u64 t; cvta.to.shared.u64 t, %1; cvt.u32.u64 %0, t; }"
        : "=r"(a) : "l"(p));
    return a;
}
#define CP_ASYNC16(dst, src) \
    asm volatile("cp.async.cg.shared.global [%0], [%1], 16;" :: "r"(dst), "l"(src))
#define CP_COMMIT() asm volatile("cp.async.commit_group;" ::: "memory")
#define CP_WAIT(n)  asm volatile("cp.async.wait_group %0;" :: "n"(n) : "memory")

#define LDSM_X4(r0, r1, r2, r3, addr)                                          \
    asm volatile("ldmatrix.sync.aligned.m8n8.x4.shared.b16 {%0,%1,%2,%3}, [%4];" \
                 : "=r"(r0), "=r"(r1), "=r"(r2), "=r"(r3) : "r"(addr))
#define LDSM_X4_T(r0, r1, r2, r3, addr)                                        \
    asm volatile("ldmatrix.sync.aligned.m8n8.x4.trans.shared.b16 {%0,%1,%2,%3}, [%4];" \
                 : "=r"(r0), "=r"(r1), "=r"(r2), "=r"(r3) : "r"(addr))

#define MMA16816H(d, a, b)                                                     \
    asm volatile("mma.sync.aligned.m16n8k16.row.col.f32.f16.f16.f32 "          \
                 "{%0,%1,%2,%3}, {%4,%5,%6,%7}, {%8,%9}, {%0,%1,%2,%3};"       \
                 : "+f"((d)[0]), "+f"((d)[1]), "+f"((d)[2]), "+f"((d)[3])      \
                 : "r"((a)[0]), "r"((a)[1]), "r"((a)[2]), "r"((a)[3]),         \
                   "r"((b)[0]), "r"((b)[1]))

__device__ __forceinline__ uint32_t pack_h2(float v0, float v1) {
    __half2 h = __floats2half2_rn(v0, v1);
    return *(uint32_t*)&h;
}

// ---------------------------------------------------------------------------
// MT1 fp16 GEMM pieces: 64x128 block tile, 8 warps as 2M x 4N (warp 32x32),
// K-chunk 32, 3-stage cp.async pipeline. A,B single fp16, paired X4 loads.
// ---------------------------------------------------------------------------
#define RS 40
#define MAT_A  (64 * RS * 2)            // 5120
#define MAT_B  (128 * RS * 2)           // 10240
#define STAGE_P (MAT_A + MAT_B)         // 15360
#define GEMM_SMEM (3 * STAGE_P)         // 46080

#define MT1_DECLS                                                              \
    extern __shared__ char smem[];                                             \
    const uint32_t sb = smem_u32(smem);                                        \
    const int tid = threadIdx.x, wid = tid >> 5, lane = tid & 31;              \
    const int wm = wid >> 2, wn = wid & 3;                                     \
    const int m_base = wm * 32, n_base = wn * 32;                              \
    const int a_r = (lane & 15);                                               \
    const int a_c = (lane >> 4) * 8;                                           \
    /* paired-B X4 lane addressing: lanes 0-15 -> nt, 16-31 -> nt+1 */         \
    const int b4_r = ((lane >> 4) << 3) + (lane & 7);                          \
    const int b4_c = ((lane >> 3) & 1) * 8;

// 3-stage mainloop: wait -> single sync -> prefetch(c+2) -> compute.
#define MT1_MAINLOOP(NCH)                                                      \
    prefetch(0, 0); CP_COMMIT();                                               \
    prefetch(1, 1); CP_COMMIT();                                               \
    for (int c = 0; c < (NCH); c++) {                                          \
        if (c + 1 < (NCH)) { CP_WAIT(1); } else { CP_WAIT(0); }                \
        __syncthreads();                                                       \
        if (c + 2 < (NCH)) {                                                   \
            int sn = c + 2; sn -= (sn >= 3) ? 3 : 0; sn -= (sn >= 3) ? 3 : 0;  \
            prefetch(c + 2, (c + 2) % 3); CP_COMMIT();                         \
        }                                                                      \
        const uint32_t As = sb + (c % 3) * STAGE_P;                            \
        const uint32_t Bs = As + MAT_A;                                        \
        _Pragma("unroll")                                                      \
        for (int kk = 0; kk < 2; kk++) {                                       \
            uint32_t ah[2][4];                                                 \
            _Pragma("unroll")                                                  \
            for (int mt = 0; mt < 2; mt++) {                                   \
                const uint32_t ao =                                            \
                    (uint32_t)((m_base + mt * 16 + a_r) * (RS * 2) +           \
                               (kk * 16 + a_c) * 2);                           \
                LDSM_X4(ah[mt][0], ah[mt][1], ah[mt][2], ah[mt][3], As + ao);  \
            }                                                                  \
            _Pragma("unroll")                                                  \
            for (int nt2 = 0; nt2 < 2; nt2++) {                                \
                const uint32_t bo =                                            \
                    (uint32_t)((n_base + nt2 * 16 + b4_r) * (RS * 2) +         \
                               (kk * 16 + b4_c) * 2);                          \
                uint32_t bv[4];                                                \
                LDSM_X4(bv[0], bv[1], bv[2], bv[3], Bs + bo);                  \
                _Pragma("unroll")                                              \
                for (int mt = 0; mt < 2; mt++) {                               \
                    MMA16816H(acc[mt][2 * nt2],     ah[mt], (bv));             \
                    MMA16816H(acc[mt][2 * nt2 + 1], ah[mt], (bv + 2));         \
                }                                                              \
            }                                                                  \
        }                                                                      \
    }

// B prefetch: 128 rows x 4 chunks = 512 cp.async over 256 threads (2 iters)
#define MT1_PREFETCH_B(stage, Bp, n0, c)                                       \
    _Pragma("unroll")                                                          \
    for (int it = 0; it < 2; it++) {                                           \
        const int idx = it * 256 + tid;                                        \
        const int rb = idx >> 2, qb = idx & 3;                                 \
        CP_ASYNC16((stage) + MAT_A + (uint32_t)(rb * (RS * 2) + qb * 16),      \
                   (Bp) + (size_t)((n0) + rb) * 96 + (c) * 4 + qb);            \
    }

// ---------------------------------------------------------------------------
// Proj GEMM: out[4096,768] = A(fp16)·Wp^T(fp16) + bias. Grid (6, 64).
// ---------------------------------------------------------------------------
__global__ __launch_bounds__(256) void gemm_proj(
    const uint4* __restrict__ Ah, const uint4* __restrict__ Bp,
    float* __restrict__ C, const float* __restrict__ bias)
{
    MT1_DECLS
    const int m0 = blockIdx.y * 64, n0 = blockIdx.x * 128;
    const int nch = CC >> 5;             // 24

    auto prefetch = [&](int c, int s) {
        const uint32_t stage = sb + s * STAGE_P;
        const int r = tid >> 2, q = tid & 3;
        CP_ASYNC16(stage + (uint32_t)(r * (RS * 2) + q * 16),
                   Ah + (size_t)(m0 + r) * 96 + c * 4 + q);
        MT1_PREFETCH_B(stage, Bp, n0, c)
    };

    float acc[2][4][4] = {};
    MT1_MAINLOOP(nch)

    #pragma unroll
    for (int mt = 0; mt < 2; mt++) {
        const int row0 = m0 + m_base + mt * 16 + (lane >> 2);
        #pragma unroll
        for (int nt = 0; nt < 4; nt++) {
            const int col = n0 + n_base + nt * 8 + (lane & 3) * 2;
            float b0 = bias[col], b1 = bias[col + 1];
            float2 v0 = { acc[mt][nt][0] + b0, acc[mt][nt][1] + b1 };
            float2 v1 = { acc[mt][nt][2] + b0, acc[mt][nt][3] + b1 };
            *(float2*)(C + (size_t)row0 * CC + col) = v0;
            *(float2*)(C + (size_t)(row0 + 8) * CC + col) = v1;
        }
    }
}

// ---------------------------------------------------------------------------
// Fused QKV GEMM (MT1): blocks [0,384) Q; [384,1152) packed K/V.
// ---------------------------------------------------------------------------
__global__ __launch_bounds__(256) void qkv_fused(
    const uint4* __restrict__ Xh, const uint4* __restrict__ Wq,
    const int* __restrict__ kidx, const int* __restrict__ kcnt,
    __half* __restrict__ qh, __half* __restrict__ kh, __half* __restrict__ vh)
{
    MT1_DECLS
    const int bid = blockIdx.x;
    const int nch = CC >> 5;             // 24

    if (bid < 384) {
        // ------------------- Q role -------------------
        const int m0 = (bid / 6) * 64, n0 = (bid % 6) * 128;
        auto prefetch = [&](int c, int s) {
            const uint32_t stage = sb + s * STAGE_P;
            const int r = tid >> 2, q = tid & 3;
            CP_ASYNC16(stage + (uint32_t)(r * (RS * 2) + q * 16),
                       Xh + (size_t)(m0 + r) * 96 + c * 4 + q);
            MT1_PREFETCH_B(stage, Wq, n0, c)
        };
        float acc[2][4][4] = {};
        MT1_MAINLOOP(nch)

        #pragma unroll
        for (int mt = 0; mt < 2; mt++) {
            #pragma unroll
            for (int h2 = 0; h2 < 2; h2++) {
                const int r = m0 + m_base + mt * 16 + h2 * 8 + (lane >> 2);
                const int b = r >> 11, n = r & (NN - 1);
                #pragma unroll
                for (int nt = 0; nt < 4; nt++) {
                    const int c = n0 + n_base + nt * 8 + (lane & 3) * 2;
                    const int h = c >> 6, d = c & 63;
                    const size_t o = (((size_t)b * HH + h) * NN + n) * HD + d;
                    *(uint32_t*)((char*)qh + o * 2) =
                        pack_h2(acc[mt][nt][h2 * 2] * 0.125f,
                                acc[mt][nt][h2 * 2 + 1] * 0.125f);
                }
            }
        }
    } else {
        // ------------------- KV role (packed tokens) -------------------
        const int idx0 = bid - 384;
        const int bz = idx0 / 384;
        const int rr2 = idx0 % 384;
        const int m0 = (rr2 / 12) * 64;
        const int n0 = (rr2 % 12) * 128;
        const int cnt = kcnt[bz];
        const int pad = (cnt + 63) & ~63;
        if (m0 >= pad) return;

        const uint4* Bp = Wq + (size_t)CC * CC / 8;  // wq rows [768,2304)

        const int pr = tid >> 2, pq = tid & 3;
        const int j1 = m0 + pr;
        const int s1 = (j1 < cnt) ? kidx[bz * NN + j1] : 0;

        auto prefetch = [&](int c, int s) {
            const uint32_t stage = sb + s * STAGE_P;
            CP_ASYNC16(stage + (uint32_t)(pr * (RS * 2) + pq * 16),
                       Xh + (size_t)(bz * NN + s1) * 96 + c * 4 + pq);
            MT1_PREFETCH_B(stage, Bp, n0, c)
        };
        float acc[2][4][4] = {};
        MT1_MAINLOOP(nch)

        #pragma unroll
        for (int mt = 0; mt < 2; mt++) {
            #pragma unroll
            for (int h2 = 0; h2 < 2; h2++) {
                const int j = m0 + m_base + mt * 16 + h2 * 8 + (lane >> 2);
                #pragma unroll
                for (int nt = 0; nt < 4; nt++) {
                    const int c = n0 + n_base + nt * 8 + (lane & 3) * 2;
                    const int isV = c >= CC;
                    const int cc = isV ? c - CC : c;
                    const int h = cc >> 6, d = cc & 63;
                    const size_t o = (((size_t)bz * HH + h) * NN + j) * HD + d;
                    __half* dst = isV ? vh : kh;
                    *(uint32_t*)((char*)dst + o * 2) =
                        pack_h2(acc[mt][nt][h2 * 2], acc[mt][nt][h2 * 2 + 1]);
                }
            }
        }
    }
}

// ---------------------------------------------------------------------------
// Fused pre-pass: [x->fp16 x8/thread][transpose wqkv][transpose wproj][scan]
// ---------------------------------------------------------------------------
#define PREP_SPLIT (BN * CC / 2048)         // 1536
#define PREP_TQ (72 * 24)                   // 1728
#define PREP_TP (24 * 24)                   // 576
#define PREP_TOTAL (PREP_SPLIT + PREP_TQ + PREP_TP + BB)

__global__ __launch_bounds__(256) void prep_all(
    const float* __restrict__ x, const int* __restrict__ mask,
    const float* __restrict__ w_qkv, const float* __restrict__ w_proj,
    __half* __restrict__ xh, __half* __restrict__ wq, __half* __restrict__ wp,
    int* __restrict__ kidx, int* __restrict__ kcnt)
{
    __shared__ float tbuf[32][33];
    __shared__ int part[256];
    const int bid = blockIdx.x, tid = threadIdx.x;

    if (bid < PREP_SPLIT) {
        const size_t i = ((size_t)bid * 256 + tid) * 8;
        float4 f0 = *(const float4*)(x + i);
        float4 f1 = *(const float4*)(x + i + 4);
        uint4 o;
        o.x = pack_h2(f0.x, f0.y);
        o.y = pack_h2(f0.z, f0.w);
        o.z = pack_h2(f1.x, f1.y);
        o.w = pack_h2(f1.z, f1.w);
        *(uint4*)(xh + i) = o;
    } else if (bid < PREP_SPLIT + PREP_TQ + PREP_TP) {
        const bool isQ = bid < PREP_SPLIT + PREP_TQ;
        const int t = isQ ? bid - PREP_SPLIT : bid - (PREP_SPLIT + PREP_TQ);
        const float* W = isQ ? w_qkv : w_proj;
        __half* dst = isQ ? wq : wp;
        const int N = isQ ? QKVC : CC;
        const int nblk = N / 32;
        const int n0 = (t % nblk) * 32, k0 = (t / nblk) * 32;
        const int tx = tid & 31, ty = tid >> 5;
        #pragma unroll
        for (int j = 0; j < 4; j++)
            tbuf[ty + 8 * j][tx] = W[(size_t)(k0 + ty + 8 * j) * N + n0 + tx];
        __syncthreads();
        #pragma unroll
        for (int j = 0; j < 4; j++) {
            const int nl = ty + 8 * j;
            dst[(size_t)(n0 + nl) * CC + k0 + tx] = __float2half_rn(tbuf[tx][nl]);
        }
    } else {
        const int b = bid - (PREP_SPLIT + PREP_TQ + PREP_TP);
        const int* m = mask + b * NN;
        int loc[8], c = 0;
        #pragma unroll
        for (int i = 0; i < 8; i++) { loc[i] = c; c += m[tid * 8 + i]; }
        part[tid] = c;
        __syncthreads();
        for (int off = 1; off < 256; off <<= 1) {
            int v = (tid >= off) ? part[tid - off] : 0;
            __syncthreads();
            part[tid] += v;
            __syncthreads();
        }
        int excl = part[tid] - c;
        #pragma unroll
        for (int i = 0; i < 8; i++)
            if (m[tid * 8 + i]) kidx[b * NN + excl + loc[i]] = tid * 8 + i;
        if (tid == 255) kcnt[b] = part[255];
    }
}

// ---------------------------------------------------------------------------
// Tensor-core attention: all-fp16, P-in-registers, paired X4 operand loads.
// (unchanged from R13)
// ---------------------------------------------------------------------------
#define QT 128
#define KT 64
#define PADB 144                 // 72 x 16-bit per row
#define SM_STG  18432            // after Q resident
#define STG_SZ  18432            // K 9216 + V 9216
#define SM_RED  18432            // overlaid on stage area (post-loop only)
#define SM_DEN  55296
#define ATTN_SMEM (55296 + 512)

__global__ __launch_bounds__(256) void attn_mma(
    const uint4* __restrict__ Qh, const uint4* __restrict__ Kh,
    const uint4* __restrict__ Vh, const int* __restrict__ kcnt,
    __half* __restrict__ aout)
{
    extern __shared__ char sm[];
    const uint32_t sb = smem_u32(sm);
    const int b = blockIdx.z, h = blockIdx.y, q0 = blockIdx.x * QT;
    const int tid = threadIdx.x, wid = tid >> 5, lane = tid & 31;
    const int wm = wid >> 1, wn = wid & 1;
    const int mb = wm * 32, nb = wn * 32;
    const int cnt = kcnt[b];
    const int ntiles = (cnt + KT - 1) / KT;
    const size_t bh = (size_t)b * HH + h;

    float* denom_s = (float*)(sm + SM_DEN);
    if (tid < 128) denom_s[tid] = 0.0f;

    // resident Q tile (single fp16)
    #pragma unroll
    for (int it = 0; it < 4; it++) {
        int idx = it * 256 + tid;
        int r = idx >> 3, c = idx & 7;
        *(uint4*)(sm + r * PADB + c * 16) = Qh[(bh * NN + q0 + r) * 8 + c];
    }

    auto prefetch = [&](int t, int s) {
        const uint32_t stg = sb + SM_STG + s * STG_SZ;
        const int k0 = t * KT;
        #pragma unroll
        for (int it = 0; it < 4; it++) {
            int idx = it * 256 + tid;
            int mat = idx >> 9;                // 0 K, 1 V
            int r = (idx >> 3) & 63, c = idx & 7;
            uint32_t dst = stg + mat * 9216 + (uint32_t)(r * PADB + c * 16);
            const uint4* g = (mat == 0) ? Kh : Vh;
            CP_ASYNC16(dst, g + (bh * NN + k0 + r) * 8 + c);
        }
    };

    float accO[2][8][4] = {};
    float denA[2][2] = {};

    const int a_r = lane & 15, a_c = (lane >> 4) * 8;
    const int b4_r = ((lane >> 4) << 3) + (lane & 7);   // paired-K X4
    const int b4_c = ((lane >> 3) & 1) * 8;
    const int t_r = lane & 15;                          // V trans rows
    const int t_cext = (lane >> 4) * 16;                // V trans dt-pair col ext

    prefetch(0, 0);
    CP_COMMIT();

    for (int t = 0; t < ntiles; t++) {
        const int s = t & 1;
        const int k0 = t * KT;
        CP_WAIT(0);
        __syncthreads();
        if (t + 1 < ntiles) { prefetch(t + 1, 1 - s); CP_COMMIT(); }

        const uint32_t Ks = sb + SM_STG + s * STG_SZ;
        const uint32_t Vs = Ks + 9216;

        // S = Q K^T over this warp's 32q x 32k (fp16), K via paired X4
        float accS[2][4][4] = {};
        #pragma unroll
        for (int ks = 0; ks < 4; ks++) {
            uint32_t ah[2][4];
            #pragma unroll
            for (int mt = 0; mt < 2; mt++) {
                uint32_t ao = sb + (uint32_t)((mb + mt * 16 + a_r) * PADB +
                                              (ks * 16 + a_c) * 2);
                LDSM_X4(ah[mt][0], ah[mt][1], ah[mt][2], ah[mt][3], ao);
            }
            #pragma unroll
            for (int nt2 = 0; nt2 < 2; nt2++) {
                uint32_t bo = (uint32_t)((nb + nt2 * 16 + b4_r) * PADB +
                                         (ks * 16 + b4_c) * 2);
                uint32_t bv[4];
                LDSM_X4(bv[0], bv[1], bv[2], bv[3], Ks + bo);
                #pragma unroll
                for (int mt = 0; mt < 2; mt++) {
                    MMA16816H(accS[mt][2 * nt2],     ah[mt], (bv));
                    MMA16816H(accS[mt][2 * nt2 + 1], ah[mt], (bv + 2));
                }
            }
        }

        // exp + mask; P packed to fp16 A fragments
        uint32_t aP[2][2][4];
        #pragma unroll
        for (int mt = 0; mt < 2; mt++) {
            #pragma unroll
            for (int nt = 0; nt < 4; nt++) {
                int c0i = nb + nt * 8 + (lane & 3) * 2;
                float m0v = (k0 + c0i     < cnt) ? 1.f : 0.f;
                float m1v = (k0 + c0i + 1 < cnt) ? 1.f : 0.f;
                #pragma unroll
                for (int h2 = 0; h2 < 2; h2++) {
                    float p0 = __expf(accS[mt][nt][h2 * 2 + 0]) * m0v;
                    float p1 = __expf(accS[mt][nt][h2 * 2 + 1]) * m1v;
                    denA[mt][h2] += p0 + p1;
                    aP[mt][nt >> 1][(nt & 1) * 2 + h2] = pack_h2(p0, p1);
                }
            }
        }

        // O += P·V (fp16), V via paired X4 trans (two dt per load)
        #pragma unroll
        for (int kt = 0; kt < 2; kt++) {
            #pragma unroll
            for (int dt2 = 0; dt2 < 4; dt2++) {
                uint32_t bo = (uint32_t)((nb + kt * 16 + t_r) * PADB +
                                         dt2 * 32 + t_cext);
                uint32_t bv[4];
                LDSM_X4_T(bv[0], bv[1], bv[2], bv[3], Vs + bo);
                #pragma unroll
                for (int mt = 0; mt < 2; mt++) {
                    MMA16816H(accO[mt][2 * dt2],     aP[mt][kt], (bv));
                    MMA16816H(accO[mt][2 * dt2 + 1], aP[mt][kt], (bv + 2));
                }
            }
        }
    }

    // denom: quad-reduce then smem atomics
    #pragma unroll
    for (int mt = 0; mt < 2; mt++)
        #pragma unroll
        for (int h2 = 0; h2 < 2; h2++) {
            float v = denA[mt][h2];
            v += __shfl_xor_sync(0xffffffffu, v, 1);
            v += __shfl_xor_sync(0xffffffffu, v, 2);
            if ((lane & 3) == 0)
                atomicAdd(&denom_s[mb + mt * 16 + h2 * 8 + (lane >> 2)], v);
        }
    __syncthreads();

    // cross-pair O reduction: wn=1 stores to REDBUF (overlaid on stage area)
    float* red = (float*)(sm + SM_RED);
    if (wn == 1) {
        #pragma unroll
        for (int mt = 0; mt < 2; mt++) {
            const int r = mb + mt * 16 + (lane >> 2);
            #pragma unroll
            for (int dt = 0; dt < 8; dt++) {
                const int cc = dt * 8 + (lane & 3) * 2;
                *(float2*)&red[(size_t)r * 64 + cc] =
                    make_float2(accO[mt][dt][0], accO[mt][dt][1]);
                *(float2*)&red[(size_t)(r + 8) * 64 + cc] =
                    make_float2(accO[mt][dt][2], accO[mt][dt][3]);
            }
        }
    }
    __syncthreads();

    // wn=0 finalizes: add pair partial, divide, single-fp16 store
    if (wn == 0) {
        #pragma unroll
        for (int mt = 0; mt < 2; mt++) {
            const int r = mb + mt * 16 + (lane >> 2);
            const float inv0 = 1.0f / denom_s[r];
            const float inv1 = 1.0f / denom_s[r + 8];
            const size_t row0 = (size_t)(b * NN + q0 + r) * CC + h * HD;
            const size_t row1 = (size_t)(b * NN + q0 + r + 8) * CC + h * HD;
            #pragma unroll
            for (int dt = 0; dt < 8; dt++) {
                const int cc = dt * 8 + (lane & 3) * 2;
                float2 pr0 = *(float2*)&red[(size_t)r * 64 + cc];
                float2 pr1 = *(float2*)&red[(size_t)(r + 8) * 64 + cc];
                float v0 = (accO[mt][dt][0] + pr0.x) * inv0;
                float v1 = (accO[mt][dt][1] + pr0.y) * inv0;
                float v2 = (accO[mt][dt][2] + pr1.x) * inv1;
                float v3 = (accO[mt][dt][3] + pr1.y) * inv1;
                *(uint32_t*)((char*)aout + (row0 + cc) * 2) = pack_h2(v0, v1);
                *(uint32_t*)((char*)aout + (row1 + cc) * 2) = pack_h2(v2, v3);
            }
        }
    }
}

// ---------------------------------------------------------------------------
extern "C" void kernel_launch(void* const* d_in, const int* in_sizes, int n_in,
                              void* d_out, int out_size)
{
    const float* x      = (const float*)d_in[0];
    const int*   mask   = (const int*)  d_in[1];
    const float* w_qkv  = (const float*)d_in[2];
    const float* w_proj = (const float*)d_in[3];
    const float* b_proj = (const float*)d_in[4];
    float* out = (float*)d_out;

    __half *xh, *wq, *wp, *ah, *qh, *kh, *vh;
    int *kidx, *kcnt;
    cudaGetSymbolAddress((void**)&xh, g_xh);
    cudaGetSymbolAddress((void**)&wq, g_wq);
    cudaGetSymbolAddress((void**)&wp, g_wp);
    cudaGetSymbolAddress((void**)&ah, g_ah);
    cudaGetSymbolAddress((void**)&qh, g_qh);
    cudaGetSymbolAddress((void**)&kh, g_kh);
    cudaGetSymbolAddress((void**)&vh, g_vh);
    cudaGetSymbolAddress((void**)&kidx, g_kidx);
    cudaGetSymbolAddress((void**)&kcnt, g_kcnt);

    cudaFuncSetAttribute(gemm_proj, cudaFuncAttributeMaxDynamicSharedMemorySize, GEMM_SMEM);
    cudaFuncSetAttribute(qkv_fused, cudaFuncAttributeMaxDynamicSharedMemorySize, GEMM_SMEM);
    cudaFuncSetAttribute(attn_mma, cudaFuncAttributeMaxDynamicSharedMemorySize, ATTN_SMEM);

    // 0) fused pre-pass
    prep_all<<<PREP_TOTAL, 256>>>(x, mask, w_qkv, w_proj, xh, wq, wp, kidx, kcnt);

    // 1) fused Q + KV GEMM (MT1, 1152 blocks, 3-stage pipeline)
    qkv_fused<<<1152, 256, GEMM_SMEM>>>(
        (const uint4*)xh, (const uint4*)wq, kidx, kcnt, qh, kh, vh);

    // 2) tensor-core attention over packed keys (all-fp16)
    attn_mma<<<dim3(NN / QT, HH, BB), 256, ATTN_SMEM>>>(
        (const uint4*)qh, (const uint4*)kh, (const uint4*)vh, kcnt, ah);

    // 3) projection GEMM (MT1, 384 blocks, 3-stage pipeline) + bias
    gemm_proj<<<dim3(CC / 128, BN / 64), 256, GEMM_SMEM>>>(
        (const uint4*)ah, (const uint4*)wp, out, b_proj);
}